// round 11
// baseline (speedup 1.0000x reference)
#include <cuda_runtime.h>
#include <cuda_bf16.h>
#include <math.h>
#include <cstdint>

#define E_DIM   1024
#define N_HEAD  16
#define HD      64
#define T_LEN   1024
#define N_LAYER 6
#define VOCAB   32000
#define BATCH   2
#define MTOK    (BATCH * T_LEN)     /* 2048 */
#define FF      (4 * E_DIM)         /* 4096 */

/* ================= scratch =============================================== */
__device__ float g_x   [MTOK * E_DIM];
__device__ __nv_bfloat16 g_yh[MTOK * E_DIM];
__device__ __nv_bfloat16 g_yl[MTOK * E_DIM];
__device__ __nv_bfloat16 g_qh[(size_t)MTOK * 3 * E_DIM];
__device__ __nv_bfloat16 g_ql[(size_t)MTOK * 3 * E_DIM];
__device__ __nv_bfloat16 g_oh[MTOK * E_DIM];
__device__ __nv_bfloat16 g_ol[MTOK * E_DIM];
__device__ __nv_bfloat16 g_hh[(size_t)MTOK * FF];
__device__ __nv_bfloat16 g_hl[(size_t)MTOK * FF];
__device__ float g_nllv[MTOK];
__device__ float g_logits_scratch[(size_t)MTOK * VOCAB];
__device__ float2 g_cs[T_LEN * 32];
__device__ __nv_bfloat16 g_qkvT_h[(size_t)N_LAYER * 3 * E_DIM * E_DIM];
__device__ __nv_bfloat16 g_qkvT_l[(size_t)N_LAYER * 3 * E_DIM * E_DIM];
__device__ __nv_bfloat16 g_projT_h[(size_t)N_LAYER * E_DIM * E_DIM];
__device__ __nv_bfloat16 g_projT_l[(size_t)N_LAYER * E_DIM * E_DIM];
__device__ __nv_bfloat16 g_w1T_h[(size_t)N_LAYER * FF * E_DIM];
__device__ __nv_bfloat16 g_w1T_l[(size_t)N_LAYER * FF * E_DIM];
__device__ __nv_bfloat16 g_w2T_h[(size_t)N_LAYER * E_DIM * FF];
__device__ __nv_bfloat16 g_w2T_l[(size_t)N_LAYER * E_DIM * FF];
__device__ __nv_bfloat16 g_lmT_h[(size_t)VOCAB * E_DIM];
__device__ __nv_bfloat16 g_lmT_l[(size_t)VOCAB * E_DIM];

/* ================= small PTX wrappers ==================================== */
__device__ __forceinline__ uint32_t smem_u32(const void* p) {
    uint32_t a;
    asm("{ .reg .u64 t; cvta.to.shared.u64 t, %1; cvt.u32.u64 %0, t; }" : "=r"(a) : "l"(p));
    return a;
}
__device__ __forceinline__ void cp16(uint32_t s, const void* g) {
    asm volatile("cp.async.cg.shared.global [%0], [%1], 16;" :: "r"(s), "l"(g));
}
__device__ __forceinline__ void cp_commit() { asm volatile("cp.async.commit_group;"); }
template<int N> __device__ __forceinline__ void cp_wait() {
    asm volatile("cp.async.wait_group %0;" :: "n"(N));
}
__device__ __forceinline__ void ldmA(uint32_t* r, uint32_t a) {
    asm volatile("ldmatrix.sync.aligned.m8n8.x4.shared.b16 {%0,%1,%2,%3}, [%4];"
                 : "=r"(r[0]), "=r"(r[1]), "=r"(r[2]), "=r"(r[3]) : "r"(a));
}
__device__ __forceinline__ void ldmB(uint32_t* r, uint32_t a) {
    asm volatile("ldmatrix.sync.aligned.m8n8.x2.shared.b16 {%0,%1}, [%2];"
                 : "=r"(r[0]), "=r"(r[1]) : "r"(a));
}
__device__ __forceinline__ void ldmB4(uint32_t& r0, uint32_t& r1, uint32_t& r2, uint32_t& r3,
                                      uint32_t a) {
    asm volatile("ldmatrix.sync.aligned.m8n8.x4.shared.b16 {%0,%1,%2,%3}, [%4];"
                 : "=r"(r0), "=r"(r1), "=r"(r2), "=r"(r3) : "r"(a));
}
__device__ __forceinline__ void ldmT(uint32_t* r, uint32_t a) {
    asm volatile("ldmatrix.sync.aligned.m8n8.x2.trans.shared.b16 {%0,%1}, [%2];"
                 : "=r"(r[0]), "=r"(r[1]) : "r"(a));
}
__device__ __forceinline__ void mma16816(float* c, const uint32_t* a, const uint32_t* b) {
    asm volatile("mma.sync.aligned.m16n8k16.row.col.f32.bf16.bf16.f32 "
                 "{%0,%1,%2,%3}, {%4,%5,%6,%7}, {%8,%9}, {%0,%1,%2,%3};"
                 : "+f"(c[0]), "+f"(c[1]), "+f"(c[2]), "+f"(c[3])
                 : "r"(a[0]), "r"(a[1]), "r"(a[2]), "r"(a[3]), "r"(b[0]), "r"(b[1]));
}
__device__ __forceinline__ uint32_t packbf(float a, float b) {
    __nv_bfloat162 t = __floats2bfloat162_rn(a, b);
    return *(uint32_t*)&t;
}

/* ================= HMMA GEMM 128x128 (used for N=1024) =================== */
#define ROWB   80
#define TILEB  (128 * ROWB)
#define STAGEB (4 * TILEB)
#define SMTOT  (2 * STAGEB)

template<bool RELU, bool SPLIT, bool ROPE>
__global__ __launch_bounds__(256, 2)
void mma_gemm(const __nv_bfloat16* __restrict__ Ah, const __nv_bfloat16* __restrict__ Al,
              const __nv_bfloat16* __restrict__ Bh, const __nv_bfloat16* __restrict__ Bl,
              int K, int N,
              float* __restrict__ C,
              __nv_bfloat16* __restrict__ Oh, __nv_bfloat16* __restrict__ Ol,
              const float* __restrict__ bias, const float* __restrict__ res,
              const float2* __restrict__ cs) {
    extern __shared__ char smem[];
    const uint32_t sb = smem_u32(smem);
    const int tid = threadIdx.x;
    const int lane = tid & 31;
    const int wid = tid >> 5;
    const int warp_m = wid & 1;
    const int warp_n = wid >> 1;
    const size_t bm = (size_t)blockIdx.y * 128;
    const size_t bn = (size_t)blockIdx.x * 128;

    float acc[4][4][4];
    #pragma unroll
    for (int i = 0; i < 4; i++)
        #pragma unroll
        for (int j = 0; j < 4; j++)
            #pragma unroll
            for (int q = 0; q < 4; q++) acc[i][j][q] = 0.f;

    const int nc = K >> 5;

    auto load_stage = [&](int c) {
        const int k0 = c << 5;
        const uint32_t sbase = sb + (c & 1) * STAGEB;
        #pragma unroll
        for (int t = 0; t < 8; t++) {
            int idx = tid + (t << 8);
            int tile = idx >> 9;
            int r    = (idx >> 2) & 127;
            int cch  = idx & 3;
            const __nv_bfloat16* base = (tile == 0) ? Ah : (tile == 1) ? Al
                                      : (tile == 2) ? Bh : Bl;
            size_t grow = ((tile < 2) ? bm : bn) + r;
            const __nv_bfloat16* g = base + grow * (size_t)K + k0 + cch * 8;
            cp16(sbase + tile * TILEB + r * ROWB + cch * 16, g);
        }
        cp_commit();
    };

    load_stage(0);

    const uint32_t aRowOff = (uint32_t)((warp_m * 64 + (lane & 15)) * ROWB + ((lane >> 4) << 4));
    const uint32_t bRow4Off = (uint32_t)((warp_n * 32 + ((lane & 16) >> 1) + (lane & 7)) * ROWB
                                         + ((lane & 8) << 1));

    for (int c = 0; c < nc; c++) {
        cp_wait<0>();
        __syncthreads();
        if (c + 1 < nc) load_stage(c + 1);

        const uint32_t st = sb + (c & 1) * STAGEB;
        const uint32_t aH = st + aRowOff;
        const uint32_t aL = st + TILEB + aRowOff;
        const uint32_t bH = st + 2 * TILEB + bRow4Off;
        const uint32_t bL = st + 3 * TILEB + bRow4Off;

        #pragma unroll
        for (int kk = 0; kk < 2; kk++) {
            const uint32_t kb = kk * 32;
            uint32_t a[4][4], bh[4][2], bl[4][2];
            #pragma unroll
            for (int p = 0; p < 2; p++) {
                ldmB4(bh[2*p][0], bh[2*p][1], bh[2*p+1][0], bh[2*p+1][1],
                      bH + p * (16 * ROWB) + kb);
                ldmB4(bl[2*p][0], bl[2*p][1], bl[2*p+1][0], bl[2*p+1][1],
                      bL + p * (16 * ROWB) + kb);
            }
            #pragma unroll
            for (int mt = 0; mt < 4; mt++)
                ldmA(a[mt], aH + mt * (16 * ROWB) + kb);
            #pragma unroll
            for (int mt = 0; mt < 4; mt++)
                #pragma unroll
                for (int nt = 0; nt < 4; nt++)
                    mma16816(acc[mt][nt], a[mt], bh[nt]);
            #pragma unroll
            for (int mt = 0; mt < 4; mt++)
                #pragma unroll
                for (int nt = 0; nt < 4; nt++)
                    mma16816(acc[mt][nt], a[mt], bl[nt]);
            #pragma unroll
            for (int mt = 0; mt < 4; mt++)
                ldmA(a[mt], aL + mt * (16 * ROWB) + kb);
            #pragma unroll
            for (int mt = 0; mt < 4; mt++)
                #pragma unroll
                for (int nt = 0; nt < 4; nt++)
                    mma16816(acc[mt][nt], a[mt], bh[nt]);
        }
    }

    #pragma unroll
    for (int mt = 0; mt < 4; mt++) {
        #pragma unroll
        for (int nt = 0; nt < 4; nt++) {
            size_t col = bn + warp_n * 32 + nt * 8 + (lane & 3) * 2;
            #pragma unroll
            for (int half = 0; half < 2; half++) {
                size_t row = bm + warp_m * 64 + mt * 16 + (lane >> 2) + half * 8;
                float v0 = acc[mt][nt][half * 2 + 0];
                float v1 = acc[mt][nt][half * 2 + 1];
                if (bias) { v0 += bias[col]; v1 += bias[col + 1]; }
                if (res) {
                    const float2 r2 = *(const float2*)(res + row * (size_t)N + col);
                    v0 += r2.x; v1 += r2.y;
                }
                if (RELU) { v0 = fmaxf(v0, 0.f); v1 = fmaxf(v1, 0.f); }
                if (ROPE && col < 2048) {
                    int t = (int)(row & (T_LEN - 1));
                    int p = ((int)col & 63) >> 1;
                    float2 c2 = cs[t * 32 + p];
                    float r0 = v0 * c2.x - v1 * c2.y;
                    float r1 = v0 * c2.y + v1 * c2.x;
                    v0 = r0; v1 = r1;
                }
                size_t o = row * (size_t)N + col;
                if (SPLIT) {
                    __nv_bfloat16 h0 = __float2bfloat16(v0);
                    __nv_bfloat16 h1 = __float2bfloat16(v1);
                    Oh[o] = h0;     Ol[o] = __float2bfloat16(v0 - __bfloat162float(h0));
                    Oh[o + 1] = h1; Ol[o + 1] = __float2bfloat16(v1 - __bfloat162float(h1));
                } else {
                    *(float2*)(C + o) = make_float2(v0, v1);
                }
            }
        }
    }
}

/* ================= HMMA GEMM 128x256 (wide: QKV / W1 / LM head) ========== */
#define WA     (128 * ROWB)          /* 10240 */
#define WB     (256 * ROWB)          /* 20480 */
#define WSA_H  0
#define WSA_L  WA
#define WSB_H  (2 * WA)
#define WSB_L  (2 * WA + WB)
#define WSTAGE (2 * WA + 2 * WB)     /* 61440 */
#define WSMTOT (2 * WSTAGE)          /* 122880 */

template<bool RELU, bool SPLIT, bool ROPE>
__global__ __launch_bounds__(256, 1)
void mma_gemm_w(const __nv_bfloat16* __restrict__ Ah, const __nv_bfloat16* __restrict__ Al,
                const __nv_bfloat16* __restrict__ Bh, const __nv_bfloat16* __restrict__ Bl,
                int K, int N,
                float* __restrict__ C,
                __nv_bfloat16* __restrict__ Oh, __nv_bfloat16* __restrict__ Ol,
                const float* __restrict__ bias, const float* __restrict__ res,
                const float2* __restrict__ cs) {
    extern __shared__ char smem[];
    const uint32_t sb = smem_u32(smem);
    const int tid = threadIdx.x;
    const int lane = tid & 31;
    const int wid = tid >> 5;
    const int warp_m = wid & 1;          /* 64-row slice */
    const int warp_n = wid >> 1;         /* 64-col slice */
    const size_t bm = (size_t)blockIdx.y * 128;
    const size_t bn = (size_t)blockIdx.x * 256;

    float acc[4][8][4];
    #pragma unroll
    for (int i = 0; i < 4; i++)
        #pragma unroll
        for (int j = 0; j < 8; j++)
            #pragma unroll
            for (int q = 0; q < 4; q++) acc[i][j][q] = 0.f;

    const int nc = K >> 5;

    auto load_stage = [&](int c) {
        const int k0 = c << 5;
        const uint32_t sbase = sb + (c & 1) * WSTAGE;
        #pragma unroll
        for (int t = 0; t < 12; t++) {
            int idx = tid + (t << 8);
            const __nv_bfloat16* base;
            uint32_t soff;
            size_t gr;
            int e;
            if (t < 2)      { e = idx;        base = Ah; soff = WSA_H; gr = bm; }
            else if (t < 4) { e = idx - 512;  base = Al; soff = WSA_L; gr = bm; }
            else if (t < 8) { e = idx - 1024; base = Bh; soff = WSB_H; gr = bn; }
            else            { e = idx - 2048; base = Bl; soff = WSB_L; gr = bn; }
            int r = e >> 2, cch = e & 3;
            cp16(sbase + soff + r * ROWB + cch * 16,
                 base + (gr + r) * (size_t)K + k0 + cch * 8);
        }
        cp_commit();
    };

    load_stage(0);

    const uint32_t aRowOff = (uint32_t)((warp_m * 64 + (lane & 15)) * ROWB + ((lane >> 4) << 4));
    const uint32_t bRow4Off = (uint32_t)((warp_n * 64 + ((lane & 16) >> 1) + (lane & 7)) * ROWB
                                         + ((lane & 8) << 1));

    for (int c = 0; c < nc; c++) {
        cp_wait<0>();
        __syncthreads();
        if (c + 1 < nc) load_stage(c + 1);

        const uint32_t st = sb + (c & 1) * WSTAGE;
        const uint32_t aH = st + WSA_H + aRowOff;
        const uint32_t aL = st + WSA_L + aRowOff;
        const uint32_t bH = st + WSB_H + bRow4Off;
        const uint32_t bL = st + WSB_L + bRow4Off;

        #pragma unroll
        for (int kk = 0; kk < 2; kk++) {
            const uint32_t kb = kk * 32;
            uint32_t a[4][4], bh[8][2], bl[8][2];
            #pragma unroll
            for (int p = 0; p < 4; p++) {
                ldmB4(bh[2*p][0], bh[2*p][1], bh[2*p+1][0], bh[2*p+1][1],
                      bH + p * (16 * ROWB) + kb);
                ldmB4(bl[2*p][0], bl[2*p][1], bl[2*p+1][0], bl[2*p+1][1],
                      bL + p * (16 * ROWB) + kb);
            }
            #pragma unroll
            for (int mt = 0; mt < 4; mt++)
                ldmA(a[mt], aH + mt * (16 * ROWB) + kb);
            #pragma unroll
            for (int mt = 0; mt < 4; mt++)
                #pragma unroll
                for (int nt = 0; nt < 8; nt++)
                    mma16816(acc[mt][nt], a[mt], bh[nt]);
            #pragma unroll
            for (int mt = 0; mt < 4; mt++)
                #pragma unroll
                for (int nt = 0; nt < 8; nt++)
                    mma16816(acc[mt][nt], a[mt], bl[nt]);
            #pragma unroll
            for (int mt = 0; mt < 4; mt++)
                ldmA(a[mt], aL + mt * (16 * ROWB) + kb);
            #pragma unroll
            for (int mt = 0; mt < 4; mt++)
                #pragma unroll
                for (int nt = 0; nt < 8; nt++)
                    mma16816(acc[mt][nt], a[mt], bh[nt]);
        }
    }

    #pragma unroll
    for (int mt = 0; mt < 4; mt++) {
        #pragma unroll
        for (int nt = 0; nt < 8; nt++) {
            size_t col = bn + warp_n * 64 + nt * 8 + (lane & 3) * 2;
            #pragma unroll
            for (int half = 0; half < 2; half++) {
                size_t row = bm + warp_m * 64 + mt * 16 + (lane >> 2) + half * 8;
                float v0 = acc[mt][nt][half * 2 + 0];
                float v1 = acc[mt][nt][half * 2 + 1];
                if (bias) { v0 += bias[col]; v1 += bias[col + 1]; }
                if (res) {
                    const float2 r2 = *(const float2*)(res + row * (size_t)N + col);
                    v0 += r2.x; v1 += r2.y;
                }
                if (RELU) { v0 = fmaxf(v0, 0.f); v1 = fmaxf(v1, 0.f); }
                if (ROPE && col < 2048) {
                    int t = (int)(row & (T_LEN - 1));
                    int p = ((int)col & 63) >> 1;
                    float2 c2 = cs[t * 32 + p];
                    float r0 = v0 * c2.x - v1 * c2.y;
                    float r1 = v0 * c2.y + v1 * c2.x;
                    v0 = r0; v1 = r1;
                }
                size_t o = row * (size_t)N + col;
                if (SPLIT) {
                    __nv_bfloat16 h0 = __float2bfloat16(v0);
                    __nv_bfloat16 h1 = __float2bfloat16(v1);
                    Oh[o] = h0;     Ol[o] = __float2bfloat16(v0 - __bfloat162float(h0));
                    Oh[o + 1] = h1; Ol[o + 1] = __float2bfloat16(v1 - __bfloat162float(h1));
                } else {
                    *(float2*)(C + o) = make_float2(v0, v1);
                }
            }
        }
    }
}

/* ================= weight transpose+split ================================ */
__global__ void wt_gen(const float* __restrict__ in, long in_zs,
                       __nv_bfloat16* __restrict__ oh, __nv_bfloat16* __restrict__ ol,
                       long out_zs, int Kd, int Nd) {
    __shared__ float t[32][33];
    int z = blockIdx.z;
    in += (size_t)z * in_zs; oh += (size_t)z * out_zs; ol += (size_t)z * out_zs;
    int n0 = blockIdx.x * 32, k0 = blockIdx.y * 32;
    int tx = threadIdx.x, ty = threadIdx.y;
    #pragma unroll
    for (int j = ty; j < 32; j += 8)
        t[j][tx] = in[(size_t)(k0 + j) * Nd + n0 + tx];
    __syncthreads();
    #pragma unroll
    for (int j = ty; j < 32; j += 8) {
        float v = t[tx][j];
        size_t o = (size_t)(n0 + j) * Kd + k0 + tx;
        __nv_bfloat16 h = __float2bfloat16(v);
        oh[o] = h;
        ol[o] = __float2bfloat16(v - __bfloat162float(h));
    }
}
__global__ void wt_qkv_all(const float* __restrict__ wq, const float* __restrict__ wk,
                           const float* __restrict__ wv,
                           __nv_bfloat16* __restrict__ oh, __nv_bfloat16* __restrict__ ol) {
    __shared__ float t[32][33];
    int z = blockIdx.z;
    int sel = z / 96;
    int zz  = z - sel * 96;
    int l = zz >> 4, h = zz & 15;
    const float* w = (sel == 0) ? wq : (sel == 1) ? wk : wv;
    const float scale = (sel == 0) ? 0.03125f : 1.0f;
    const float* in = w + (size_t)zz * E_DIM * HD;
    size_t orow0 = (size_t)l * 3 * E_DIM + (size_t)sel * E_DIM + h * HD;
    __nv_bfloat16* ohp = oh + orow0 * E_DIM;
    __nv_bfloat16* olp = ol + orow0 * E_DIM;
    int d0 = blockIdx.x * 32, e0 = blockIdx.y * 32;
    int tx = threadIdx.x, ty = threadIdx.y;
    #pragma unroll
    for (int j = ty; j < 32; j += 8)
        t[j][tx] = in[(size_t)(e0 + j) * HD + d0 + tx];
    __syncthreads();
    #pragma unroll
    for (int j = ty; j < 32; j += 8) {
        float v = t[tx][j] * scale;
        size_t o = (size_t)(d0 + j) * E_DIM + e0 + tx;
        __nv_bfloat16 hh = __float2bfloat16(v);
        ohp[o] = hh;
        olp[o] = __float2bfloat16(v - __bfloat162float(hh));
    }
}

/* ================= fused embed + LN1(layer0) + cs table ================== */
__global__ __launch_bounds__(256)
void embed_ln_kernel(const int* __restrict__ idx, const float* __restrict__ emb,
                     const float* __restrict__ g, const float* __restrict__ b,
                     float* __restrict__ x,
                     __nv_bfloat16* __restrict__ yh, __nv_bfloat16* __restrict__ yl) {
    int m = blockIdx.x, tid = threadIdx.x;
    __shared__ float r1[256], r2[256];
    const float4* src = (const float4*)(emb + (size_t)idx[m] * E_DIM);
    float4 v = src[tid];
    ((float4*)(x + (size_t)m * E_DIM))[tid] = v;
    r1[tid] = v.x + v.y + v.z + v.w;
    r2[tid] = v.x * v.x + v.y * v.y + v.z * v.z + v.w * v.w;
    if (m < 128) {
        int i = m * 256 + tid;
        if (i < T_LEN * 32) {
            int t = i >> 5, p = i & 31;
            float invf = powf(10000.f, -(float)(2 * p) / (float)HD);
            float sn, c;
            sincosf((float)t * invf, &sn, &c);
            g_cs[i] = make_float2(c, sn);
        }
    }
    __syncthreads();
    for (int s = 128; s > 0; s >>= 1) {
        if (tid < s) { r1[tid] += r1[tid + s]; r2[tid] += r2[tid + s]; }
        __syncthreads();
    }
    float mean = r1[0] * (1.0f / E_DIM);
    float var  = r2[0] * (1.0f / E_DIM) - mean * mean;
    float rstd = rsqrtf(var + 1e-5f);
    float4 gg = ((const float4*)g)[tid];
    float4 bb = ((const float4*)b)[tid];
    float o[4] = { (v.x - mean) * rstd * gg.x + bb.x, (v.y - mean) * rstd * gg.y + bb.y,
                   (v.z - mean) * rstd * gg.z + bb.z, (v.w - mean) * rstd * gg.w + bb.w };
    size_t base = (size_t)m * E_DIM + tid * 4;
    #pragma unroll
    for (int j = 0; j < 4; j++) {
        __nv_bfloat16 h = __float2bfloat16(o[j]);
        yh[base + j] = h;
        yl[base + j] = __float2bfloat16(o[j] - __bfloat162float(h));
    }
}

__global__ __launch_bounds__(256)
void ln_split_kernel(const float* __restrict__ x, const float* __restrict__ g,
                     const float* __restrict__ b,
                     __nv_bfloat16* __restrict__ yh, __nv_bfloat16* __restrict__ yl) {
    int m = blockIdx.x, tid = threadIdx.x;
    __shared__ float r1[256], r2[256];
    const float4* xr = (const float4*)(x + (size_t)m * E_DIM);
    float4 v = xr[tid];
    r1[tid] = v.x + v.y + v.z + v.w;
    r2[tid] = v.x * v.x + v.y * v.y + v.z * v.z + v.w * v.w;
    __syncthreads();
    for (int s = 128; s > 0; s >>= 1) {
        if (tid < s) { r1[tid] += r1[tid + s]; r2[tid] += r2[tid + s]; }
        __syncthreads();
    }
    float mean = r1[0] * (1.0f / E_DIM);
    float var  = r2[0] * (1.0f / E_DIM) - mean * mean;
    float rstd = rsqrtf(var + 1e-5f);
    float4 gg = ((const float4*)g)[tid];
    float4 bb = ((const float4*)b)[tid];
    float o[4] = { (v.x - mean) * rstd * gg.x + bb.x, (v.y - mean) * rstd * gg.y + bb.y,
                   (v.z - mean) * rstd * gg.z + bb.z, (v.w - mean) * rstd * gg.w + bb.w };
    size_t base = (size_t)m * E_DIM + tid * 4;
    #pragma unroll
    for (int j = 0; j < 4; j++) {
        __nv_bfloat16 h = __float2bfloat16(o[j]);
        yh[base + j] = h;
        yl[base + j] = __float2bfloat16(o[j] - __bfloat162float(h));
    }
}

__global__ void split_kernel(const float* __restrict__ x,
                             __nv_bfloat16* __restrict__ oh, __nv_bfloat16* __restrict__ ol, int n) {
    int i = blockIdx.x * blockDim.x + threadIdx.x;
    if (i < n) {
        float v = x[i];
        __nv_bfloat16 h = __float2bfloat16(v);
        oh[i] = h;
        ol[i] = __float2bfloat16(v - __bfloat162float(h));
    }
}

/* ======== flash attention (HMMA, split-bf16): 64q tiles, 64k chunks ====== */
#define ARS  144
#define ATILE (64 * ARS)
#define ASM  (4 * ATILE)

__global__ __launch_bounds__(128)
void attn_kernel(const __nv_bfloat16* __restrict__ qg_h, const __nv_bfloat16* __restrict__ qg_l,
                 __nv_bfloat16* __restrict__ oh, __nv_bfloat16* __restrict__ ol) {
    extern __shared__ char sm[];
    const uint32_t sb = smem_u32(sm);
    const int tid = threadIdx.x, lane = tid & 31, w = tid >> 5;
    const int qt = blockIdx.x;
    const int b  = blockIdx.y >> 4;
    const int h  = blockIdx.y & 15;
    const int t0 = qt * 64;
    const size_t mbase = (size_t)b * T_LEN;

    for (int i = tid; i < 512; i += 128) {
        int r = i >> 3, c = i & 7;
        size_t src = (mbase + t0 + r) * 3072 + h * 64 + c * 8;
        cp16(sb + r * ARS + c * 16, qg_h + src);
        cp16(sb + ATILE + r * ARS + c * 16, qg_l + src);
    }
    cp_commit(); cp_wait<0>(); __syncthreads();

    uint32_t Qh[4][4], Ql[4][4];
    {
        uint32_t qo = sb + (w * 16 + (lane & 15)) * ARS + ((lane >> 4) << 4);
        #pragma unroll
        for (int ks = 0; ks < 4; ks++) {
            ldmA(Qh[ks], qo + ks * 32);
            ldmA(Ql[ks], qo + ATILE + ks * 32);
        }
    }
    __syncthreads();

    float O[8][4];
    #pragma unroll
    for (int i = 0; i < 8; i++)
        #pragma unroll
        for (int j = 0; j < 4; j++) O[i][j] = 0.f;
    float m0 = -1e30f, m1 = -1e30f, l0 = 0.f, l1 = 0.f;
    const int g = lane >> 2, t4 = lane & 3;
    const int row0 = t0 + w * 16 + g;
    const int row1 = row0 + 8;

    const int nch = qt + 1;
    for (int ch = 0; ch < nch; ch++) {
        const int c0 = ch * 64;
        for (int i = tid; i < 512; i += 128) {
            int r = i >> 3, c = i & 7;
            size_t srck = (mbase + c0 + r) * 3072 + 1024 + h * 64 + c * 8;
            cp16(sb + 0 * ATILE + r * ARS + c * 16, qg_h + srck);
            cp16(sb + 1 * ATILE + r * ARS + c * 16, qg_l + srck);
            cp16(sb + 2 * ATILE + r * ARS + c * 16, qg_h + srck + 1024);
            cp16(sb + 3 * ATILE + r * ARS + c * 16, qg_l + srck + 1024);
        }
        cp_commit(); cp_wait<0>(); __syncthreads();

        float S[8][4];
        const uint32_t kbo = sb + (lane & 7) * ARS + (((lane >> 3) & 1) << 4);
        #pragma unroll
        for (int nt = 0; nt < 8; nt++) {
            #pragma unroll
            for (int j = 0; j < 4; j++) S[nt][j] = 0.f;
            uint32_t kh[4][2], kl[4][2];
            #pragma unroll
            for (int ks = 0; ks < 4; ks++) {
                ldmB(kh[ks], kbo + nt * (8 * ARS) + ks * 32);
                ldmB(kl[ks], kbo + ATILE + nt * (8 * ARS) + ks * 32);
            }
            #pragma unroll
            for (int ks = 0; ks < 4; ks++) {
                mma16816(S[nt], Qh[ks], kh[ks]);
                mma16816(S[nt], Qh[ks], kl[ks]);
                mma16816(S[nt], Ql[ks], kh[ks]);
            }
        }

        if (ch == nch - 1) {
            #pragma unroll
            for (int nt = 0; nt < 8; nt++) {
                int kc = c0 + nt * 8 + 2 * t4;
                if (kc > row0)     S[nt][0] = -1e30f;
                if (kc + 1 > row0) S[nt][1] = -1e30f;
                if (kc > row1)     S[nt][2] = -1e30f;
                if (kc + 1 > row1) S[nt][3] = -1e30f;
            }
        }

        float mc0 = -1e30f, mc1 = -1e30f;
        #pragma unroll
        for (int nt = 0; nt < 8; nt++) {
            mc0 = fmaxf(mc0, fmaxf(S[nt][0], S[nt][1]));
            mc1 = fmaxf(mc1, fmaxf(S[nt][2], S[nt][3]));
        }
        mc0 = fmaxf(mc0, __shfl_xor_sync(~0u, mc0, 1));
        mc0 = fmaxf(mc0, __shfl_xor_sync(~0u, mc0, 2));
        mc1 = fmaxf(mc1, __shfl_xor_sync(~0u, mc1, 1));
        mc1 = fmaxf(mc1, __shfl_xor_sync(~0u, mc1, 2));
        float mn0 = fmaxf(m0, mc0), mn1 = fmaxf(m1, mc1);
        float a0 = __expf(m0 - mn0), a1 = __expf(m1 - mn1);
        m0 = mn0; m1 = mn1;
        float s0 = 0.f, s1 = 0.f;
        #pragma unroll
        for (int nt = 0; nt < 8; nt++) {
            S[nt][0] = __expf(S[nt][0] - mn0); s0 += S[nt][0];
            S[nt][1] = __expf(S[nt][1] - mn0); s0 += S[nt][1];
            S[nt][2] = __expf(S[nt][2] - mn1); s1 += S[nt][2];
            S[nt][3] = __expf(S[nt][3] - mn1); s1 += S[nt][3];
        }
        s0 += __shfl_xor_sync(~0u, s0, 1); s0 += __shfl_xor_sync(~0u, s0, 2);
        s1 += __shfl_xor_sync(~0u, s1, 1); s1 += __shfl_xor_sync(~0u, s1, 2);
        l0 = l0 * a0 + s0;
        l1 = l1 * a1 + s1;
        #pragma unroll
        for (int nt = 0; nt < 8; nt++) {
            O[nt][0] *= a0; O[nt][1] *= a0; O[nt][2] *= a1; O[nt][3] *= a1;
        }

        #pragma unroll
        for (int ks = 0; ks < 4; ks++) {
            uint32_t Ph[4], Pl[4];
            #pragma unroll
            for (int half = 0; half < 2; half++) {
                float p0 = S[2 * ks + half][0], p1 = S[2 * ks + half][1];
                float p2 = S[2 * ks + half][2], p3 = S[2 * ks + half][3];
                __nv_bfloat16 h0 = __float2bfloat16(p0), h1 = __float2bfloat16(p1);
                __nv_bfloat16 h2 = __float2bfloat16(p2), h3 = __float2bfloat16(p3);
                Ph[half * 2 + 0] = packbf(__bfloat162float(h0), __bfloat162float(h1));
                Ph[half * 2 + 1] = packbf(__bfloat162float(h2), __bfloat162float(h3));
                Pl[half * 2 + 0] = packbf(p0 - __bfloat162float(h0), p1 - __bfloat162float(h1));
                Pl[half * 2 + 1] = packbf(p2 - __bfloat162float(h2), p3 - __bfloat162float(h3));
            }
            uint32_t A_h[4] = { Ph[0], Ph[1], Ph[2], Ph[3] };
            uint32_t A_l[4] = { Pl[0], Pl[1], Pl[2], Pl[3] };
            const uint32_t vbase = sb + 2 * ATILE + (ks * 16 + (lane & 15)) * ARS;
            #pragma unroll
            for (int nt = 0; nt < 8; nt++) {
                uint32_t vh[2], vl[2];
                ldmT(vh, vbase + nt * 16);
                ldmT(vl, vbase + ATILE + nt * 16);
                mma16816(O[nt], A_h, vh);
                mma16816(O[nt], A_h, vl);
                mma16816(O[nt], A_l, vh);
            }
        }
        __syncthreads();
    }

    const float il0 = 1.f / l0, il1 = 1.f / l1;
    #pragma unroll
    for (int nt = 0; nt < 8; nt++) {
        size_t p0 = (mbase + row0) * E_DIM + h * 64 + nt * 8 + 2 * t4;
        size_t p1 = (mbase + row1) * E_DIM + h * 64 + nt * 8 + 2 * t4;
        float o00 = O[nt][0] * il0, o01 = O[nt][1] * il0;
        float o10 = O[nt][2] * il1, o11 = O[nt][3] * il1;
        __nv_bfloat16 h00 = __float2bfloat16(o00), h01 = __float2bfloat16(o01);
        __nv_bfloat16 h10 = __float2bfloat16(o10), h11 = __float2bfloat16(o11);
        oh[p0] = h00;     ol[p0] = __float2bfloat16(o00 - __bfloat162float(h00));
        oh[p0 + 1] = h01; ol[p0 + 1] = __float2bfloat16(o01 - __bfloat162float(h01));
        oh[p1] = h10;     ol[p1] = __float2bfloat16(o10 - __bfloat162float(h10));
        oh[p1 + 1] = h11; ol[p1 + 1] = __float2bfloat16(o11 - __bfloat162float(h11));
    }
}

/* ================= NLL + loss ============================================ */
__global__ __launch_bounds__(256)
void nll_kernel(const float* __restrict__ logits, const int* __restrict__ tgt,
                float* __restrict__ nll) {
    int m = blockIdx.x, tid = threadIdx.x;
    const float* lr = logits + (size_t)m * VOCAB;
    __shared__ float red[256];
    float mx = -1e30f;
    for (int n = tid; n < VOCAB; n += 256) mx = fmaxf(mx, lr[n]);
    red[tid] = mx;
    __syncthreads();
    for (int s = 128; s > 0; s >>= 1) {
        if (tid < s) red[tid] = fmaxf(red[tid], red[tid + s]);
        __syncthreads();
    }
    mx = red[0];
    __syncthreads();
    float sum = 0.f;
    for (int n = tid; n < VOCAB; n += 256) sum += __expf(lr[n] - mx);
    red[tid] = sum;
    __syncthreads();
    for (int s = 128; s > 0; s >>= 1) {
        if (tid < s) red[tid] += red[tid + s];
        __syncthreads();
    }
    if (tid == 0)
        nll[m] = (logf(red[0]) + mx) - lr[tgt[m]];
}

__global__ __launch_bounds__(256)
void loss_reduce_kernel(const float* __restrict__ nll, float* __restrict__ out) {
    __shared__ float red[256];
    int tid = threadIdx.x;
    float s = 0.f;
    for (int i = tid; i < MTOK; i += 256) s += nll[i];
    red[tid] = s;
    __syncthreads();
    for (int k = 128; k > 0; k >>= 1) {
        if (tid < k) red[tid] += red[tid + k];
        __syncthreads();
    }
    if (tid == 0) out[0] = red[0] * (1.0f / MTOK);
}

/* ================= host orchestration ==================================== */
extern "C" void kernel_launch(void* const* d_in, const int* in_sizes, int n_in,
                              void* d_out, int out_size) {
    const int*   idx   = (const int*)  d_in[0];
    const int*   tgt   = (const int*)  d_in[1];
    const float* emb   = (const float*)d_in[2];
    const float* wq    = (const float*)d_in[3];
    const float* wk    = (const float*)d_in[4];
    const float* wv    = (const float*)d_in[5];
    const float* wproj = (const float*)d_in[6];
    const float* bproj = (const float*)d_in[7];
    const float* w1    = (const float*)d_in[8];
    const float* b1    = (const float*)d_in[9];
    const float* w2    = (const float*)d_in[10];
    const float* b2    = (const float*)d_in[11];
    const float* ln1g  = (const float*)d_in[12];
    const float* ln1b  = (const float*)d_in[13];
    const float* ln2g  = (const float*)d_in[14];
    const float* ln2b  = (const float*)d_in[15];
    const float* lm_w  = (const float*)d_in[16];
    const float* lm_b  = (const float*)d_in[17];

    float *x, *nll, *lscr;
    float2* cs;
    __nv_bfloat16 *yh, *yl, *qh, *ql, *oh, *ol, *hh, *hl;
    __nv_bfloat16 *qkvTh, *qkvTl, *projTh, *projTl, *w1Th, *w1Tl, *w2Th, *w2Tl, *lmTh, *lmTl;
    cudaGetSymbolAddress((void**)&x,     g_x);
    cudaGetSymbolAddress((void**)&yh,    g_yh);
    cudaGetSymbolAddress((void**)&yl,    g_yl);
    cudaGetSymbolAddress((void**)&qh,    g_qh);
    cudaGetSymbolAddress((void**)&ql,    g_ql);
    cudaGetSymbolAddress((void**)&oh,    g_oh);
    cudaGetSymbolAddress((void**)&ol,    g_ol);
    cudaGetSymbolAddress((void**)&hh,    g_hh);
    cudaGetSymbolAddress((void**)&hl,    g_hl);
    cudaGetSymbolAddress((void**)&nll,   g_nllv);
    cudaGetSymbolAddress((void**)&lscr,  g_logits_scratch);
    cudaGetSymbolAddress((void**)&cs,    g_cs);
    cudaGetSymbolAddress((void**)&qkvTh, g_qkvT_h);
    cudaGetSymbolAddress((void**)&qkvTl, g_qkvT_l);
    cudaGetSymbolAddress((void**)&projTh, g_projT_h);
    cudaGetSymbolAddress((void**)&projTl, g_projT_l);
    cudaGetSymbolAddress((void**)&w1Th,  g_w1T_h);
    cudaGetSymbolAddress((void**)&w1Tl,  g_w1T_l);
    cudaGetSymbolAddress((void**)&w2Th,  g_w2T_h);
    cudaGetSymbolAddress((void**)&w2Tl,  g_w2T_l);
    cudaGetSymbolAddress((void**)&lmTh,  g_lmT_h);
    cudaGetSymbolAddress((void**)&lmTl,  g_lmT_l);

    cudaFuncSetAttribute(mma_gemm<false, false, false>, cudaFuncAttributeMaxDynamicSharedMemorySize, SMTOT);
    cudaFuncSetAttribute(mma_gemm_w<false, true,  true >, cudaFuncAttributeMaxDynamicSharedMemorySize, WSMTOT);
    cudaFuncSetAttribute(mma_gemm_w<true,  true,  false>, cudaFuncAttributeMaxDynamicSharedMemorySize, WSMTOT);
    cudaFuncSetAttribute(mma_gemm_w<false, false, false>, cudaFuncAttributeMaxDynamicSharedMemorySize, WSMTOT);

    const long BTV = (long)MTOK * VOCAB;
    float* logits = ((long)out_size >= BTV) ? (float*)d_out : lscr;

    dim3 tb(32, 8);
    /* ncu -s 5 (2 harness launches first) captures my launch #3 = wide QKV GEMM */
    embed_ln_kernel<<<MTOK, 256>>>(idx, emb, ln1g, ln1b, x, yh, yl);                   /* 0 */
    wt_qkv_all<<<dim3(2, 32, 288), tb>>>(wq, wk, wv, qkvTh, qkvTl);                    /* 1 */
    wt_gen<<<dim3(32, 32, N_LAYER), tb>>>(wproj, (long)E_DIM * E_DIM, projTh, projTl,  /* 2 */
                                          (long)E_DIM * E_DIM, E_DIM, E_DIM);
    mma_gemm_w<false, true, true><<<dim3(3 * E_DIM / 256, MTOK / 128), 256, WSMTOT>>>( /* 3 */
        yh, yl, qkvTh, qkvTl, E_DIM, 3 * E_DIM,
        nullptr, qh, ql, nullptr, nullptr, (const float2*)cs);
    attn_kernel<<<dim3(T_LEN / 64, BATCH * N_HEAD), 128, ASM>>>(qh, ql, oh, ol);

    wt_gen<<<dim3(128, 32, N_LAYER), tb>>>(w1, (long)E_DIM * FF, w1Th, w1Tl,
                                           (long)E_DIM * FF, E_DIM, FF);
    wt_gen<<<dim3(32, 128, N_LAYER), tb>>>(w2, (long)FF * E_DIM, w2Th, w2Tl,
                                           (long)FF * E_DIM, FF, E_DIM);
    wt_gen<<<dim3(1000, 32, 1), tb>>>(lm_w, 0, lmTh, lmTl, 0, E_DIM, VOCAB);

    for (int l = 0; l < N_LAYER; l++) {
        size_t qkvW = (size_t)l * 3 * E_DIM * E_DIM;
        size_t prW  = (size_t)l * E_DIM * E_DIM;
        size_t w1W  = (size_t)l * FF * E_DIM;

        if (l > 0) {
            ln_split_kernel<<<MTOK, 256>>>(x, ln1g + (size_t)l * E_DIM, ln1b + (size_t)l * E_DIM, yh, yl);
            mma_gemm_w<false, true, true><<<dim3(3 * E_DIM / 256, MTOK / 128), 256, WSMTOT>>>(
                yh, yl, qkvTh + qkvW, qkvTl + qkvW, E_DIM, 3 * E_DIM,
                nullptr, qh, ql, nullptr, nullptr, (const float2*)cs);
            attn_kernel<<<dim3(T_LEN / 64, BATCH * N_HEAD), 128, ASM>>>(qh, ql, oh, ol);
        }

        mma_gemm<false, false, false><<<dim3(E_DIM / 128, MTOK / 128), 256, SMTOT>>>(
            oh, ol, projTh + prW, projTl + prW, E_DIM, E_DIM,
            x, nullptr, nullptr, bproj + (size_t)l * E_DIM, x, nullptr);

        ln_split_kernel<<<MTOK, 256>>>(x, ln2g + (size_t)l * E_DIM, ln2b + (size_t)l * E_DIM, yh, yl);

        mma_gemm_w<true, true, false><<<dim3(FF / 256, MTOK / 128), 256, WSMTOT>>>(
            yh, yl, w1Th + w1W, w1Tl + w1W, E_DIM, FF,
            nullptr, hh, hl, b1 + (size_t)l * FF, nullptr, nullptr);

        mma_gemm<false, false, false><<<dim3(E_DIM / 128, MTOK / 128), 256, SMTOT>>>(
            hh, hl, w2Th + w1W, w2Tl + w1W, FF, E_DIM,
            x, nullptr, nullptr, b2 + (size_t)l * E_DIM, x, nullptr);
    }

    split_kernel<<<(MTOK * E_DIM + 255) / 256, 256>>>(x, yh, yl, MTOK * E_DIM);

    mma_gemm_w<false, false, false><<<dim3(VOCAB / 256, MTOK / 128), 256, WSMTOT>>>(
        yh, yl, lmTh, lmTl, E_DIM, VOCAB,
        logits, nullptr, nullptr, lm_b, nullptr, nullptr);

    nll_kernel<<<MTOK, 256>>>(logits, tgt, nll);

    if ((long)out_size == BTV + 1) {
        loss_reduce_kernel<<<1, 256>>>(nll, (float*)d_out + BTV);
    } else if ((long)out_size < BTV) {
        loss_reduce_kernel<<<1, 256>>>(nll, (float*)d_out);
    }
}

// round 12
// speedup vs baseline: 1.0450x; 1.0450x over previous
#include <cuda_runtime.h>
#include <cuda_bf16.h>
#include <math.h>
#include <cstdint>

#define E_DIM   1024
#define N_HEAD  16
#define HD      64
#define T_LEN   1024
#define N_LAYER 6
#define VOCAB   32000
#define BATCH   2
#define MTOK    (BATCH * T_LEN)     /* 2048 */
#define FF      (4 * E_DIM)         /* 4096 */

/* ================= scratch =============================================== */
__device__ float g_x   [MTOK * E_DIM];
__device__ __nv_bfloat16 g_yh[MTOK * E_DIM];
__device__ __nv_bfloat16 g_yl[MTOK * E_DIM];
__device__ __nv_bfloat16 g_qh[(size_t)MTOK * 3 * E_DIM];
__device__ __nv_bfloat16 g_ql[(size_t)MTOK * 3 * E_DIM];
__device__ __nv_bfloat16 g_oh[MTOK * E_DIM];
__device__ __nv_bfloat16 g_ol[MTOK * E_DIM];
__device__ __nv_bfloat16 g_hh[(size_t)MTOK * FF];
__device__ __nv_bfloat16 g_hl[(size_t)MTOK * FF];
__device__ float g_nllv[MTOK];
__device__ float g_logits_scratch[(size_t)MTOK * VOCAB];
__device__ float2 g_cs[T_LEN * 32];
__device__ __nv_bfloat16 g_qkvT_h[(size_t)N_LAYER * 3 * E_DIM * E_DIM];
__device__ __nv_bfloat16 g_qkvT_l[(size_t)N_LAYER * 3 * E_DIM * E_DIM];
__device__ __nv_bfloat16 g_projT_h[(size_t)N_LAYER * E_DIM * E_DIM];
__device__ __nv_bfloat16 g_projT_l[(size_t)N_LAYER * E_DIM * E_DIM];
__device__ __nv_bfloat16 g_w1T_h[(size_t)N_LAYER * FF * E_DIM];
__device__ __nv_bfloat16 g_w1T_l[(size_t)N_LAYER * FF * E_DIM];
__device__ __nv_bfloat16 g_w2T_h[(size_t)N_LAYER * E_DIM * FF];
__device__ __nv_bfloat16 g_w2T_l[(size_t)N_LAYER * E_DIM * FF];
__device__ __nv_bfloat16 g_lmT_h[(size_t)VOCAB * E_DIM];
__device__ __nv_bfloat16 g_lmT_l[(size_t)VOCAB * E_DIM];

/* ================= small PTX wrappers ==================================== */
__device__ __forceinline__ uint32_t smem_u32(const void* p) {
    uint32_t a;
    asm("{ .reg .u64 t; cvta.to.shared.u64 t, %1; cvt.u32.u64 %0, t; }" : "=r"(a) : "l"(p));
    return a;
}
__device__ __forceinline__ void cp16(uint32_t s, const void* g) {
    asm volatile("cp.async.cg.shared.global [%0], [%1], 16;" :: "r"(s), "l"(g));
}
__device__ __forceinline__ void cp_commit() { asm volatile("cp.async.commit_group;"); }
template<int N> __device__ __forceinline__ void cp_wait() {
    asm volatile("cp.async.wait_group %0;" :: "n"(N));
}
__device__ __forceinline__ void ldmA(uint32_t* r, uint32_t a) {
    asm volatile("ldmatrix.sync.aligned.m8n8.x4.shared.b16 {%0,%1,%2,%3}, [%4];"
                 : "=r"(r[0]), "=r"(r[1]), "=r"(r[2]), "=r"(r[3]) : "r"(a));
}
__device__ __forceinline__ void ldmB(uint32_t* r, uint32_t a) {
    asm volatile("ldmatrix.sync.aligned.m8n8.x2.shared.b16 {%0,%1}, [%2];"
                 : "=r"(r[0]), "=r"(r[1]) : "r"(a));
}
__device__ __forceinline__ void ldmB4(uint32_t& r0, uint32_t& r1, uint32_t& r2, uint32_t& r3,
                                      uint32_t a) {
    asm volatile("ldmatrix.sync.aligned.m8n8.x4.shared.b16 {%0,%1,%2,%3}, [%4];"
                 : "=r"(r0), "=r"(r1), "=r"(r2), "=r"(r3) : "r"(a));
}
__device__ __forceinline__ void ldmT(uint32_t* r, uint32_t a) {
    asm volatile("ldmatrix.sync.aligned.m8n8.x2.trans.shared.b16 {%0,%1}, [%2];"
                 : "=r"(r[0]), "=r"(r[1]) : "r"(a));
}
__device__ __forceinline__ void mma16816(float* c, const uint32_t* a, const uint32_t* b) {
    asm volatile("mma.sync.aligned.m16n8k16.row.col.f32.bf16.bf16.f32 "
                 "{%0,%1,%2,%3}, {%4,%5,%6,%7}, {%8,%9}, {%0,%1,%2,%3};"
                 : "+f"(c[0]), "+f"(c[1]), "+f"(c[2]), "+f"(c[3])
                 : "r"(a[0]), "r"(a[1]), "r"(a[2]), "r"(a[3]), "r"(b[0]), "r"(b[1]));
}
__device__ __forceinline__ uint32_t packbf(float a, float b) {
    __nv_bfloat162 t = __floats2bfloat162_rn(a, b);
    return *(uint32_t*)&t;
}

/* ================= HMMA GEMM 128x128 (N=1024: proj, W2) ================== */
#define ROWB   80
#define TILEB  (128 * ROWB)
#define STAGEB (4 * TILEB)
#define SMTOT  (2 * STAGEB)

template<bool RELU, bool SPLIT, bool ROPE>
__global__ __launch_bounds__(256, 2)
void mma_gemm(const __nv_bfloat16* __restrict__ Ah, const __nv_bfloat16* __restrict__ Al,
              const __nv_bfloat16* __restrict__ Bh, const __nv_bfloat16* __restrict__ Bl,
              int K, int N,
              float* __restrict__ C,
              __nv_bfloat16* __restrict__ Oh, __nv_bfloat16* __restrict__ Ol,
              const float* __restrict__ bias, const float* __restrict__ res,
              const float2* __restrict__ cs) {
    extern __shared__ char smem[];
    const uint32_t sb = smem_u32(smem);
    const int tid = threadIdx.x;
    const int lane = tid & 31;
    const int wid = tid >> 5;
    const int warp_m = wid & 1;
    const int warp_n = wid >> 1;
    const size_t bm = (size_t)blockIdx.y * 128;
    const size_t bn = (size_t)blockIdx.x * 128;

    float acc[4][4][4];
    #pragma unroll
    for (int i = 0; i < 4; i++)
        #pragma unroll
        for (int j = 0; j < 4; j++)
            #pragma unroll
            for (int q = 0; q < 4; q++) acc[i][j][q] = 0.f;

    const int nc = K >> 5;

    auto load_stage = [&](int c) {
        const int k0 = c << 5;
        const uint32_t sbase = sb + (c & 1) * STAGEB;
        #pragma unroll
        for (int t = 0; t < 8; t++) {
            int idx = tid + (t << 8);
            int tile = idx >> 9;
            int r    = (idx >> 2) & 127;
            int cch  = idx & 3;
            const __nv_bfloat16* base = (tile == 0) ? Ah : (tile == 1) ? Al
                                      : (tile == 2) ? Bh : Bl;
            size_t grow = ((tile < 2) ? bm : bn) + r;
            const __nv_bfloat16* g = base + grow * (size_t)K + k0 + cch * 8;
            cp16(sbase + tile * TILEB + r * ROWB + cch * 16, g);
        }
        cp_commit();
    };

    load_stage(0);

    const uint32_t aRowOff = (uint32_t)((warp_m * 64 + (lane & 15)) * ROWB + ((lane >> 4) << 4));
    const uint32_t bRow4Off = (uint32_t)((warp_n * 32 + ((lane & 16) >> 1) + (lane & 7)) * ROWB
                                         + ((lane & 8) << 1));

    for (int c = 0; c < nc; c++) {
        cp_wait<0>();
        __syncthreads();
        if (c + 1 < nc) load_stage(c + 1);

        const uint32_t st = sb + (c & 1) * STAGEB;
        const uint32_t aH = st + aRowOff;
        const uint32_t aL = st + TILEB + aRowOff;
        const uint32_t bH = st + 2 * TILEB + bRow4Off;
        const uint32_t bL = st + 3 * TILEB + bRow4Off;

        #pragma unroll
        for (int kk = 0; kk < 2; kk++) {
            const uint32_t kb = kk * 32;
            uint32_t a[4][4], bh[4][2], bl[4][2];
            #pragma unroll
            for (int p = 0; p < 2; p++) {
                ldmB4(bh[2*p][0], bh[2*p][1], bh[2*p+1][0], bh[2*p+1][1],
                      bH + p * (16 * ROWB) + kb);
                ldmB4(bl[2*p][0], bl[2*p][1], bl[2*p+1][0], bl[2*p+1][1],
                      bL + p * (16 * ROWB) + kb);
            }
            #pragma unroll
            for (int mt = 0; mt < 4; mt++)
                ldmA(a[mt], aH + mt * (16 * ROWB) + kb);
            #pragma unroll
            for (int mt = 0; mt < 4; mt++)
                #pragma unroll
                for (int nt = 0; nt < 4; nt++)
                    mma16816(acc[mt][nt], a[mt], bh[nt]);
            #pragma unroll
            for (int mt = 0; mt < 4; mt++)
                #pragma unroll
                for (int nt = 0; nt < 4; nt++)
                    mma16816(acc[mt][nt], a[mt], bl[nt]);
            #pragma unroll
            for (int mt = 0; mt < 4; mt++)
                ldmA(a[mt], aL + mt * (16 * ROWB) + kb);
            #pragma unroll
            for (int mt = 0; mt < 4; mt++)
                #pragma unroll
                for (int nt = 0; nt < 4; nt++)
                    mma16816(acc[mt][nt], a[mt], bh[nt]);
        }
    }

    #pragma unroll
    for (int mt = 0; mt < 4; mt++) {
        #pragma unroll
        for (int nt = 0; nt < 4; nt++) {
            size_t col = bn + warp_n * 32 + nt * 8 + (lane & 3) * 2;
            #pragma unroll
            for (int half = 0; half < 2; half++) {
                size_t row = bm + warp_m * 64 + mt * 16 + (lane >> 2) + half * 8;
                float v0 = acc[mt][nt][half * 2 + 0];
                float v1 = acc[mt][nt][half * 2 + 1];
                if (bias) { v0 += bias[col]; v1 += bias[col + 1]; }
                if (res) {
                    const float2 r2 = *(const float2*)(res + row * (size_t)N + col);
                    v0 += r2.x; v1 += r2.y;
                }
                if (RELU) { v0 = fmaxf(v0, 0.f); v1 = fmaxf(v1, 0.f); }
                if (ROPE && col < 2048) {
                    int t = (int)(row & (T_LEN - 1));
                    int p = ((int)col & 63) >> 1;
                    float2 c2 = cs[t * 32 + p];
                    float r0 = v0 * c2.x - v1 * c2.y;
                    float r1 = v0 * c2.y + v1 * c2.x;
                    v0 = r0; v1 = r1;
                }
                size_t o = row * (size_t)N + col;
                if (SPLIT) {
                    __nv_bfloat16 h0 = __float2bfloat16(v0);
                    __nv_bfloat16 h1 = __float2bfloat16(v1);
                    Oh[o] = h0;     Ol[o] = __float2bfloat16(v0 - __bfloat162float(h0));
                    Oh[o + 1] = h1; Ol[o + 1] = __float2bfloat16(v1 - __bfloat162float(h1));
                } else {
                    *(float2*)(C + o) = make_float2(v0, v1);
                }
            }
        }
    }
}

/* ============ HMMA GEMM 128x256, 512 threads (QKV / W1 / LM head) ======== */
#define WA     (128 * ROWB)          /* 10240 */
#define WB     (256 * ROWB)          /* 20480 */
#define WSA_H  0
#define WSA_L  WA
#define WSB_H  (2 * WA)
#define WSB_L  (2 * WA + WB)
#define WSTAGE (2 * WA + 2 * WB)     /* 61440 */
#define WSMTOT (2 * WSTAGE)          /* 122880 */

template<bool RELU, bool SPLIT, bool ROPE>
__global__ __launch_bounds__(512, 1)
void mma_gemm_w(const __nv_bfloat16* __restrict__ Ah, const __nv_bfloat16* __restrict__ Al,
                const __nv_bfloat16* __restrict__ Bh, const __nv_bfloat16* __restrict__ Bl,
                int K, int N,
                float* __restrict__ C,
                __nv_bfloat16* __restrict__ Oh, __nv_bfloat16* __restrict__ Ol,
                const float* __restrict__ bias, const float* __restrict__ res,
                const float2* __restrict__ cs) {
    extern __shared__ char smem[];
    const uint32_t sb = smem_u32(smem);
    const int tid = threadIdx.x;
    const int lane = tid & 31;
    const int wid = tid >> 5;            /* 0..15 */
    const int warp_m = wid & 1;          /* 64-row slice */
    const int warp_n = wid >> 1;         /* 0..7: 32-col slice */
    const size_t bm = (size_t)blockIdx.y * 128;
    const size_t bn = (size_t)blockIdx.x * 256;

    float acc[4][4][4];                  /* warp tile 64x32 -> 64 regs */
    #pragma unroll
    for (int i = 0; i < 4; i++)
        #pragma unroll
        for (int j = 0; j < 4; j++)
            #pragma unroll
            for (int q = 0; q < 4; q++) acc[i][j][q] = 0.f;

    const int nc = K >> 5;

    auto load_stage = [&](int c) {
        const int k0 = c << 5;
        const uint32_t sbase = sb + (c & 1) * WSTAGE;
        #pragma unroll
        for (int t = 0; t < 6; t++) {
            int idx = tid + (t << 9);    /* 0..3071 */
            const __nv_bfloat16* base;
            uint32_t soff;
            size_t gr;
            int e;
            if (idx < 512)       { e = idx;        base = Ah; soff = WSA_H; gr = bm; }
            else if (idx < 1024) { e = idx - 512;  base = Al; soff = WSA_L; gr = bm; }
            else if (idx < 2048) { e = idx - 1024; base = Bh; soff = WSB_H; gr = bn; }
            else                 { e = idx - 2048; base = Bl; soff = WSB_L; gr = bn; }
            int r = e >> 2, cch = e & 3;
            cp16(sbase + soff + r * ROWB + cch * 16,
                 base + (gr + r) * (size_t)K + k0 + cch * 8);
        }
        cp_commit();
    };

    load_stage(0);

    const uint32_t aRowOff = (uint32_t)((warp_m * 64 + (lane & 15)) * ROWB + ((lane >> 4) << 4));
    const uint32_t bRow4Off = (uint32_t)((warp_n * 32 + ((lane & 16) >> 1) + (lane & 7)) * ROWB
                                         + ((lane & 8) << 1));

    for (int c = 0; c < nc; c++) {
        cp_wait<0>();
        __syncthreads();
        if (c + 1 < nc) load_stage(c + 1);

        const uint32_t st = sb + (c & 1) * WSTAGE;
        const uint32_t aH = st + WSA_H + aRowOff;
        const uint32_t aL = st + WSA_L + aRowOff;
        const uint32_t bH = st + WSB_H + bRow4Off;
        const uint32_t bL = st + WSB_L + bRow4Off;

        #pragma unroll
        for (int kk = 0; kk < 2; kk++) {
            const uint32_t kb = kk * 32;
            uint32_t a[4][4], bh[4][2], bl[4][2];
            #pragma unroll
            for (int p = 0; p < 2; p++) {
                ldmB4(bh[2*p][0], bh[2*p][1], bh[2*p+1][0], bh[2*p+1][1],
                      bH + p * (16 * ROWB) + kb);
                ldmB4(bl[2*p][0], bl[2*p][1], bl[2*p+1][0], bl[2*p+1][1],
                      bL + p * (16 * ROWB) + kb);
            }
            #pragma unroll
            for (int mt = 0; mt < 4; mt++)
                ldmA(a[mt], aH + mt * (16 * ROWB) + kb);
            #pragma unroll
            for (int mt = 0; mt < 4; mt++)
                #pragma unroll
                for (int nt = 0; nt < 4; nt++)
                    mma16816(acc[mt][nt], a[mt], bh[nt]);
            #pragma unroll
            for (int mt = 0; mt < 4; mt++)
                #pragma unroll
                for (int nt = 0; nt < 4; nt++)
                    mma16816(acc[mt][nt], a[mt], bl[nt]);
            #pragma unroll
            for (int mt = 0; mt < 4; mt++)
                ldmA(a[mt], aL + mt * (16 * ROWB) + kb);
            #pragma unroll
            for (int mt = 0; mt < 4; mt++)
                #pragma unroll
                for (int nt = 0; nt < 4; nt++)
                    mma16816(acc[mt][nt], a[mt], bh[nt]);
        }
    }

    #pragma unroll
    for (int mt = 0; mt < 4; mt++) {
        #pragma unroll
        for (int nt = 0; nt < 4; nt++) {
            size_t col = bn + warp_n * 32 + nt * 8 + (lane & 3) * 2;
            #pragma unroll
            for (int half = 0; half < 2; half++) {
                size_t row = bm + warp_m * 64 + mt * 16 + (lane >> 2) + half * 8;
                float v0 = acc[mt][nt][half * 2 + 0];
                float v1 = acc[mt][nt][half * 2 + 1];
                if (bias) { v0 += bias[col]; v1 += bias[col + 1]; }
                if (res) {
                    const float2 r2 = *(const float2*)(res + row * (size_t)N + col);
                    v0 += r2.x; v1 += r2.y;
                }
                if (RELU) { v0 = fmaxf(v0, 0.f); v1 = fmaxf(v1, 0.f); }
                if (ROPE && col < 2048) {
                    int t = (int)(row & (T_LEN - 1));
                    int p = ((int)col & 63) >> 1;
                    float2 c2 = cs[t * 32 + p];
                    float r0 = v0 * c2.x - v1 * c2.y;
                    float r1 = v0 * c2.y + v1 * c2.x;
                    v0 = r0; v1 = r1;
                }
                size_t o = row * (size_t)N + col;
                if (SPLIT) {
                    __nv_bfloat16 h0 = __float2bfloat16(v0);
                    __nv_bfloat16 h1 = __float2bfloat16(v1);
                    Oh[o] = h0;     Ol[o] = __float2bfloat16(v0 - __bfloat162float(h0));
                    Oh[o + 1] = h1; Ol[o + 1] = __float2bfloat16(v1 - __bfloat162float(h1));
                } else {
                    *(float2*)(C + o) = make_float2(v0, v1);
                }
            }
        }
    }
}

/* ================= weight transpose+split ================================ */
__global__ void wt_gen(const float* __restrict__ in, long in_zs,
                       __nv_bfloat16* __restrict__ oh, __nv_bfloat16* __restrict__ ol,
                       long out_zs, int Kd, int Nd) {
    __shared__ float t[32][33];
    int z = blockIdx.z;
    in += (size_t)z * in_zs; oh += (size_t)z * out_zs; ol += (size_t)z * out_zs;
    int n0 = blockIdx.x * 32, k0 = blockIdx.y * 32;
    int tx = threadIdx.x, ty = threadIdx.y;
    #pragma unroll
    for (int j = ty; j < 32; j += 8)
        t[j][tx] = in[(size_t)(k0 + j) * Nd + n0 + tx];
    __syncthreads();
    #pragma unroll
    for (int j = ty; j < 32; j += 8) {
        float v = t[tx][j];
        size_t o = (size_t)(n0 + j) * Kd + k0 + tx;
        __nv_bfloat16 h = __float2bfloat16(v);
        oh[o] = h;
        ol[o] = __float2bfloat16(v - __bfloat162float(h));
    }
}
__global__ void wt_qkv_all(const float* __restrict__ wq, const float* __restrict__ wk,
                           const float* __restrict__ wv,
                           __nv_bfloat16* __restrict__ oh, __nv_bfloat16* __restrict__ ol) {
    __shared__ float t[32][33];
    int z = blockIdx.z;
    int sel = z / 96;
    int zz  = z - sel * 96;
    int l = zz >> 4, h = zz & 15;
    const float* w = (sel == 0) ? wq : (sel == 1) ? wk : wv;
    const float scale = (sel == 0) ? 0.03125f : 1.0f;
    const float* in = w + (size_t)zz * E_DIM * HD;
    size_t orow0 = (size_t)l * 3 * E_DIM + (size_t)sel * E_DIM + h * HD;
    __nv_bfloat16* ohp = oh + orow0 * E_DIM;
    __nv_bfloat16* olp = ol + orow0 * E_DIM;
    int d0 = blockIdx.x * 32, e0 = blockIdx.y * 32;
    int tx = threadIdx.x, ty = threadIdx.y;
    #pragma unroll
    for (int j = ty; j < 32; j += 8)
        t[j][tx] = in[(size_t)(e0 + j) * HD + d0 + tx];
    __syncthreads();
    #pragma unroll
    for (int j = ty; j < 32; j += 8) {
        float v = t[tx][j] * scale;
        size_t o = (size_t)(d0 + j) * E_DIM + e0 + tx;
        __nv_bfloat16 hh = __float2bfloat16(v);
        ohp[o] = hh;
        olp[o] = __float2bfloat16(v - __bfloat162float(hh));
    }
}

/* ================= fused embed + LN1(layer0) + cs table ================== */
__global__ __launch_bounds__(256)
void embed_ln_kernel(const int* __restrict__ idx, const float* __restrict__ emb,
                     const float* __restrict__ g, const float* __restrict__ b,
                     float* __restrict__ x,
                     __nv_bfloat16* __restrict__ yh, __nv_bfloat16* __restrict__ yl) {
    int m = blockIdx.x, tid = threadIdx.x;
    __shared__ float r1[256], r2[256];
    const float4* src = (const float4*)(emb + (size_t)idx[m] * E_DIM);
    float4 v = src[tid];
    ((float4*)(x + (size_t)m * E_DIM))[tid] = v;
    r1[tid] = v.x + v.y + v.z + v.w;
    r2[tid] = v.x * v.x + v.y * v.y + v.z * v.z + v.w * v.w;
    if (m < 128) {
        int i = m * 256 + tid;
        if (i < T_LEN * 32) {
            int t = i >> 5, p = i & 31;
            float invf = powf(10000.f, -(float)(2 * p) / (float)HD);
            float sn, c;
            sincosf((float)t * invf, &sn, &c);
            g_cs[i] = make_float2(c, sn);
        }
    }
    __syncthreads();
    for (int s = 128; s > 0; s >>= 1) {
        if (tid < s) { r1[tid] += r1[tid + s]; r2[tid] += r2[tid + s]; }
        __syncthreads();
    }
    float mean = r1[0] * (1.0f / E_DIM);
    float var  = r2[0] * (1.0f / E_DIM) - mean * mean;
    float rstd = rsqrtf(var + 1e-5f);
    float4 gg = ((const float4*)g)[tid];
    float4 bb = ((const float4*)b)[tid];
    float o[4] = { (v.x - mean) * rstd * gg.x + bb.x, (v.y - mean) * rstd * gg.y + bb.y,
                   (v.z - mean) * rstd * gg.z + bb.z, (v.w - mean) * rstd * gg.w + bb.w };
    size_t base = (size_t)m * E_DIM + tid * 4;
    #pragma unroll
    for (int j = 0; j < 4; j++) {
        __nv_bfloat16 h = __float2bfloat16(o[j]);
        yh[base + j] = h;
        yl[base + j] = __float2bfloat16(o[j] - __bfloat162float(h));
    }
}

__global__ __launch_bounds__(256)
void ln_split_kernel(const float* __restrict__ x, const float* __restrict__ g,
                     const float* __restrict__ b,
                     __nv_bfloat16* __restrict__ yh, __nv_bfloat16* __restrict__ yl) {
    int m = blockIdx.x, tid = threadIdx.x;
    __shared__ float r1[256], r2[256];
    const float4* xr = (const float4*)(x + (size_t)m * E_DIM);
    float4 v = xr[tid];
    r1[tid] = v.x + v.y + v.z + v.w;
    r2[tid] = v.x * v.x + v.y * v.y + v.z * v.z + v.w * v.w;
    __syncthreads();
    for (int s = 128; s > 0; s >>= 1) {
        if (tid < s) { r1[tid] += r1[tid + s]; r2[tid] += r2[tid + s]; }
        __syncthreads();
    }
    float mean = r1[0] * (1.0f / E_DIM);
    float var  = r2[0] * (1.0f / E_DIM) - mean * mean;
    float rstd = rsqrtf(var + 1e-5f);
    float4 gg = ((const float4*)g)[tid];
    float4 bb = ((const float4*)b)[tid];
    float o[4] = { (v.x - mean) * rstd * gg.x + bb.x, (v.y - mean) * rstd * gg.y + bb.y,
                   (v.z - mean) * rstd * gg.z + bb.z, (v.w - mean) * rstd * gg.w + bb.w };
    size_t base = (size_t)m * E_DIM + tid * 4;
    #pragma unroll
    for (int j = 0; j < 4; j++) {
        __nv_bfloat16 h = __float2bfloat16(o[j]);
        yh[base + j] = h;
        yl[base + j] = __float2bfloat16(o[j] - __bfloat162float(h));
    }
}

__global__ void split_kernel(const float* __restrict__ x,
                             __nv_bfloat16* __restrict__ oh, __nv_bfloat16* __restrict__ ol, int n) {
    int i = blockIdx.x * blockDim.x + threadIdx.x;
    if (i < n) {
        float v = x[i];
        __nv_bfloat16 h = __float2bfloat16(v);
        oh[i] = h;
        ol[i] = __float2bfloat16(v - __bfloat162float(h));
    }
}

/* ======== flash attention (HMMA, split-bf16): 64q tiles, 64k chunks ====== */
#define ARS  144
#define ATILE (64 * ARS)
#define ASM  (4 * ATILE)

__global__ __launch_bounds__(128)
void attn_kernel(const __nv_bfloat16* __restrict__ qg_h, const __nv_bfloat16* __restrict__ qg_l,
                 __nv_bfloat16* __restrict__ oh, __nv_bfloat16* __restrict__ ol) {
    extern __shared__ char sm[];
    const uint32_t sb = smem_u32(sm);
    const int tid = threadIdx.x, lane = tid & 31, w = tid >> 5;
    const int qt = blockIdx.x;
    const int b  = blockIdx.y >> 4;
    const int h  = blockIdx.y & 15;
    const int t0 = qt * 64;
    const size_t mbase = (size_t)b * T_LEN;

    for (int i = tid; i < 512; i += 128) {
        int r = i >> 3, c = i & 7;
        size_t src = (mbase + t0 + r) * 3072 + h * 64 + c * 8;
        cp16(sb + r * ARS + c * 16, qg_h + src);
        cp16(sb + ATILE + r * ARS + c * 16, qg_l + src);
    }
    cp_commit(); cp_wait<0>(); __syncthreads();

    uint32_t Qh[4][4], Ql[4][4];
    {
        uint32_t qo = sb + (w * 16 + (lane & 15)) * ARS + ((lane >> 4) << 4);
        #pragma unroll
        for (int ks = 0; ks < 4; ks++) {
            ldmA(Qh[ks], qo + ks * 32);
            ldmA(Ql[ks], qo + ATILE + ks * 32);
        }
    }
    __syncthreads();

    float O[8][4];
    #pragma unroll
    for (int i = 0; i < 8; i++)
        #pragma unroll
        for (int j = 0; j < 4; j++) O[i][j] = 0.f;
    float m0 = -1e30f, m1 = -1e30f, l0 = 0.f, l1 = 0.f;
    const int g = lane >> 2, t4 = lane & 3;
    const int row0 = t0 + w * 16 + g;
    const int row1 = row0 + 8;

    const int nch = qt + 1;
    for (int ch = 0; ch < nch; ch++) {
        const int c0 = ch * 64;
        for (int i = tid; i < 512; i += 128) {
            int r = i >> 3, c = i & 7;
            size_t srck = (mbase + c0 + r) * 3072 + 1024 + h * 64 + c * 8;
            cp16(sb + 0 * ATILE + r * ARS + c * 16, qg_h + srck);
            cp16(sb + 1 * ATILE + r * ARS + c * 16, qg_l + srck);
            cp16(sb + 2 * ATILE + r * ARS + c * 16, qg_h + srck + 1024);
            cp16(sb + 3 * ATILE + r * ARS + c * 16, qg_l + srck + 1024);
        }
        cp_commit(); cp_wait<0>(); __syncthreads();

        float S[8][4];
        const uint32_t kbo = sb + (lane & 7) * ARS + (((lane >> 3) & 1) << 4);
        #pragma unroll
        for (int nt = 0; nt < 8; nt++) {
            #pragma unroll
            for (int j = 0; j < 4; j++) S[nt][j] = 0.f;
            uint32_t kh[4][2], kl[4][2];
            #pragma unroll
            for (int ks = 0; ks < 4; ks++) {
                ldmB(kh[ks], kbo + nt * (8 * ARS) + ks * 32);
                ldmB(kl[ks], kbo + ATILE + nt * (8 * ARS) + ks * 32);
            }
            #pragma unroll
            for (int ks = 0; ks < 4; ks++) {
                mma16816(S[nt], Qh[ks], kh[ks]);
                mma16816(S[nt], Qh[ks], kl[ks]);
                mma16816(S[nt], Ql[ks], kh[ks]);
            }
        }

        if (ch == nch - 1) {
            #pragma unroll
            for (int nt = 0; nt < 8; nt++) {
                int kc = c0 + nt * 8 + 2 * t4;
                if (kc > row0)     S[nt][0] = -1e30f;
                if (kc + 1 > row0) S[nt][1] = -1e30f;
                if (kc > row1)     S[nt][2] = -1e30f;
                if (kc + 1 > row1) S[nt][3] = -1e30f;
            }
        }

        float mc0 = -1e30f, mc1 = -1e30f;
        #pragma unroll
        for (int nt = 0; nt < 8; nt++) {
            mc0 = fmaxf(mc0, fmaxf(S[nt][0], S[nt][1]));
            mc1 = fmaxf(mc1, fmaxf(S[nt][2], S[nt][3]));
        }
        mc0 = fmaxf(mc0, __shfl_xor_sync(~0u, mc0, 1));
        mc0 = fmaxf(mc0, __shfl_xor_sync(~0u, mc0, 2));
        mc1 = fmaxf(mc1, __shfl_xor_sync(~0u, mc1, 1));
        mc1 = fmaxf(mc1, __shfl_xor_sync(~0u, mc1, 2));
        float mn0 = fmaxf(m0, mc0), mn1 = fmaxf(m1, mc1);
        float a0 = __expf(m0 - mn0), a1 = __expf(m1 - mn1);
        m0 = mn0; m1 = mn1;
        float s0 = 0.f, s1 = 0.f;
        #pragma unroll
        for (int nt = 0; nt < 8; nt++) {
            S[nt][0] = __expf(S[nt][0] - mn0); s0 += S[nt][0];
            S[nt][1] = __expf(S[nt][1] - mn0); s0 += S[nt][1];
            S[nt][2] = __expf(S[nt][2] - mn1); s1 += S[nt][2];
            S[nt][3] = __expf(S[nt][3] - mn1); s1 += S[nt][3];
        }
        s0 += __shfl_xor_sync(~0u, s0, 1); s0 += __shfl_xor_sync(~0u, s0, 2);
        s1 += __shfl_xor_sync(~0u, s1, 1); s1 += __shfl_xor_sync(~0u, s1, 2);
        l0 = l0 * a0 + s0;
        l1 = l1 * a1 + s1;
        #pragma unroll
        for (int nt = 0; nt < 8; nt++) {
            O[nt][0] *= a0; O[nt][1] *= a0; O[nt][2] *= a1; O[nt][3] *= a1;
        }

        #pragma unroll
        for (int ks = 0; ks < 4; ks++) {
            uint32_t Ph[4], Pl[4];
            #pragma unroll
            for (int half = 0; half < 2; half++) {
                float p0 = S[2 * ks + half][0], p1 = S[2 * ks + half][1];
                float p2 = S[2 * ks + half][2], p3 = S[2 * ks + half][3];
                __nv_bfloat16 h0 = __float2bfloat16(p0), h1 = __float2bfloat16(p1);
                __nv_bfloat16 h2 = __float2bfloat16(p2), h3 = __float2bfloat16(p3);
                Ph[half * 2 + 0] = packbf(__bfloat162float(h0), __bfloat162float(h1));
                Ph[half * 2 + 1] = packbf(__bfloat162float(h2), __bfloat162float(h3));
                Pl[half * 2 + 0] = packbf(p0 - __bfloat162float(h0), p1 - __bfloat162float(h1));
                Pl[half * 2 + 1] = packbf(p2 - __bfloat162float(h2), p3 - __bfloat162float(h3));
            }
            uint32_t A_h[4] = { Ph[0], Ph[1], Ph[2], Ph[3] };
            uint32_t A_l[4] = { Pl[0], Pl[1], Pl[2], Pl[3] };
            const uint32_t vbase = sb + 2 * ATILE + (ks * 16 + (lane & 15)) * ARS;
            #pragma unroll
            for (int nt = 0; nt < 8; nt++) {
                uint32_t vh[2], vl[2];
                ldmT(vh, vbase + nt * 16);
                ldmT(vl, vbase + ATILE + nt * 16);
                mma16816(O[nt], A_h, vh);
                mma16816(O[nt], A_h, vl);
                mma16816(O[nt], A_l, vh);
            }
        }
        __syncthreads();
    }

    const float il0 = 1.f / l0, il1 = 1.f / l1;
    #pragma unroll
    for (int nt = 0; nt < 8; nt++) {
        size_t p0 = (mbase + row0) * E_DIM + h * 64 + nt * 8 + 2 * t4;
        size_t p1 = (mbase + row1) * E_DIM + h * 64 + nt * 8 + 2 * t4;
        float o00 = O[nt][0] * il0, o01 = O[nt][1] * il0;
        float o10 = O[nt][2] * il1, o11 = O[nt][3] * il1;
        __nv_bfloat16 h00 = __float2bfloat16(o00), h01 = __float2bfloat16(o01);
        __nv_bfloat16 h10 = __float2bfloat16(o10), h11 = __float2bfloat16(o11);
        oh[p0] = h00;     ol[p0] = __float2bfloat16(o00 - __bfloat162float(h00));
        oh[p0 + 1] = h01; ol[p0 + 1] = __float2bfloat16(o01 - __bfloat162float(h01));
        oh[p1] = h10;     ol[p1] = __float2bfloat16(o10 - __bfloat162float(h10));
        oh[p1 + 1] = h11; ol[p1 + 1] = __float2bfloat16(o11 - __bfloat162float(h11));
    }
}

/* ================= NLL + loss ============================================ */
__global__ __launch_bounds__(256)
void nll_kernel(const float* __restrict__ logits, const int* __restrict__ tgt,
                float* __restrict__ nll) {
    int m = blockIdx.x, tid = threadIdx.x;
    const float* lr = logits + (size_t)m * VOCAB;
    __shared__ float red[256];
    float mx = -1e30f;
    for (int n = tid; n < VOCAB; n += 256) mx = fmaxf(mx, lr[n]);
    red[tid] = mx;
    __syncthreads();
    for (int s = 128; s > 0; s >>= 1) {
        if (tid < s) red[tid] = fmaxf(red[tid], red[tid + s]);
        __syncthreads();
    }
    mx = red[0];
    __syncthreads();
    float sum = 0.f;
    for (int n = tid; n < VOCAB; n += 256) sum += __expf(lr[n] - mx);
    red[tid] = sum;
    __syncthreads();
    for (int s = 128; s > 0; s >>= 1) {
        if (tid < s) red[tid] += red[tid + s];
        __syncthreads();
    }
    if (tid == 0)
        nll[m] = (logf(red[0]) + mx) - lr[tgt[m]];
}

__global__ __launch_bounds__(256)
void loss_reduce_kernel(const float* __restrict__ nll, float* __restrict__ out) {
    __shared__ float red[256];
    int tid = threadIdx.x;
    float s = 0.f;
    for (int i = tid; i < MTOK; i += 256) s += nll[i];
    red[tid] = s;
    __syncthreads();
    for (int k = 128; k > 0; k >>= 1) {
        if (tid < k) red[tid] += red[tid + k];
        __syncthreads();
    }
    if (tid == 0) out[0] = red[0] * (1.0f / MTOK);
}

/* ================= host orchestration ==================================== */
extern "C" void kernel_launch(void* const* d_in, const int* in_sizes, int n_in,
                              void* d_out, int out_size) {
    const int*   idx   = (const int*)  d_in[0];
    const int*   tgt   = (const int*)  d_in[1];
    const float* emb   = (const float*)d_in[2];
    const float* wq    = (const float*)d_in[3];
    const float* wk    = (const float*)d_in[4];
    const float* wv    = (const float*)d_in[5];
    const float* wproj = (const float*)d_in[6];
    const float* bproj = (const float*)d_in[7];
    const float* w1    = (const float*)d_in[8];
    const float* b1    = (const float*)d_in[9];
    const float* w2    = (const float*)d_in[10];
    const float* b2    = (const float*)d_in[11];
    const float* ln1g  = (const float*)d_in[12];
    const float* ln1b  = (const float*)d_in[13];
    const float* ln2g  = (const float*)d_in[14];
    const float* ln2b  = (const float*)d_in[15];
    const float* lm_w  = (const float*)d_in[16];
    const float* lm_b  = (const float*)d_in[17];

    float *x, *nll, *lscr;
    float2* cs;
    __nv_bfloat16 *yh, *yl, *qh, *ql, *oh, *ol, *hh, *hl;
    __nv_bfloat16 *qkvTh, *qkvTl, *projTh, *projTl, *w1Th, *w1Tl, *w2Th, *w2Tl, *lmTh, *lmTl;
    cudaGetSymbolAddress((void**)&x,     g_x);
    cudaGetSymbolAddress((void**)&yh,    g_yh);
    cudaGetSymbolAddress((void**)&yl,    g_yl);
    cudaGetSymbolAddress((void**)&qh,    g_qh);
    cudaGetSymbolAddress((void**)&ql,    g_ql);
    cudaGetSymbolAddress((void**)&oh,    g_oh);
    cudaGetSymbolAddress((void**)&ol,    g_ol);
    cudaGetSymbolAddress((void**)&hh,    g_hh);
    cudaGetSymbolAddress((void**)&hl,    g_hl);
    cudaGetSymbolAddress((void**)&nll,   g_nllv);
    cudaGetSymbolAddress((void**)&lscr,  g_logits_scratch);
    cudaGetSymbolAddress((void**)&cs,    g_cs);
    cudaGetSymbolAddress((void**)&qkvTh, g_qkvT_h);
    cudaGetSymbolAddress((void**)&qkvTl, g_qkvT_l);
    cudaGetSymbolAddress((void**)&projTh, g_projT_h);
    cudaGetSymbolAddress((void**)&projTl, g_projT_l);
    cudaGetSymbolAddress((void**)&w1Th,  g_w1T_h);
    cudaGetSymbolAddress((void**)&w1Tl,  g_w1T_l);
    cudaGetSymbolAddress((void**)&w2Th,  g_w2T_h);
    cudaGetSymbolAddress((void**)&w2Tl,  g_w2T_l);
    cudaGetSymbolAddress((void**)&lmTh,  g_lmT_h);
    cudaGetSymbolAddress((void**)&lmTl,  g_lmT_l);

    cudaFuncSetAttribute(mma_gemm<false, false, false>, cudaFuncAttributeMaxDynamicSharedMemorySize, SMTOT);
    cudaFuncSetAttribute(mma_gemm_w<false, true,  true >, cudaFuncAttributeMaxDynamicSharedMemorySize, WSMTOT);
    cudaFuncSetAttribute(mma_gemm_w<true,  true,  false>, cudaFuncAttributeMaxDynamicSharedMemorySize, WSMTOT);
    cudaFuncSetAttribute(mma_gemm_w<false, false, false>, cudaFuncAttributeMaxDynamicSharedMemorySize, WSMTOT);

    const long BTV = (long)MTOK * VOCAB;
    float* logits = ((long)out_size >= BTV) ? (float*)d_out : lscr;

    dim3 tb(32, 8);
    /* ncu -s 5 (2 harness launches first) captures my launch #3 = wide QKV GEMM */
    embed_ln_kernel<<<MTOK, 256>>>(idx, emb, ln1g, ln1b, x, yh, yl);                   /* 0 */
    wt_qkv_all<<<dim3(2, 32, 288), tb>>>(wq, wk, wv, qkvTh, qkvTl);                    /* 1 */
    wt_gen<<<dim3(32, 32, N_LAYER), tb>>>(wproj, (long)E_DIM * E_DIM, projTh, projTl,  /* 2 */
                                          (long)E_DIM * E_DIM, E_DIM, E_DIM);
    mma_gemm_w<false, true, true><<<dim3(3 * E_DIM / 256, MTOK / 128), 512, WSMTOT>>>( /* 3 */
        yh, yl, qkvTh, qkvTl, E_DIM, 3 * E_DIM,
        nullptr, qh, ql, nullptr, nullptr, (const float2*)cs);
    attn_kernel<<<dim3(T_LEN / 64, BATCH * N_HEAD), 128, ASM>>>(qh, ql, oh, ol);

    wt_gen<<<dim3(128, 32, N_LAYER), tb>>>(w1, (long)E_DIM * FF, w1Th, w1Tl,
                                           (long)E_DIM * FF, E_DIM, FF);
    wt_gen<<<dim3(32, 128, N_LAYER), tb>>>(w2, (long)FF * E_DIM, w2Th, w2Tl,
                                           (long)FF * E_DIM, FF, E_DIM);
    wt_gen<<<dim3(1000, 32, 1), tb>>>(lm_w, 0, lmTh, lmTl, 0, E_DIM, VOCAB);

    for (int l = 0; l < N_LAYER; l++) {
        size_t qkvW = (size_t)l * 3 * E_DIM * E_DIM;
        size_t prW  = (size_t)l * E_DIM * E_DIM;
        size_t w1W  = (size_t)l * FF * E_DIM;

        if (l > 0) {
            ln_split_kernel<<<MTOK, 256>>>(x, ln1g + (size_t)l * E_DIM, ln1b + (size_t)l * E_DIM, yh, yl);
            mma_gemm_w<false, true, true><<<dim3(3 * E_DIM / 256, MTOK / 128), 512, WSMTOT>>>(
                yh, yl, qkvTh + qkvW, qkvTl + qkvW, E_DIM, 3 * E_DIM,
                nullptr, qh, ql, nullptr, nullptr, (const float2*)cs);
            attn_kernel<<<dim3(T_LEN / 64, BATCH * N_HEAD), 128, ASM>>>(qh, ql, oh, ol);
        }

        mma_gemm<false, false, false><<<dim3(E_DIM / 128, MTOK / 128), 256, SMTOT>>>(
            oh, ol, projTh + prW, projTl + prW, E_DIM, E_DIM,
            x, nullptr, nullptr, bproj + (size_t)l * E_DIM, x, nullptr);

        ln_split_kernel<<<MTOK, 256>>>(x, ln2g + (size_t)l * E_DIM, ln2b + (size_t)l * E_DIM, yh, yl);

        mma_gemm_w<true, true, false><<<dim3(FF / 256, MTOK / 128), 512, WSMTOT>>>(
            yh, yl, w1Th + w1W, w1Tl + w1W, E_DIM, FF,
            nullptr, hh, hl, b1 + (size_t)l * FF, nullptr, nullptr);

        mma_gemm<false, false, false><<<dim3(E_DIM / 128, MTOK / 128), 256, SMTOT>>>(
            hh, hl, w2Th + w1W, w2Tl + w1W, FF, E_DIM,
            x, nullptr, nullptr, b2 + (size_t)l * E_DIM, x, nullptr);
    }

    split_kernel<<<(MTOK * E_DIM + 255) / 256, 256>>>(x, yh, yl, MTOK * E_DIM);

    mma_gemm_w<false, false, false><<<dim3(VOCAB / 256, MTOK / 128), 512, WSMTOT>>>(
        yh, yl, lmTh, lmTl, E_DIM, VOCAB,
        logits, nullptr, nullptr, lm_b, nullptr, nullptr);

    nll_kernel<<<MTOK, 256>>>(logits, tgt, nll);

    if ((long)out_size == BTV + 1) {
        loss_reduce_kernel<<<1, 256>>>(nll, (float*)d_out + BTV);
    } else if ((long)out_size < BTV) {
        loss_reduce_kernel<<<1, 256>>>(nll, (float*)d_out);
    }
}

// round 14
// speedup vs baseline: 1.0915x; 1.0445x over previous
#include <cuda_runtime.h>
#include <cuda_bf16.h>
#include <math.h>
#include <cstdint>

#define E_DIM   1024
#define N_HEAD  16
#define HD      64
#define T_LEN   1024
#define N_LAYER 6
#define VOCAB   32000
#define BATCH   2
#define MTOK    (BATCH * T_LEN)     /* 2048 */
#define FF      (4 * E_DIM)         /* 4096 */

/* ================= scratch =============================================== */
__device__ float g_x   [MTOK * E_DIM];
__device__ __nv_bfloat16 g_yh[MTOK * E_DIM];
__device__ __nv_bfloat16 g_yl[MTOK * E_DIM];
__device__ __nv_bfloat16 g_qh[(size_t)MTOK * 3 * E_DIM];
__device__ __nv_bfloat16 g_ql[(size_t)MTOK * 3 * E_DIM];
__device__ __nv_bfloat16 g_oh[MTOK * E_DIM];
__device__ __nv_bfloat16 g_ol[MTOK * E_DIM];
__device__ __nv_bfloat16 g_hh[(size_t)MTOK * FF];
__device__ __nv_bfloat16 g_hl[(size_t)MTOK * FF];
__device__ float g_nllv[MTOK];
__device__ float g_logits_scratch[(size_t)MTOK * VOCAB];
__device__ float2 g_cs[T_LEN * 32];
__device__ __nv_bfloat16 g_qkvT_h[(size_t)N_LAYER * 3 * E_DIM * E_DIM];
__device__ __nv_bfloat16 g_qkvT_l[(size_t)N_LAYER * 3 * E_DIM * E_DIM];
__device__ __nv_bfloat16 g_projT_h[(size_t)N_LAYER * E_DIM * E_DIM];
__device__ __nv_bfloat16 g_projT_l[(size_t)N_LAYER * E_DIM * E_DIM];
__device__ __nv_bfloat16 g_w1T_h[(size_t)N_LAYER * FF * E_DIM];
__device__ __nv_bfloat16 g_w1T_l[(size_t)N_LAYER * FF * E_DIM];
__device__ __nv_bfloat16 g_w2T_h[(size_t)N_LAYER * E_DIM * FF];
__device__ __nv_bfloat16 g_w2T_l[(size_t)N_LAYER * E_DIM * FF];
__device__ __nv_bfloat16 g_lmT_h[(size_t)VOCAB * E_DIM];
__device__ __nv_bfloat16 g_lmT_l[(size_t)VOCAB * E_DIM];

/* ================= small PTX wrappers ==================================== */
__device__ __forceinline__ uint32_t smem_u32(const void* p) {
    uint32_t a;
    asm("{ .reg .u64 t; cvta.to.shared.u64 t, %1; cvt.u32.u64 %0, t; }" : "=r"(a) : "l"(p));
    return a;
}
__device__ __forceinline__ void cp16(uint32_t s, const void* g) {
    asm volatile("cp.async.cg.shared.global [%0], [%1], 16;" :: "r"(s), "l"(g));
}
__device__ __forceinline__ void cp_commit() { asm volatile("cp.async.commit_group;"); }
template<int N> __device__ __forceinline__ void cp_wait() {
    asm volatile("cp.async.wait_group %0;" :: "n"(N));
}
__device__ __forceinline__ void ldmA(uint32_t* r, uint32_t a) {
    asm volatile("ldmatrix.sync.aligned.m8n8.x4.shared.b16 {%0,%1,%2,%3}, [%4];"
                 : "=r"(r[0]), "=r"(r[1]), "=r"(r[2]), "=r"(r[3]) : "r"(a));
}
__device__ __forceinline__ void ldmB(uint32_t* r, uint32_t a) {
    asm volatile("ldmatrix.sync.aligned.m8n8.x2.shared.b16 {%0,%1}, [%2];"
                 : "=r"(r[0]), "=r"(r[1]) : "r"(a));
}
__device__ __forceinline__ void ldmB4(uint32_t& r0, uint32_t& r1, uint32_t& r2, uint32_t& r3,
                                      uint32_t a) {
    asm volatile("ldmatrix.sync.aligned.m8n8.x4.shared.b16 {%0,%1,%2,%3}, [%4];"
                 : "=r"(r0), "=r"(r1), "=r"(r2), "=r"(r3) : "r"(a));
}
__device__ __forceinline__ void ldmT(uint32_t* r, uint32_t a) {
    asm volatile("ldmatrix.sync.aligned.m8n8.x2.trans.shared.b16 {%0,%1}, [%2];"
                 : "=r"(r[0]), "=r"(r[1]) : "r"(a));
}
__device__ __forceinline__ void mma16816(float* c, const uint32_t* a, const uint32_t* b) {
    asm volatile("mma.sync.aligned.m16n8k16.row.col.f32.bf16.bf16.f32 "
                 "{%0,%1,%2,%3}, {%4,%5,%6,%7}, {%8,%9}, {%0,%1,%2,%3};"
                 : "+f"(c[0]), "+f"(c[1]), "+f"(c[2]), "+f"(c[3])
                 : "r"(a[0]), "r"(a[1]), "r"(a[2]), "r"(a[3]), "r"(b[0]), "r"(b[1]));
}
__device__ __forceinline__ uint32_t packbf(float a, float b) {
    __nv_bfloat162 t = __floats2bfloat162_rn(a, b);
    return *(uint32_t*)&t;
}

/* ================= HMMA GEMM 128x128 (all layer GEMMs) =================== */
#define ROWB   80
#define TILEB  (128 * ROWB)
#define STAGEB (4 * TILEB)
#define SMTOT  (2 * STAGEB)

template<bool RELU, bool SPLIT, bool ROPE>
__global__ __launch_bounds__(256, 2)
void mma_gemm(const __nv_bfloat16* __restrict__ Ah, const __nv_bfloat16* __restrict__ Al,
              const __nv_bfloat16* __restrict__ Bh, const __nv_bfloat16* __restrict__ Bl,
              int K, int N,
              float* __restrict__ C,
              __nv_bfloat16* __restrict__ Oh, __nv_bfloat16* __restrict__ Ol,
              const float* __restrict__ bias, const float* __restrict__ res,
              const float2* __restrict__ cs) {
    extern __shared__ char smem[];
    const uint32_t sb = smem_u32(smem);
    const int tid = threadIdx.x;
    const int lane = tid & 31;
    const int wid = tid >> 5;
    const int warp_m = wid & 1;
    const int warp_n = wid >> 1;
    const size_t bm = (size_t)blockIdx.y * 128;
    const size_t bn = (size_t)blockIdx.x * 128;

    float acc[4][4][4];
    #pragma unroll
    for (int i = 0; i < 4; i++)
        #pragma unroll
        for (int j = 0; j < 4; j++)
            #pragma unroll
            for (int q = 0; q < 4; q++) acc[i][j][q] = 0.f;

    const int nc = K >> 5;

    auto load_stage = [&](int c) {
        const int k0 = c << 5;
        const uint32_t sbase = sb + (c & 1) * STAGEB;
        #pragma unroll
        for (int t = 0; t < 8; t++) {
            int idx = tid + (t << 8);
            int tile = idx >> 9;
            int r    = (idx >> 2) & 127;
            int cch  = idx & 3;
            const __nv_bfloat16* base = (tile == 0) ? Ah : (tile == 1) ? Al
                                      : (tile == 2) ? Bh : Bl;
            size_t grow = ((tile < 2) ? bm : bn) + r;
            const __nv_bfloat16* g = base + grow * (size_t)K + k0 + cch * 8;
            cp16(sbase + tile * TILEB + r * ROWB + cch * 16, g);
        }
        cp_commit();
    };

    load_stage(0);

    const uint32_t aRowOff = (uint32_t)((warp_m * 64 + (lane & 15)) * ROWB + ((lane >> 4) << 4));
    const uint32_t bRow4Off = (uint32_t)((warp_n * 32 + ((lane & 16) >> 1) + (lane & 7)) * ROWB
                                         + ((lane & 8) << 1));

    for (int c = 0; c < nc; c++) {
        cp_wait<0>();
        __syncthreads();
        if (c + 1 < nc) load_stage(c + 1);

        const uint32_t st = sb + (c & 1) * STAGEB;
        const uint32_t aH = st + aRowOff;
        const uint32_t aL = st + TILEB + aRowOff;
        const uint32_t bH = st + 2 * TILEB + bRow4Off;
        const uint32_t bL = st + 3 * TILEB + bRow4Off;

        #pragma unroll
        for (int kk = 0; kk < 2; kk++) {
            const uint32_t kb = kk * 32;
            uint32_t a[4][4], bh[4][2], bl[4][2];
            #pragma unroll
            for (int p = 0; p < 2; p++) {
                ldmB4(bh[2*p][0], bh[2*p][1], bh[2*p+1][0], bh[2*p+1][1],
                      bH + p * (16 * ROWB) + kb);
                ldmB4(bl[2*p][0], bl[2*p][1], bl[2*p+1][0], bl[2*p+1][1],
                      bL + p * (16 * ROWB) + kb);
            }
            #pragma unroll
            for (int mt = 0; mt < 4; mt++)
                ldmA(a[mt], aH + mt * (16 * ROWB) + kb);
            #pragma unroll
            for (int mt = 0; mt < 4; mt++)
                #pragma unroll
                for (int nt = 0; nt < 4; nt++)
                    mma16816(acc[mt][nt], a[mt], bh[nt]);
            #pragma unroll
            for (int mt = 0; mt < 4; mt++)
                #pragma unroll
                for (int nt = 0; nt < 4; nt++)
                    mma16816(acc[mt][nt], a[mt], bl[nt]);
            #pragma unroll
            for (int mt = 0; mt < 4; mt++)
                ldmA(a[mt], aL + mt * (16 * ROWB) + kb);
            #pragma unroll
            for (int mt = 0; mt < 4; mt++)
                #pragma unroll
                for (int nt = 0; nt < 4; nt++)
                    mma16816(acc[mt][nt], a[mt], bh[nt]);
        }
    }

    #pragma unroll
    for (int mt = 0; mt < 4; mt++) {
        #pragma unroll
        for (int nt = 0; nt < 4; nt++) {
            size_t col = bn + warp_n * 32 + nt * 8 + (lane & 3) * 2;
            #pragma unroll
            for (int half = 0; half < 2; half++) {
                size_t row = bm + warp_m * 64 + mt * 16 + (lane >> 2) + half * 8;
                float v0 = acc[mt][nt][half * 2 + 0];
                float v1 = acc[mt][nt][half * 2 + 1];
                if (bias) { v0 += bias[col]; v1 += bias[col + 1]; }
                if (res) {
                    const float2 r2 = *(const float2*)(res + row * (size_t)N + col);
                    v0 += r2.x; v1 += r2.y;
                }
                if (RELU) { v0 = fmaxf(v0, 0.f); v1 = fmaxf(v1, 0.f); }
                if (ROPE && col < 2048) {
                    int t = (int)(row & (T_LEN - 1));
                    int p = ((int)col & 63) >> 1;
                    float2 c2 = cs[t * 32 + p];
                    float r0 = v0 * c2.x - v1 * c2.y;
                    float r1 = v0 * c2.y + v1 * c2.x;
                    v0 = r0; v1 = r1;
                }
                size_t o = row * (size_t)N + col;
                if (SPLIT) {
                    __nv_bfloat16 h0 = __float2bfloat16(v0);
                    __nv_bfloat16 h1 = __float2bfloat16(v1);
                    Oh[o] = h0;     Ol[o] = __float2bfloat16(v0 - __bfloat162float(h0));
                    Oh[o + 1] = h1; Ol[o + 1] = __float2bfloat16(v1 - __bfloat162float(h1));
                } else {
                    *(float2*)(C + o) = make_float2(v0, v1);
                }
            }
        }
    }
}

/* ============ HMMA GEMM 128x256, 512 threads (LM head only) ============== */
#define WA     (128 * ROWB)
#define WB     (256 * ROWB)
#define WSA_H  0
#define WSA_L  WA
#define WSB_H  (2 * WA)
#define WSB_L  (2 * WA + WB)
#define WSTAGE (2 * WA + 2 * WB)     /* 61440 */
#define WSMTOT (2 * WSTAGE)          /* 122880 */

template<bool RELU, bool SPLIT, bool ROPE>
__global__ __launch_bounds__(512, 1)
void mma_gemm_w(const __nv_bfloat16* __restrict__ Ah, const __nv_bfloat16* __restrict__ Al,
                const __nv_bfloat16* __restrict__ Bh, const __nv_bfloat16* __restrict__ Bl,
                int K, int N,
                float* __restrict__ C,
                __nv_bfloat16* __restrict__ Oh, __nv_bfloat16* __restrict__ Ol,
                const float* __restrict__ bias, const float* __restrict__ res,
                const float2* __restrict__ cs) {
    extern __shared__ char smem[];
    const uint32_t sb = smem_u32(smem);
    const int tid = threadIdx.x;
    const int lane = tid & 31;
    const int wid = tid >> 5;
    const int warp_m = wid & 1;
    const int warp_n = wid >> 1;
    const size_t bm = (size_t)blockIdx.y * 128;
    const size_t bn = (size_t)blockIdx.x * 256;

    float acc[4][4][4];
    #pragma unroll
    for (int i = 0; i < 4; i++)
        #pragma unroll
        for (int j = 0; j < 4; j++)
            #pragma unroll
            for (int q = 0; q < 4; q++) acc[i][j][q] = 0.f;

    const int nc = K >> 5;

    auto load_stage = [&](int c) {
        const int k0 = c << 5;
        const uint32_t sbase = sb + (c & 1) * WSTAGE;
        #pragma unroll
        for (int t = 0; t < 6; t++) {
            int idx = tid + (t << 9);
            const __nv_bfloat16* base;
            uint32_t soff;
            size_t gr;
            int e;
            if (idx < 512)       { e = idx;        base = Ah; soff = WSA_H; gr = bm; }
            else if (idx < 1024) { e = idx - 512;  base = Al; soff = WSA_L; gr = bm; }
            else if (idx < 2048) { e = idx - 1024; base = Bh; soff = WSB_H; gr = bn; }
            else                 { e = idx - 2048; base = Bl; soff = WSB_L; gr = bn; }
            int r = e >> 2, cch = e & 3;
            cp16(sbase + soff + r * ROWB + cch * 16,
                 base + (gr + r) * (size_t)K + k0 + cch * 8);
        }
        cp_commit();
    };

    load_stage(0);

    const uint32_t aRowOff = (uint32_t)((warp_m * 64 + (lane & 15)) * ROWB + ((lane >> 4) << 4));
    const uint32_t bRow4Off = (uint32_t)((warp_n * 32 + ((lane & 16) >> 1) + (lane & 7)) * ROWB
                                         + ((lane & 8) << 1));

    for (int c = 0; c < nc; c++) {
        cp_wait<0>();
        __syncthreads();
        if (c + 1 < nc) load_stage(c + 1);

        const uint32_t st = sb + (c & 1) * WSTAGE;
        const uint32_t aH = st + WSA_H + aRowOff;
        const uint32_t aL = st + WSA_L + aRowOff;
        const uint32_t bH = st + WSB_H + bRow4Off;
        const uint32_t bL = st + WSB_L + bRow4Off;

        #pragma unroll
        for (int kk = 0; kk < 2; kk++) {
            const uint32_t kb = kk * 32;
            uint32_t a[4][4], bh[4][2], bl[4][2];
            #pragma unroll
            for (int p = 0; p < 2; p++) {
                ldmB4(bh[2*p][0], bh[2*p][1], bh[2*p+1][0], bh[2*p+1][1],
                      bH + p * (16 * ROWB) + kb);
                ldmB4(bl[2*p][0], bl[2*p][1], bl[2*p+1][0], bl[2*p+1][1],
                      bL + p * (16 * ROWB) + kb);
            }
            #pragma unroll
            for (int mt = 0; mt < 4; mt++)
                ldmA(a[mt], aH + mt * (16 * ROWB) + kb);
            #pragma unroll
            for (int mt = 0; mt < 4; mt++)
                #pragma unroll
                for (int nt = 0; nt < 4; nt++)
                    mma16816(acc[mt][nt], a[mt], bh[nt]);
            #pragma unroll
            for (int mt = 0; mt < 4; mt++)
                #pragma unroll
                for (int nt = 0; nt < 4; nt++)
                    mma16816(acc[mt][nt], a[mt], bl[nt]);
            #pragma unroll
            for (int mt = 0; mt < 4; mt++)
                ldmA(a[mt], aL + mt * (16 * ROWB) + kb);
            #pragma unroll
            for (int mt = 0; mt < 4; mt++)
                #pragma unroll
                for (int nt = 0; nt < 4; nt++)
                    mma16816(acc[mt][nt], a[mt], bh[nt]);
        }
    }

    #pragma unroll
    for (int mt = 0; mt < 4; mt++) {
        #pragma unroll
        for (int nt = 0; nt < 4; nt++) {
            size_t col = bn + warp_n * 32 + nt * 8 + (lane & 3) * 2;
            #pragma unroll
            for (int half = 0; half < 2; half++) {
                size_t row = bm + warp_m * 64 + mt * 16 + (lane >> 2) + half * 8;
                float v0 = acc[mt][nt][half * 2 + 0];
                float v1 = acc[mt][nt][half * 2 + 1];
                if (bias) { v0 += bias[col]; v1 += bias[col + 1]; }
                if (res) {
                    const float2 r2 = *(const float2*)(res + row * (size_t)N + col);
                    v0 += r2.x; v1 += r2.y;
                }
                if (RELU) { v0 = fmaxf(v0, 0.f); v1 = fmaxf(v1, 0.f); }
                if (ROPE && col < 2048) {
                    int t = (int)(row & (T_LEN - 1));
                    int p = ((int)col & 63) >> 1;
                    float2 c2 = cs[t * 32 + p];
                    float r0 = v0 * c2.x - v1 * c2.y;
                    float r1 = v0 * c2.y + v1 * c2.x;
                    v0 = r0; v1 = r1;
                }
                size_t o = row * (size_t)N + col;
                if (SPLIT) {
                    __nv_bfloat16 h0 = __float2bfloat16(v0);
                    __nv_bfloat16 h1 = __float2bfloat16(v1);
                    Oh[o] = h0;     Ol[o] = __float2bfloat16(v0 - __bfloat162float(h0));
                    Oh[o + 1] = h1; Ol[o + 1] = __float2bfloat16(v1 - __bfloat162float(h1));
                } else {
                    *(float2*)(C + o) = make_float2(v0, v1);
                }
            }
        }
    }
}

/* ================= weight transpose+split ================================ */
__global__ void wt_gen(const float* __restrict__ in, long in_zs,
                       __nv_bfloat16* __restrict__ oh, __nv_bfloat16* __restrict__ ol,
                       long out_zs, int Kd, int Nd) {
    __shared__ float t[32][33];
    int z = blockIdx.z;
    in += (size_t)z * in_zs; oh += (size_t)z * out_zs; ol += (size_t)z * out_zs;
    int n0 = blockIdx.x * 32, k0 = blockIdx.y * 32;
    int tx = threadIdx.x, ty = threadIdx.y;
    #pragma unroll
    for (int j = ty; j < 32; j += 8)
        t[j][tx] = in[(size_t)(k0 + j) * Nd + n0 + tx];
    __syncthreads();
    #pragma unroll
    for (int j = ty; j < 32; j += 8) {
        float v = t[tx][j];
        size_t o = (size_t)(n0 + j) * Kd + k0 + tx;
        __nv_bfloat16 h = __float2bfloat16(v);
        oh[o] = h;
        ol[o] = __float2bfloat16(v - __bfloat162float(h));
    }
}
__global__ void wt_qkv_all(const float* __restrict__ wq, const float* __restrict__ wk,
                           const float* __restrict__ wv,
                           __nv_bfloat16* __restrict__ oh, __nv_bfloat16* __restrict__ ol) {
    __shared__ float t[32][33];
    int z = blockIdx.z;
    int sel = z / 96;
    int zz  = z - sel * 96;
    int l = zz >> 4, h = zz & 15;
    const float* w = (sel == 0) ? wq : (sel == 1) ? wk : wv;
    const float scale = (sel == 0) ? 0.03125f : 1.0f;
    const float* in = w + (size_t)zz * E_DIM * HD;
    size_t orow0 = (size_t)l * 3 * E_DIM + (size_t)sel * E_DIM + h * HD;
    __nv_bfloat16* ohp = oh + orow0 * E_DIM;
    __nv_bfloat16* olp = ol + orow0 * E_DIM;
    int d0 = blockIdx.x * 32, e0 = blockIdx.y * 32;
    int tx = threadIdx.x, ty = threadIdx.y;
    #pragma unroll
    for (int j = ty; j < 32; j += 8)
        t[j][tx] = in[(size_t)(e0 + j) * HD + d0 + tx];
    __syncthreads();
    #pragma unroll
    for (int j = ty; j < 32; j += 8) {
        float v = t[tx][j] * scale;
        size_t o = (size_t)(d0 + j) * E_DIM + e0 + tx;
        __nv_bfloat16 hh = __float2bfloat16(v);
        ohp[o] = hh;
        olp[o] = __float2bfloat16(v - __bfloat162float(hh));
    }
}

/* ================= fused embed + LN1(layer0) + cs table ================== */
__global__ __launch_bounds__(256)
void embed_ln_kernel(const int* __restrict__ idx, const float* __restrict__ emb,
                     const float* __restrict__ g, const float* __restrict__ b,
                     float* __restrict__ x,
                     __nv_bfloat16* __restrict__ yh, __nv_bfloat16* __restrict__ yl) {
    int m = blockIdx.x, tid = threadIdx.x;
    __shared__ float r1[256], r2[256];
    const float4* src = (const float4*)(emb + (size_t)idx[m] * E_DIM);
    float4 v = src[tid];
    ((float4*)(x + (size_t)m * E_DIM))[tid] = v;
    r1[tid] = v.x + v.y + v.z + v.w;
    r2[tid] = v.x * v.x + v.y * v.y + v.z * v.z + v.w * v.w;
    if (m < 128) {
        int i = m * 256 + tid;
        if (i < T_LEN * 32) {
            int t = i >> 5, p = i & 31;
            float invf = powf(10000.f, -(float)(2 * p) / (float)HD);
            float sn, c;
            sincosf((float)t * invf, &sn, &c);
            g_cs[i] = make_float2(c, sn);
        }
    }
    __syncthreads();
    for (int s = 128; s > 0; s >>= 1) {
        if (tid < s) { r1[tid] += r1[tid + s]; r2[tid] += r2[tid + s]; }
        __syncthreads();
    }
    float mean = r1[0] * (1.0f / E_DIM);
    float var  = r2[0] * (1.0f / E_DIM) - mean * mean;
    float rstd = rsqrtf(var + 1e-5f);
    float4 gg = ((const float4*)g)[tid];
    float4 bb = ((const float4*)b)[tid];
    float o[4] = { (v.x - mean) * rstd * gg.x + bb.x, (v.y - mean) * rstd * gg.y + bb.y,
                   (v.z - mean) * rstd * gg.z + bb.z, (v.w - mean) * rstd * gg.w + bb.w };
    size_t base = (size_t)m * E_DIM + tid * 4;
    #pragma unroll
    for (int j = 0; j < 4; j++) {
        __nv_bfloat16 h = __float2bfloat16(o[j]);
        yh[base + j] = h;
        yl[base + j] = __float2bfloat16(o[j] - __bfloat162float(h));
    }
}

__global__ __launch_bounds__(256)
void ln_split_kernel(const float* __restrict__ x, const float* __restrict__ g,
                     const float* __restrict__ b,
                     __nv_bfloat16* __restrict__ yh, __nv_bfloat16* __restrict__ yl) {
    int m = blockIdx.x, tid = threadIdx.x;
    __shared__ float r1[256], r2[256];
    const float4* xr = (const float4*)(x + (size_t)m * E_DIM);
    float4 v = xr[tid];
    r1[tid] = v.x + v.y + v.z + v.w;
    r2[tid] = v.x * v.x + v.y * v.y + v.z * v.z + v.w * v.w;
    __syncthreads();
    for (int s = 128; s > 0; s >>= 1) {
        if (tid < s) { r1[tid] += r1[tid + s]; r2[tid] += r2[tid + s]; }
        __syncthreads();
    }
    float mean = r1[0] * (1.0f / E_DIM);
    float var  = r2[0] * (1.0f / E_DIM) - mean * mean;
    float rstd = rsqrtf(var + 1e-5f);
    float4 gg = ((const float4*)g)[tid];
    float4 bb = ((const float4*)b)[tid];
    float o[4] = { (v.x - mean) * rstd * gg.x + bb.x, (v.y - mean) * rstd * gg.y + bb.y,
                   (v.z - mean) * rstd * gg.z + bb.z, (v.w - mean) * rstd * gg.w + bb.w };
    size_t base = (size_t)m * E_DIM + tid * 4;
    #pragma unroll
    for (int j = 0; j < 4; j++) {
        __nv_bfloat16 h = __float2bfloat16(o[j]);
        yh[base + j] = h;
        yl[base + j] = __float2bfloat16(o[j] - __bfloat162float(h));
    }
}

__global__ void split_kernel(const float* __restrict__ x,
                             __nv_bfloat16* __restrict__ oh, __nv_bfloat16* __restrict__ ol, int n) {
    int i = blockIdx.x * blockDim.x + threadIdx.x;
    if (i < n) {
        float v = x[i];
        __nv_bfloat16 h = __float2bfloat16(v);
        oh[i] = h;
        ol[i] = __float2bfloat16(v - __bfloat162float(h));
    }
}

/* ======== flash attention (HMMA, split-bf16): 64q tiles, 64k chunks ====== */
#define ARS  144
#define ATILE (64 * ARS)
#define ASM  (4 * ATILE)

__global__ __launch_bounds__(128)
void attn_kernel(const __nv_bfloat16* __restrict__ qg_h, const __nv_bfloat16* __restrict__ qg_l,
                 __nv_bfloat16* __restrict__ oh, __nv_bfloat16* __restrict__ ol) {
    extern __shared__ char sm[];
    const uint32_t sb = smem_u32(sm);
    const int tid = threadIdx.x, lane = tid & 31, w = tid >> 5;
    const int qt = blockIdx.x;
    const int b  = blockIdx.y >> 4;
    const int h  = blockIdx.y & 15;
    const int t0 = qt * 64;
    const size_t mbase = (size_t)b * T_LEN;

    for (int i = tid; i < 512; i += 128) {
        int r = i >> 3, c = i & 7;
        size_t src = (mbase + t0 + r) * 3072 + h * 64 + c * 8;
        cp16(sb + r * ARS + c * 16, qg_h + src);
        cp16(sb + ATILE + r * ARS + c * 16, qg_l + src);
    }
    cp_commit(); cp_wait<0>(); __syncthreads();

    uint32_t Qh[4][4], Ql[4][4];
    {
        uint32_t qo = sb + (w * 16 + (lane & 15)) * ARS + ((lane >> 4) << 4);
        #pragma unroll
        for (int ks = 0; ks < 4; ks++) {
            ldmA(Qh[ks], qo + ks * 32);
            ldmA(Ql[ks], qo + ATILE + ks * 32);
        }
    }
    __syncthreads();

    float O[8][4];
    #pragma unroll
    for (int i = 0; i < 8; i++)
        #pragma unroll
        for (int j = 0; j < 4; j++) O[i][j] = 0.f;
    float m0 = -1e30f, m1 = -1e30f, l0 = 0.f, l1 = 0.f;
    const int g = lane >> 2, t4 = lane & 3;
    const int row0 = t0 + w * 16 + g;
    const int row1 = row0 + 8;

    const int nch = qt + 1;
    for (int ch = 0; ch < nch; ch++) {
        const int c0 = ch * 64;
        for (int i = tid; i < 512; i += 128) {
            int r = i >> 3, c = i & 7;
            size_t srck = (mbase + c0 + r) * 3072 + 1024 + h * 64 + c * 8;
            cp16(sb + 0 * ATILE + r * ARS + c * 16, qg_h + srck);
            cp16(sb + 1 * ATILE + r * ARS + c * 16, qg_l + srck);
            cp16(sb + 2 * ATILE + r * ARS + c * 16, qg_h + srck + 1024);
            cp16(sb + 3 * ATILE + r * ARS + c * 16, qg_l + srck + 1024);
        }
        cp_commit(); cp_wait<0>(); __syncthreads();

        float S[8][4];
        const uint32_t kbo = sb + (lane & 7) * ARS + (((lane >> 3) & 1) << 4);
        #pragma unroll
        for (int nt = 0; nt < 8; nt++) {
            #pragma unroll
            for (int j = 0; j < 4; j++) S[nt][j] = 0.f;
            uint32_t kh[4][2], kl[4][2];
            #pragma unroll
            for (int ks = 0; ks < 4; ks++) {
                ldmB(kh[ks], kbo + nt * (8 * ARS) + ks * 32);
                ldmB(kl[ks], kbo + ATILE + nt * (8 * ARS) + ks * 32);
            }
            #pragma unroll
            for (int ks = 0; ks < 4; ks++) {
                mma16816(S[nt], Qh[ks], kh[ks]);
                mma16816(S[nt], Qh[ks], kl[ks]);
                mma16816(S[nt], Ql[ks], kh[ks]);
            }
        }

        if (ch == nch - 1) {
            #pragma unroll
            for (int nt = 0; nt < 8; nt++) {
                int kc = c0 + nt * 8 + 2 * t4;
                if (kc > row0)     S[nt][0] = -1e30f;
                if (kc + 1 > row0) S[nt][1] = -1e30f;
                if (kc > row1)     S[nt][2] = -1e30f;
                if (kc + 1 > row1) S[nt][3] = -1e30f;
            }
        }

        float mc0 = -1e30f, mc1 = -1e30f;
        #pragma unroll
        for (int nt = 0; nt < 8; nt++) {
            mc0 = fmaxf(mc0, fmaxf(S[nt][0], S[nt][1]));
            mc1 = fmaxf(mc1, fmaxf(S[nt][2], S[nt][3]));
        }
        mc0 = fmaxf(mc0, __shfl_xor_sync(~0u, mc0, 1));
        mc0 = fmaxf(mc0, __shfl_xor_sync(~0u, mc0, 2));
        mc1 = fmaxf(mc1, __shfl_xor_sync(~0u, mc1, 1));
        mc1 = fmaxf(mc1, __shfl_xor_sync(~0u, mc1, 2));
        float mn0 = fmaxf(m0, mc0), mn1 = fmaxf(m1, mc1);
        float a0 = __expf(m0 - mn0), a1 = __expf(m1 - mn1);
        m0 = mn0; m1 = mn1;
        float s0 = 0.f, s1 = 0.f;
        #pragma unroll
        for (int nt = 0; nt < 8; nt++) {
            S[nt][0] = __expf(S[nt][0] - mn0); s0 += S[nt][0];
            S[nt][1] = __expf(S[nt][1] - mn0); s0 += S[nt][1];
            S[nt][2] = __expf(S[nt][2] - mn1); s1 += S[nt][2];
            S[nt][3] = __expf(S[nt][3] - mn1); s1 += S[nt][3];
        }
        s0 += __shfl_xor_sync(~0u, s0, 1); s0 += __shfl_xor_sync(~0u, s0, 2);
        s1 += __shfl_xor_sync(~0u, s1, 1); s1 += __shfl_xor_sync(~0u, s1, 2);
        l0 = l0 * a0 + s0;
        l1 = l1 * a1 + s1;
        #pragma unroll
        for (int nt = 0; nt < 8; nt++) {
            O[nt][0] *= a0; O[nt][1] *= a0; O[nt][2] *= a1; O[nt][3] *= a1;
        }

        #pragma unroll
        for (int ks = 0; ks < 4; ks++) {
            uint32_t Ph[4], Pl[4];
            #pragma unroll
            for (int half = 0; half < 2; half++) {
                float p0 = S[2 * ks + half][0], p1 = S[2 * ks + half][1];
                float p2 = S[2 * ks + half][2], p3 = S[2 * ks + half][3];
                __nv_bfloat16 h0 = __float2bfloat16(p0), h1 = __float2bfloat16(p1);
                __nv_bfloat16 h2 = __float2bfloat16(p2), h3 = __float2bfloat16(p3);
                Ph[half * 2 + 0] = packbf(__bfloat162float(h0), __bfloat162float(h1));
                Ph[half * 2 + 1] = packbf(__bfloat162float(h2), __bfloat162float(h3));
                Pl[half * 2 + 0] = packbf(p0 - __bfloat162float(h0), p1 - __bfloat162float(h1));
                Pl[half * 2 + 1] = packbf(p2 - __bfloat162float(h2), p3 - __bfloat162float(h3));
            }
            uint32_t A_h[4] = { Ph[0], Ph[1], Ph[2], Ph[3] };
            uint32_t A_l[4] = { Pl[0], Pl[1], Pl[2], Pl[3] };
            const uint32_t vbase = sb + 2 * ATILE + (ks * 16 + (lane & 15)) * ARS;
            #pragma unroll
            for (int nt = 0; nt < 8; nt++) {
                uint32_t vh[2], vl[2];
                ldmT(vh, vbase + nt * 16);
                ldmT(vl, vbase + ATILE + nt * 16);
                mma16816(O[nt], A_h, vh);
                mma16816(O[nt], A_h, vl);
                mma16816(O[nt], A_l, vh);
            }
        }
        __syncthreads();
    }

    const float il0 = 1.f / l0, il1 = 1.f / l1;
    #pragma unroll
    for (int nt = 0; nt < 8; nt++) {
        size_t p0 = (mbase + row0) * E_DIM + h * 64 + nt * 8 + 2 * t4;
        size_t p1 = (mbase + row1) * E_DIM + h * 64 + nt * 8 + 2 * t4;
        float o00 = O[nt][0] * il0, o01 = O[nt][1] * il0;
        float o10 = O[nt][2] * il1, o11 = O[nt][3] * il1;
        __nv_bfloat16 h00 = __float2bfloat16(o00), h01 = __float2bfloat16(o01);
        __nv_bfloat16 h10 = __float2bfloat16(o10), h11 = __float2bfloat16(o11);
        oh[p0] = h00;     ol[p0] = __float2bfloat16(o00 - __bfloat162float(h00));
        oh[p0 + 1] = h01; ol[p0 + 1] = __float2bfloat16(o01 - __bfloat162float(h01));
        oh[p1] = h10;     ol[p1] = __float2bfloat16(o10 - __bfloat162float(h10));
        oh[p1 + 1] = h11; ol[p1 + 1] = __float2bfloat16(o11 - __bfloat162float(h11));
    }
}

/* ================= NLL + loss ============================================ */
__global__ __launch_bounds__(256)
void nll_kernel(const float* __restrict__ logits, const int* __restrict__ tgt,
                float* __restrict__ nll) {
    int m = blockIdx.x, tid = threadIdx.x;
    const float* lr = logits + (size_t)m * VOCAB;
    __shared__ float red[256];
    float mx = -1e30f;
    for (int n = tid; n < VOCAB; n += 256) mx = fmaxf(mx, lr[n]);
    red[tid] = mx;
    __syncthreads();
    for (int s = 128; s > 0; s >>= 1) {
        if (tid < s) red[tid] = fmaxf(red[tid], red[tid + s]);
        __syncthreads();
    }
    mx = red[0];
    __syncthreads();
    float sum = 0.f;
    for (int n = tid; n < VOCAB; n += 256) sum += __expf(lr[n] - mx);
    red[tid] = sum;
    __syncthreads();
    for (int s = 128; s > 0; s >>= 1) {
        if (tid < s) red[tid] += red[tid + s];
        __syncthreads();
    }
    if (tid == 0)
        nll[m] = (logf(red[0]) + mx) - lr[tgt[m]];
}

__global__ __launch_bounds__(256)
void loss_reduce_kernel(const float* __restrict__ nll, float* __restrict__ out) {
    __shared__ float red[256];
    int tid = threadIdx.x;
    float s = 0.f;
    for (int i = tid; i < MTOK; i += 256) s += nll[i];
    red[tid] = s;
    __syncthreads();
    for (int k = 128; k > 0; k >>= 1) {
        if (tid < k) red[tid] += red[tid + k];
        __syncthreads();
    }
    if (tid == 0) out[0] = red[0] * (1.0f / MTOK);
}

/* ================= host orchestration ==================================== */
extern "C" void kernel_launch(void* const* d_in, const int* in_sizes, int n_in,
                              void* d_out, int out_size) {
    const int*   idx   = (const int*)  d_in[0];
    const int*   tgt   = (const int*)  d_in[1];
    const float* emb   = (const float*)d_in[2];
    const float* wq    = (const float*)d_in[3];
    const float* wk    = (const float*)d_in[4];
    const float* wv    = (const float*)d_in[5];
    const float* wproj = (const float*)d_in[6];
    const float* bproj = (const float*)d_in[7];
    const float* w1    = (const float*)d_in[8];
    const float* b1    = (const float*)d_in[9];
    const float* w2    = (const float*)d_in[10];
    const float* b2    = (const float*)d_in[11];
    const float* ln1g  = (const float*)d_in[12];
    const float* ln1b  = (const float*)d_in[13];
    const float* ln2g  = (const float*)d_in[14];
    const float* ln2b  = (const float*)d_in[15];
    const float* lm_w  = (const float*)d_in[16];
    const float* lm_b  = (const float*)d_in[17];

    float *x, *nll, *lscr;
    float2* cs;
    __nv_bfloat16 *yh, *yl, *qh, *ql, *oh, *ol, *hh, *hl;
    __nv_bfloat16 *qkvTh, *qkvTl, *projTh, *projTl, *w1Th, *w1Tl, *w2Th, *w2Tl, *lmTh, *lmTl;
    cudaGetSymbolAddress((void**)&x,     g_x);
    cudaGetSymbolAddress((void**)&yh,    g_yh);
    cudaGetSymbolAddress((void**)&yl,    g_yl);
    cudaGetSymbolAddress((void**)&qh,    g_qh);
    cudaGetSymbolAddress((void**)&ql,    g_ql);
    cudaGetSymbolAddress((void**)&oh,    g_oh);
    cudaGetSymbolAddress((void**)&ol,    g_ol);
    cudaGetSymbolAddress((void**)&hh,    g_hh);
    cudaGetSymbolAddress((void**)&hl,    g_hl);
    cudaGetSymbolAddress((void**)&nll,   g_nllv);
    cudaGetSymbolAddress((void**)&lscr,  g_logits_scratch);
    cudaGetSymbolAddress((void**)&cs,    g_cs);
    cudaGetSymbolAddress((void**)&qkvTh, g_qkvT_h);
    cudaGetSymbolAddress((void**)&qkvTl, g_qkvT_l);
    cudaGetSymbolAddress((void**)&projTh, g_projT_h);
    cudaGetSymbolAddress((void**)&projTl, g_projT_l);
    cudaGetSymbolAddress((void**)&w1Th,  g_w1T_h);
    cudaGetSymbolAddress((void**)&w1Tl,  g_w1T_l);
    cudaGetSymbolAddress((void**)&w2Th,  g_w2T_h);
    cudaGetSymbolAddress((void**)&w2Tl,  g_w2T_l);
    cudaGetSymbolAddress((void**)&lmTh,  g_lmT_h);
    cudaGetSymbolAddress((void**)&lmTl,  g_lmT_l);

    cudaFuncSetAttribute(mma_gemm<false, false, false>, cudaFuncAttributeMaxDynamicSharedMemorySize, SMTOT);
    cudaFuncSetAttribute(mma_gemm<false, true,  true >, cudaFuncAttributeMaxDynamicSharedMemorySize, SMTOT);
    cudaFuncSetAttribute(mma_gemm<true,  true,  false>, cudaFuncAttributeMaxDynamicSharedMemorySize, SMTOT);
    cudaFuncSetAttribute(mma_gemm_w<false, false, false>, cudaFuncAttributeMaxDynamicSharedMemorySize, WSMTOT);

    const long BTV = (long)MTOK * VOCAB;
    float* logits = ((long)out_size >= BTV) ? (float*)d_out : lscr;

    dim3 tb(32, 8);
    embed_ln_kernel<<<MTOK, 256>>>(idx, emb, ln1g, ln1b, x, yh, yl);
    wt_qkv_all<<<dim3(2, 32, 288), tb>>>(wq, wk, wv, qkvTh, qkvTl);
    mma_gemm<false, true, true><<<dim3(3 * E_DIM / 128, MTOK / 128), 256, SMTOT>>>(
        yh, yl, qkvTh, qkvTl, E_DIM, 3 * E_DIM,
        nullptr, qh, ql, nullptr, nullptr, (const float2*)cs);
    attn_kernel<<<dim3(T_LEN / 64, BATCH * N_HEAD), 128, ASM>>>(qh, ql, oh, ol);

    wt_gen<<<dim3(32, 32, N_LAYER), tb>>>(wproj, (long)E_DIM * E_DIM, projTh, projTl,
                                          (long)E_DIM * E_DIM, E_DIM, E_DIM);
    wt_gen<<<dim3(128, 32, N_LAYER), tb>>>(w1, (long)E_DIM * FF, w1Th, w1Tl,
                                           (long)E_DIM * FF, E_DIM, FF);
    wt_gen<<<dim3(32, 128, N_LAYER), tb>>>(w2, (long)FF * E_DIM, w2Th, w2Tl,
                                           (long)FF * E_DIM, FF, E_DIM);
    wt_gen<<<dim3(1000, 32, 1), tb>>>(lm_w, 0, lmTh, lmTl, 0, E_DIM, VOCAB);

    for (int l = 0; l < N_LAYER; l++) {
        size_t qkvW = (size_t)l * 3 * E_DIM * E_DIM;
        size_t prW  = (size_t)l * E_DIM * E_DIM;
        size_t w1W  = (size_t)l * FF * E_DIM;

        if (l > 0) {
            ln_split_kernel<<<MTOK, 256>>>(x, ln1g + (size_t)l * E_DIM, ln1b + (size_t)l * E_DIM, yh, yl);
            mma_gemm<false, true, true><<<dim3(3 * E_DIM / 128, MTOK / 128), 256, SMTOT>>>(
                yh, yl, qkvTh + qkvW, qkvTl + qkvW, E_DIM, 3 * E_DIM,
                nullptr, qh, ql, nullptr, nullptr, (const float2*)cs);
            attn_kernel<<<dim3(T_LEN / 64, BATCH * N_HEAD), 128, ASM>>>(qh, ql, oh, ol);
        }

        mma_gemm<false, false, false><<<dim3(E_DIM / 128, MTOK / 128), 256, SMTOT>>>(
            oh, ol, projTh + prW, projTl + prW, E_DIM, E_DIM,
            x, nullptr, nullptr, bproj + (size_t)l * E_DIM, x, nullptr);

        ln_split_kernel<<<MTOK, 256>>>(x, ln2g + (size_t)l * E_DIM, ln2b + (size_t)l * E_DIM, yh, yl);

        mma_gemm<true, true, false><<<dim3(FF / 128, MTOK / 128), 256, SMTOT>>>(
            yh, yl, w1Th + w1W, w1Tl + w1W, E_DIM, FF,
            nullptr, hh, hl, b1 + (size_t)l * FF, nullptr, nullptr);

        mma_gemm<false, false, false><<<dim3(E_DIM / 128, MTOK / 128), 256, SMTOT>>>(
            hh, hl, w2Th + w1W, w2Tl + w1W, FF, E_DIM,
            x, nullptr, nullptr, b2 + (size_t)l * E_DIM, x, nullptr);
    }

    split_kernel<<<(MTOK * E_DIM + 255) / 256, 256>>>(x, yh, yl, MTOK * E_DIM);

    /* LM head: wide 128x256 kernel — grid 125x16 = 2000 CTAs, deep waves */
    mma_gemm_w<false, false, false><<<dim3(VOCAB / 256, MTOK / 128), 512, WSMTOT>>>(
        yh, yl, lmTh, lmTl, E_DIM, VOCAB,
        logits, nullptr, nullptr, lm_b, nullptr, nullptr);

    nll_kernel<<<MTOK, 256>>>(logits, tgt, nll);

    if ((long)out_size == BTV + 1) {
        loss_reduce_kernel<<<1, 256>>>(nll, (float*)d_out + BTV);
    } else if ((long)out_size < BTV) {
        loss_reduce_kernel<<<1, 256>>>(nll, (float*)d_out);
    }
}

// round 15
// speedup vs baseline: 1.1709x; 1.0727x over previous
#include <cuda_runtime.h>
#include <cuda_bf16.h>
#include <cuda_fp16.h>
#include <math.h>
#include <cstdint>

#define E_DIM   1024
#define N_HEAD  16
#define HD      64
#define T_LEN   1024
#define N_LAYER 6
#define VOCAB   32000
#define BATCH   2
#define MTOK    (BATCH * T_LEN)     /* 2048 */
#define FF      (4 * E_DIM)         /* 4096 */

/* ================= scratch =============================================== */
__device__ float g_x   [MTOK * E_DIM];
__device__ __nv_bfloat16 g_yh[MTOK * E_DIM];
__device__ __nv_bfloat16 g_yl[MTOK * E_DIM];
__device__ __nv_bfloat16 g_qh[(size_t)MTOK * 3 * E_DIM];
__device__ __nv_bfloat16 g_ql[(size_t)MTOK * 3 * E_DIM];
__device__ __nv_bfloat16 g_oh[MTOK * E_DIM];
__device__ __nv_bfloat16 g_ol[MTOK * E_DIM];
__device__ __nv_bfloat16 g_hh[(size_t)MTOK * FF];
__device__ __nv_bfloat16 g_hl[(size_t)MTOK * FF];
__device__ float g_nllv[MTOK];
__device__ float g_logits_scratch[(size_t)MTOK * VOCAB];
__device__ float2 g_cs[T_LEN * 32];
__device__ __nv_bfloat16 g_qkvT_h[(size_t)N_LAYER * 3 * E_DIM * E_DIM];
__device__ __nv_bfloat16 g_qkvT_l[(size_t)N_LAYER * 3 * E_DIM * E_DIM];
__device__ __nv_bfloat16 g_projT_h[(size_t)N_LAYER * E_DIM * E_DIM];
__device__ __nv_bfloat16 g_projT_l[(size_t)N_LAYER * E_DIM * E_DIM];
__device__ __nv_bfloat16 g_w1T_h[(size_t)N_LAYER * FF * E_DIM];
__device__ __nv_bfloat16 g_w1T_l[(size_t)N_LAYER * FF * E_DIM];
__device__ __nv_bfloat16 g_w2T_h[(size_t)N_LAYER * E_DIM * FF];
__device__ __nv_bfloat16 g_w2T_l[(size_t)N_LAYER * E_DIM * FF];
__device__ __half g_lmT_h[(size_t)VOCAB * E_DIM];   /* fp16 hi */
__device__ __half g_lmT_l[(size_t)VOCAB * E_DIM];   /* fp16 lo */
__device__ __half g_yf  [MTOK * E_DIM];             /* fp16 LM input */

/* ================= small PTX wrappers ==================================== */
__device__ __forceinline__ uint32_t smem_u32(const void* p) {
    uint32_t a;
    asm("{ .reg .u64 t; cvta.to.shared.u64 t, %1; cvt.u32.u64 %0, t; }" : "=r"(a) : "l"(p));
    return a;
}
__device__ __forceinline__ void cp16(uint32_t s, const void* g) {
    asm volatile("cp.async.cg.shared.global [%0], [%1], 16;" :: "r"(s), "l"(g));
}
__device__ __forceinline__ void cp_commit() { asm volatile("cp.async.commit_group;"); }
template<int N> __device__ __forceinline__ void cp_wait() {
    asm volatile("cp.async.wait_group %0;" :: "n"(N));
}
__device__ __forceinline__ void ldmA(uint32_t* r, uint32_t a) {
    asm volatile("ldmatrix.sync.aligned.m8n8.x4.shared.b16 {%0,%1,%2,%3}, [%4];"
                 : "=r"(r[0]), "=r"(r[1]), "=r"(r[2]), "=r"(r[3]) : "r"(a));
}
__device__ __forceinline__ void ldmB(uint32_t* r, uint32_t a) {
    asm volatile("ldmatrix.sync.aligned.m8n8.x2.shared.b16 {%0,%1}, [%2];"
                 : "=r"(r[0]), "=r"(r[1]) : "r"(a));
}
__device__ __forceinline__ void ldmB4(uint32_t& r0, uint32_t& r1, uint32_t& r2, uint32_t& r3,
                                      uint32_t a) {
    asm volatile("ldmatrix.sync.aligned.m8n8.x4.shared.b16 {%0,%1,%2,%3}, [%4];"
                 : "=r"(r0), "=r"(r1), "=r"(r2), "=r"(r3) : "r"(a));
}
__device__ __forceinline__ void ldmT(uint32_t* r, uint32_t a) {
    asm volatile("ldmatrix.sync.aligned.m8n8.x2.trans.shared.b16 {%0,%1}, [%2];"
                 : "=r"(r[0]), "=r"(r[1]) : "r"(a));
}
__device__ __forceinline__ void mma16816(float* c, const uint32_t* a, const uint32_t* b) {
    asm volatile("mma.sync.aligned.m16n8k16.row.col.f32.bf16.bf16.f32 "
                 "{%0,%1,%2,%3}, {%4,%5,%6,%7}, {%8,%9}, {%0,%1,%2,%3};"
                 : "+f"(c[0]), "+f"(c[1]), "+f"(c[2]), "+f"(c[3])
                 : "r"(a[0]), "r"(a[1]), "r"(a[2]), "r"(a[3]), "r"(b[0]), "r"(b[1]));
}
__device__ __forceinline__ void mma16816h(float* c, const uint32_t* a, const uint32_t* b) {
    asm volatile("mma.sync.aligned.m16n8k16.row.col.f32.f16.f16.f32 "
                 "{%0,%1,%2,%3}, {%4,%5,%6,%7}, {%8,%9}, {%0,%1,%2,%3};"
                 : "+f"(c[0]), "+f"(c[1]), "+f"(c[2]), "+f"(c[3])
                 : "r"(a[0]), "r"(a[1]), "r"(a[2]), "r"(a[3]), "r"(b[0]), "r"(b[1]));
}
__device__ __forceinline__ uint32_t packbf(float a, float b) {
    __nv_bfloat162 t = __floats2bfloat162_rn(a, b);
    return *(uint32_t*)&t;
}

/* ================= HMMA GEMM 128x128 (all layer GEMMs) =================== */
#define ROWB   80
#define TILEB  (128 * ROWB)
#define STAGEB (4 * TILEB)
#define SMTOT  (2 * STAGEB)

template<bool RELU, bool SPLIT, bool ROPE>
__global__ __launch_bounds__(256, 2)
void mma_gemm(const __nv_bfloat16* __restrict__ Ah, const __nv_bfloat16* __restrict__ Al,
              const __nv_bfloat16* __restrict__ Bh, const __nv_bfloat16* __restrict__ Bl,
              int K, int N,
              float* __restrict__ C,
              __nv_bfloat16* __restrict__ Oh, __nv_bfloat16* __restrict__ Ol,
              const float* __restrict__ bias, const float* __restrict__ res,
              const float2* __restrict__ cs) {
    extern __shared__ char smem[];
    const uint32_t sb = smem_u32(smem);
    const int tid = threadIdx.x;
    const int lane = tid & 31;
    const int wid = tid >> 5;
    const int warp_m = wid & 1;
    const int warp_n = wid >> 1;
    const size_t bm = (size_t)blockIdx.y * 128;
    const size_t bn = (size_t)blockIdx.x * 128;

    float acc[4][4][4];
    #pragma unroll
    for (int i = 0; i < 4; i++)
        #pragma unroll
        for (int j = 0; j < 4; j++)
            #pragma unroll
            for (int q = 0; q < 4; q++) acc[i][j][q] = 0.f;

    const int nc = K >> 5;

    auto load_stage = [&](int c) {
        const int k0 = c << 5;
        const uint32_t sbase = sb + (c & 1) * STAGEB;
        #pragma unroll
        for (int t = 0; t < 8; t++) {
            int idx = tid + (t << 8);
            int tile = idx >> 9;
            int r    = (idx >> 2) & 127;
            int cch  = idx & 3;
            const __nv_bfloat16* base = (tile == 0) ? Ah : (tile == 1) ? Al
                                      : (tile == 2) ? Bh : Bl;
            size_t grow = ((tile < 2) ? bm : bn) + r;
            const __nv_bfloat16* g = base + grow * (size_t)K + k0 + cch * 8;
            cp16(sbase + tile * TILEB + r * ROWB + cch * 16, g);
        }
        cp_commit();
    };

    load_stage(0);

    const uint32_t aRowOff = (uint32_t)((warp_m * 64 + (lane & 15)) * ROWB + ((lane >> 4) << 4));
    const uint32_t bRow4Off = (uint32_t)((warp_n * 32 + ((lane & 16) >> 1) + (lane & 7)) * ROWB
                                         + ((lane & 8) << 1));

    for (int c = 0; c < nc; c++) {
        cp_wait<0>();
        __syncthreads();
        if (c + 1 < nc) load_stage(c + 1);

        const uint32_t st = sb + (c & 1) * STAGEB;
        const uint32_t aH = st + aRowOff;
        const uint32_t aL = st + TILEB + aRowOff;
        const uint32_t bH = st + 2 * TILEB + bRow4Off;
        const uint32_t bL = st + 3 * TILEB + bRow4Off;

        #pragma unroll
        for (int kk = 0; kk < 2; kk++) {
            const uint32_t kb = kk * 32;
            uint32_t a[4][4], bh[4][2], bl[4][2];
            #pragma unroll
            for (int p = 0; p < 2; p++) {
                ldmB4(bh[2*p][0], bh[2*p][1], bh[2*p+1][0], bh[2*p+1][1],
                      bH + p * (16 * ROWB) + kb);
                ldmB4(bl[2*p][0], bl[2*p][1], bl[2*p+1][0], bl[2*p+1][1],
                      bL + p * (16 * ROWB) + kb);
            }
            #pragma unroll
            for (int mt = 0; mt < 4; mt++)
                ldmA(a[mt], aH + mt * (16 * ROWB) + kb);
            #pragma unroll
            for (int mt = 0; mt < 4; mt++)
                #pragma unroll
                for (int nt = 0; nt < 4; nt++)
                    mma16816(acc[mt][nt], a[mt], bh[nt]);
            #pragma unroll
            for (int mt = 0; mt < 4; mt++)
                #pragma unroll
                for (int nt = 0; nt < 4; nt++)
                    mma16816(acc[mt][nt], a[mt], bl[nt]);
            #pragma unroll
            for (int mt = 0; mt < 4; mt++)
                ldmA(a[mt], aL + mt * (16 * ROWB) + kb);
            #pragma unroll
            for (int mt = 0; mt < 4; mt++)
                #pragma unroll
                for (int nt = 0; nt < 4; nt++)
                    mma16816(acc[mt][nt], a[mt], bh[nt]);
        }
    }

    #pragma unroll
    for (int mt = 0; mt < 4; mt++) {
        #pragma unroll
        for (int nt = 0; nt < 4; nt++) {
            size_t col = bn + warp_n * 32 + nt * 8 + (lane & 3) * 2;
            #pragma unroll
            for (int half = 0; half < 2; half++) {
                size_t row = bm + warp_m * 64 + mt * 16 + (lane >> 2) + half * 8;
                float v0 = acc[mt][nt][half * 2 + 0];
                float v1 = acc[mt][nt][half * 2 + 1];
                if (bias) { v0 += bias[col]; v1 += bias[col + 1]; }
                if (res) {
                    const float2 r2 = *(const float2*)(res + row * (size_t)N + col);
                    v0 += r2.x; v1 += r2.y;
                }
                if (RELU) { v0 = fmaxf(v0, 0.f); v1 = fmaxf(v1, 0.f); }
                if (ROPE && col < 2048) {
                    int t = (int)(row & (T_LEN - 1));
                    int p = ((int)col & 63) >> 1;
                    float2 c2 = cs[t * 32 + p];
                    float r0 = v0 * c2.x - v1 * c2.y;
                    float r1 = v0 * c2.y + v1 * c2.x;
                    v0 = r0; v1 = r1;
                }
                size_t o = row * (size_t)N + col;
                if (SPLIT) {
                    __nv_bfloat16 h0 = __float2bfloat16(v0);
                    __nv_bfloat16 h1 = __float2bfloat16(v1);
                    Oh[o] = h0;     Ol[o] = __float2bfloat16(v0 - __bfloat162float(h0));
                    Oh[o + 1] = h1; Ol[o + 1] = __float2bfloat16(v1 - __bfloat162float(h1));
                } else {
                    *(float2*)(C + o) = make_float2(v0, v1);
                }
            }
        }
    }
}

/* ====== LM-head GEMM: fp16, A single + B hi/lo, 2 MMAs per k-step ======== */
#define LTILEB (128 * ROWB)          /* 10240 */
#define LSTAGE (3 * LTILEB)          /* 30720: A, Bh, Bl */
#define LSMTOT (2 * LSTAGE)          /* 61440 */

__global__ __launch_bounds__(256, 2)
void mma_gemm_lm(const __half* __restrict__ A,
                 const __half* __restrict__ Bh, const __half* __restrict__ Bl,
                 int K, int N,
                 float* __restrict__ C, const float* __restrict__ bias) {
    extern __shared__ char smem[];
    const uint32_t sb = smem_u32(smem);
    const int tid = threadIdx.x;
    const int lane = tid & 31;
    const int wid = tid >> 5;
    const int warp_m = wid & 1;
    const int warp_n = wid >> 1;
    const size_t bm = (size_t)blockIdx.y * 128;
    const size_t bn = (size_t)blockIdx.x * 128;

    float acc[4][4][4];
    #pragma unroll
    for (int i = 0; i < 4; i++)
        #pragma unroll
        for (int j = 0; j < 4; j++)
            #pragma unroll
            for (int q = 0; q < 4; q++) acc[i][j][q] = 0.f;

    const int nc = K >> 5;

    auto load_stage = [&](int c) {
        const int k0 = c << 5;
        const uint32_t sbase = sb + (c & 1) * LSTAGE;
        #pragma unroll
        for (int t = 0; t < 6; t++) {
            int idx = tid + (t << 8);            /* 0..1535 */
            int tile = idx >> 9;                 /* 0 A, 1 Bh, 2 Bl */
            int r    = (idx >> 2) & 127;
            int cch  = idx & 3;
            const __half* base = (tile == 0) ? A : (tile == 1) ? Bh : Bl;
            size_t grow = ((tile == 0) ? bm : bn) + r;
            cp16(sbase + tile * LTILEB + r * ROWB + cch * 16,
                 base + grow * (size_t)K + k0 + cch * 8);
        }
        cp_commit();
    };

    load_stage(0);

    const uint32_t aRowOff = (uint32_t)((warp_m * 64 + (lane & 15)) * ROWB + ((lane >> 4) << 4));
    const uint32_t bRow4Off = (uint32_t)((warp_n * 32 + ((lane & 16) >> 1) + (lane & 7)) * ROWB
                                         + ((lane & 8) << 1));

    for (int c = 0; c < nc; c++) {
        cp_wait<0>();
        __syncthreads();
        if (c + 1 < nc) load_stage(c + 1);

        const uint32_t st = sb + (c & 1) * LSTAGE;
        const uint32_t aT = st + aRowOff;
        const uint32_t bH = st + LTILEB + bRow4Off;
        const uint32_t bL = st + 2 * LTILEB + bRow4Off;

        #pragma unroll
        for (int kk = 0; kk < 2; kk++) {
            const uint32_t kb = kk * 32;
            uint32_t a[4][4], bh[4][2], bl[4][2];
            #pragma unroll
            for (int p = 0; p < 2; p++) {
                ldmB4(bh[2*p][0], bh[2*p][1], bh[2*p+1][0], bh[2*p+1][1],
                      bH + p * (16 * ROWB) + kb);
                ldmB4(bl[2*p][0], bl[2*p][1], bl[2*p+1][0], bl[2*p+1][1],
                      bL + p * (16 * ROWB) + kb);
            }
            #pragma unroll
            for (int mt = 0; mt < 4; mt++)
                ldmA(a[mt], aT + mt * (16 * ROWB) + kb);
            #pragma unroll
            for (int mt = 0; mt < 4; mt++)
                #pragma unroll
                for (int nt = 0; nt < 4; nt++)
                    mma16816h(acc[mt][nt], a[mt], bh[nt]);
            #pragma unroll
            for (int mt = 0; mt < 4; mt++)
                #pragma unroll
                for (int nt = 0; nt < 4; nt++)
                    mma16816h(acc[mt][nt], a[mt], bl[nt]);
        }
    }

    #pragma unroll
    for (int mt = 0; mt < 4; mt++) {
        #pragma unroll
        for (int nt = 0; nt < 4; nt++) {
            size_t col = bn + warp_n * 32 + nt * 8 + (lane & 3) * 2;
            #pragma unroll
            for (int half = 0; half < 2; half++) {
                size_t row = bm + warp_m * 64 + mt * 16 + (lane >> 2) + half * 8;
                float v0 = acc[mt][nt][half * 2 + 0] + bias[col];
                float v1 = acc[mt][nt][half * 2 + 1] + bias[col + 1];
                *(float2*)(C + row * (size_t)N + col) = make_float2(v0, v1);
            }
        }
    }
}

/* ================= weight transpose+split ================================ */
__global__ void wt_gen(const float* __restrict__ in, long in_zs,
                       __nv_bfloat16* __restrict__ oh, __nv_bfloat16* __restrict__ ol,
                       long out_zs, int Kd, int Nd) {
    __shared__ float t[32][33];
    int z = blockIdx.z;
    in += (size_t)z * in_zs; oh += (size_t)z * out_zs; ol += (size_t)z * out_zs;
    int n0 = blockIdx.x * 32, k0 = blockIdx.y * 32;
    int tx = threadIdx.x, ty = threadIdx.y;
    #pragma unroll
    for (int j = ty; j < 32; j += 8)
        t[j][tx] = in[(size_t)(k0 + j) * Nd + n0 + tx];
    __syncthreads();
    #pragma unroll
    for (int j = ty; j < 32; j += 8) {
        float v = t[tx][j];
        size_t o = (size_t)(n0 + j) * Kd + k0 + tx;
        __nv_bfloat16 h = __float2bfloat16(v);
        oh[o] = h;
        ol[o] = __float2bfloat16(v - __bfloat162float(h));
    }
}
/* LM weight: fp16 hi/lo transpose [1024][32000] -> [32000][1024] */
__global__ void wt_lm16(const float* __restrict__ in,
                        __half* __restrict__ oh, __half* __restrict__ ol) {
    __shared__ float t[32][33];
    int n0 = blockIdx.x * 32, k0 = blockIdx.y * 32;
    int tx = threadIdx.x, ty = threadIdx.y;
    #pragma unroll
    for (int j = ty; j < 32; j += 8)
        t[j][tx] = in[(size_t)(k0 + j) * VOCAB + n0 + tx];
    __syncthreads();
    #pragma unroll
    for (int j = ty; j < 32; j += 8) {
        float v = t[tx][j];
        size_t o = (size_t)(n0 + j) * E_DIM + k0 + tx;
        __half h = __float2half_rn(v);
        oh[o] = h;
        ol[o] = __float2half_rn(v - __half2float(h));
    }
}
__global__ void wt_qkv_all(const float* __restrict__ wq, const float* __restrict__ wk,
                           const float* __restrict__ wv,
                           __nv_bfloat16* __restrict__ oh, __nv_bfloat16* __restrict__ ol) {
    __shared__ float t[32][33];
    int z = blockIdx.z;
    int sel = z / 96;
    int zz  = z - sel * 96;
    int l = zz >> 4, h = zz & 15;
    const float* w = (sel == 0) ? wq : (sel == 1) ? wk : wv;
    const float scale = (sel == 0) ? 0.03125f : 1.0f;
    const float* in = w + (size_t)zz * E_DIM * HD;
    size_t orow0 = (size_t)l * 3 * E_DIM + (size_t)sel * E_DIM + h * HD;
    __nv_bfloat16* ohp = oh + orow0 * E_DIM;
    __nv_bfloat16* olp = ol + orow0 * E_DIM;
    int d0 = blockIdx.x * 32, e0 = blockIdx.y * 32;
    int tx = threadIdx.x, ty = threadIdx.y;
    #pragma unroll
    for (int j = ty; j < 32; j += 8)
        t[j][tx] = in[(size_t)(e0 + j) * HD + d0 + tx];
    __syncthreads();
    #pragma unroll
    for (int j = ty; j < 32; j += 8) {
        float v = t[tx][j] * scale;
        size_t o = (size_t)(d0 + j) * E_DIM + e0 + tx;
        __nv_bfloat16 hh = __float2bfloat16(v);
        ohp[o] = hh;
        olp[o] = __float2bfloat16(v - __bfloat162float(hh));
    }
}

/* ================= fused embed + LN1(layer0) + cs table ================== */
__global__ __launch_bounds__(256)
void embed_ln_kernel(const int* __restrict__ idx, const float* __restrict__ emb,
                     const float* __restrict__ g, const float* __restrict__ b,
                     float* __restrict__ x,
                     __nv_bfloat16* __restrict__ yh, __nv_bfloat16* __restrict__ yl) {
    int m = blockIdx.x, tid = threadIdx.x;
    __shared__ float r1[256], r2[256];
    const float4* src = (const float4*)(emb + (size_t)idx[m] * E_DIM);
    float4 v = src[tid];
    ((float4*)(x + (size_t)m * E_DIM))[tid] = v;
    r1[tid] = v.x + v.y + v.z + v.w;
    r2[tid] = v.x * v.x + v.y * v.y + v.z * v.z + v.w * v.w;
    if (m < 128) {
        int i = m * 256 + tid;
        if (i < T_LEN * 32) {
            int t = i >> 5, p = i & 31;
            float invf = powf(10000.f, -(float)(2 * p) / (float)HD);
            float sn, c;
            sincosf((float)t * invf, &sn, &c);
            g_cs[i] = make_float2(c, sn);
        }
    }
    __syncthreads();
    for (int s = 128; s > 0; s >>= 1) {
        if (tid < s) { r1[tid] += r1[tid + s]; r2[tid] += r2[tid + s]; }
        __syncthreads();
    }
    float mean = r1[0] * (1.0f / E_DIM);
    float var  = r2[0] * (1.0f / E_DIM) - mean * mean;
    float rstd = rsqrtf(var + 1e-5f);
    float4 gg = ((const float4*)g)[tid];
    float4 bb = ((const float4*)b)[tid];
    float o[4] = { (v.x - mean) * rstd * gg.x + bb.x, (v.y - mean) * rstd * gg.y + bb.y,
                   (v.z - mean) * rstd * gg.z + bb.z, (v.w - mean) * rstd * gg.w + bb.w };
    size_t base = (size_t)m * E_DIM + tid * 4;
    #pragma unroll
    for (int j = 0; j < 4; j++) {
        __nv_bfloat16 h = __float2bfloat16(o[j]);
        yh[base + j] = h;
        yl[base + j] = __float2bfloat16(o[j] - __bfloat162float(h));
    }
}

__global__ __launch_bounds__(256)
void ln_split_kernel(const float* __restrict__ x, const float* __restrict__ g,
                     const float* __restrict__ b,
                     __nv_bfloat16* __restrict__ yh, __nv_bfloat16* __restrict__ yl) {
    int m = blockIdx.x, tid = threadIdx.x;
    __shared__ float r1[256], r2[256];
    const float4* xr = (const float4*)(x + (size_t)m * E_DIM);
    float4 v = xr[tid];
    r1[tid] = v.x + v.y + v.z + v.w;
    r2[tid] = v.x * v.x + v.y * v.y + v.z * v.z + v.w * v.w;
    __syncthreads();
    for (int s = 128; s > 0; s >>= 1) {
        if (tid < s) { r1[tid] += r1[tid + s]; r2[tid] += r2[tid + s]; }
        __syncthreads();
    }
    float mean = r1[0] * (1.0f / E_DIM);
    float var  = r2[0] * (1.0f / E_DIM) - mean * mean;
    float rstd = rsqrtf(var + 1e-5f);
    float4 gg = ((const float4*)g)[tid];
    float4 bb = ((const float4*)b)[tid];
    float o[4] = { (v.x - mean) * rstd * gg.x + bb.x, (v.y - mean) * rstd * gg.y + bb.y,
                   (v.z - mean) * rstd * gg.z + bb.z, (v.w - mean) * rstd * gg.w + bb.w };
    size_t base = (size_t)m * E_DIM + tid * 4;
    #pragma unroll
    for (int j = 0; j < 4; j++) {
        __nv_bfloat16 h = __float2bfloat16(o[j]);
        yh[base + j] = h;
        yl[base + j] = __float2bfloat16(o[j] - __bfloat162float(h));
    }
}

__global__ void split_f16_kernel(const float* __restrict__ x,
                                 __half* __restrict__ yf, int n) {
    int i = blockIdx.x * blockDim.x + threadIdx.x;
    if (i < n) yf[i] = __float2half_rn(x[i]);
}

/* ======== flash attention (HMMA, split-bf16): 64q tiles, 64k chunks ====== */
#define ARS  144
#define ATILE (64 * ARS)
#define ASM  (4 * ATILE)

__global__ __launch_bounds__(128)
void attn_kernel(const __nv_bfloat16* __restrict__ qg_h, const __nv_bfloat16* __restrict__ qg_l,
                 __nv_bfloat16* __restrict__ oh, __nv_bfloat16* __restrict__ ol) {
    extern __shared__ char sm[];
    const uint32_t sb = smem_u32(sm);
    const int tid = threadIdx.x, lane = tid & 31, w = tid >> 5;
    const int qt = blockIdx.x;
    const int b  = blockIdx.y >> 4;
    const int h  = blockIdx.y & 15;
    const int t0 = qt * 64;
    const size_t mbase = (size_t)b * T_LEN;

    for (int i = tid; i < 512; i += 128) {
        int r = i >> 3, c = i & 7;
        size_t src = (mbase + t0 + r) * 3072 + h * 64 + c * 8;
        cp16(sb + r * ARS + c * 16, qg_h + src);
        cp16(sb + ATILE + r * ARS + c * 16, qg_l + src);
    }
    cp_commit(); cp_wait<0>(); __syncthreads();

    uint32_t Qh[4][4], Ql[4][4];
    {
        uint32_t qo = sb + (w * 16 + (lane & 15)) * ARS + ((lane >> 4) << 4);
        #pragma unroll
        for (int ks = 0; ks < 4; ks++) {
            ldmA(Qh[ks], qo + ks * 32);
            ldmA(Ql[ks], qo + ATILE + ks * 32);
        }
    }
    __syncthreads();

    float O[8][4];
    #pragma unroll
    for (int i = 0; i < 8; i++)
        #pragma unroll
        for (int j = 0; j < 4; j++) O[i][j] = 0.f;
    float m0 = -1e30f, m1 = -1e30f, l0 = 0.f, l1 = 0.f;
    const int g = lane >> 2, t4 = lane & 3;
    const int row0 = t0 + w * 16 + g;
    const int row1 = row0 + 8;

    const int nch = qt + 1;
    for (int ch = 0; ch < nch; ch++) {
        const int c0 = ch * 64;
        for (int i = tid; i < 512; i += 128) {
            int r = i >> 3, c = i & 7;
            size_t srck = (mbase + c0 + r) * 3072 + 1024 + h * 64 + c * 8;
            cp16(sb + 0 * ATILE + r * ARS + c * 16, qg_h + srck);
            cp16(sb + 1 * ATILE + r * ARS + c * 16, qg_l + srck);
            cp16(sb + 2 * ATILE + r * ARS + c * 16, qg_h + srck + 1024);
            cp16(sb + 3 * ATILE + r * ARS + c * 16, qg_l + srck + 1024);
        }
        cp_commit(); cp_wait<0>(); __syncthreads();

        float S[8][4];
        const uint32_t kbo = sb + (lane & 7) * ARS + (((lane >> 3) & 1) << 4);
        #pragma unroll
        for (int nt = 0; nt < 8; nt++) {
            #pragma unroll
            for (int j = 0; j < 4; j++) S[nt][j] = 0.f;
            uint32_t kh[4][2], kl[4][2];
            #pragma unroll
            for (int ks = 0; ks < 4; ks++) {
                ldmB(kh[ks], kbo + nt * (8 * ARS) + ks * 32);
                ldmB(kl[ks], kbo + ATILE + nt * (8 * ARS) + ks * 32);
            }
            #pragma unroll
            for (int ks = 0; ks < 4; ks++) {
                mma16816(S[nt], Qh[ks], kh[ks]);
                mma16816(S[nt], Qh[ks], kl[ks]);
                mma16816(S[nt], Ql[ks], kh[ks]);
            }
        }

        if (ch == nch - 1) {
            #pragma unroll
            for (int nt = 0; nt < 8; nt++) {
                int kc = c0 + nt * 8 + 2 * t4;
                if (kc > row0)     S[nt][0] = -1e30f;
                if (kc + 1 > row0) S[nt][1] = -1e30f;
                if (kc > row1)     S[nt][2] = -1e30f;
                if (kc + 1 > row1) S[nt][3] = -1e30f;
            }
        }

        float mc0 = -1e30f, mc1 = -1e30f;
        #pragma unroll
        for (int nt = 0; nt < 8; nt++) {
            mc0 = fmaxf(mc0, fmaxf(S[nt][0], S[nt][1]));
            mc1 = fmaxf(mc1, fmaxf(S[nt][2], S[nt][3]));
        }
        mc0 = fmaxf(mc0, __shfl_xor_sync(~0u, mc0, 1));
        mc0 = fmaxf(mc0, __shfl_xor_sync(~0u, mc0, 2));
        mc1 = fmaxf(mc1, __shfl_xor_sync(~0u, mc1, 1));
        mc1 = fmaxf(mc1, __shfl_xor_sync(~0u, mc1, 2));
        float mn0 = fmaxf(m0, mc0), mn1 = fmaxf(m1, mc1);
        float a0 = __expf(m0 - mn0), a1 = __expf(m1 - mn1);
        m0 = mn0; m1 = mn1;
        float s0 = 0.f, s1 = 0.f;
        #pragma unroll
        for (int nt = 0; nt < 8; nt++) {
            S[nt][0] = __expf(S[nt][0] - mn0); s0 += S[nt][0];
            S[nt][1] = __expf(S[nt][1] - mn0); s0 += S[nt][1];
            S[nt][2] = __expf(S[nt][2] - mn1); s1 += S[nt][2];
            S[nt][3] = __expf(S[nt][3] - mn1); s1 += S[nt][3];
        }
        s0 += __shfl_xor_sync(~0u, s0, 1); s0 += __shfl_xor_sync(~0u, s0, 2);
        s1 += __shfl_xor_sync(~0u, s1, 1); s1 += __shfl_xor_sync(~0u, s1, 2);
        l0 = l0 * a0 + s0;
        l1 = l1 * a1 + s1;
        #pragma unroll
        for (int nt = 0; nt < 8; nt++) {
            O[nt][0] *= a0; O[nt][1] *= a0; O[nt][2] *= a1; O[nt][3] *= a1;
        }

        #pragma unroll
        for (int ks = 0; ks < 4; ks++) {
            uint32_t Ph[4], Pl[4];
            #pragma unroll
            for (int half = 0; half < 2; half++) {
                float p0 = S[2 * ks + half][0], p1 = S[2 * ks + half][1];
                float p2 = S[2 * ks + half][2], p3 = S[2 * ks + half][3];
                __nv_bfloat16 h0 = __float2bfloat16(p0), h1 = __float2bfloat16(p1);
                __nv_bfloat16 h2 = __float2bfloat16(p2), h3 = __float2bfloat16(p3);
                Ph[half * 2 + 0] = packbf(__bfloat162float(h0), __bfloat162float(h1));
                Ph[half * 2 + 1] = packbf(__bfloat162float(h2), __bfloat162float(h3));
                Pl[half * 2 + 0] = packbf(p0 - __bfloat162float(h0), p1 - __bfloat162float(h1));
                Pl[half * 2 + 1] = packbf(p2 - __bfloat162float(h2), p3 - __bfloat162float(h3));
            }
            uint32_t A_h[4] = { Ph[0], Ph[1], Ph[2], Ph[3] };
            uint32_t A_l[4] = { Pl[0], Pl[1], Pl[2], Pl[3] };
            const uint32_t vbase = sb + 2 * ATILE + (ks * 16 + (lane & 15)) * ARS;
            #pragma unroll
            for (int nt = 0; nt < 8; nt++) {
                uint32_t vh[2], vl[2];
                ldmT(vh, vbase + nt * 16);
                ldmT(vl, vbase + ATILE + nt * 16);
                mma16816(O[nt], A_h, vh);
                mma16816(O[nt], A_h, vl);
                mma16816(O[nt], A_l, vh);
            }
        }
        __syncthreads();
    }

    const float il0 = 1.f / l0, il1 = 1.f / l1;
    #pragma unroll
    for (int nt = 0; nt < 8; nt++) {
        size_t p0 = (mbase + row0) * E_DIM + h * 64 + nt * 8 + 2 * t4;
        size_t p1 = (mbase + row1) * E_DIM + h * 64 + nt * 8 + 2 * t4;
        float o00 = O[nt][0] * il0, o01 = O[nt][1] * il0;
        float o10 = O[nt][2] * il1, o11 = O[nt][3] * il1;
        __nv_bfloat16 h00 = __float2bfloat16(o00), h01 = __float2bfloat16(o01);
        __nv_bfloat16 h10 = __float2bfloat16(o10), h11 = __float2bfloat16(o11);
        oh[p0] = h00;     ol[p0] = __float2bfloat16(o00 - __bfloat162float(h00));
        oh[p0 + 1] = h01; ol[p0 + 1] = __float2bfloat16(o01 - __bfloat162float(h01));
        oh[p1] = h10;     ol[p1] = __float2bfloat16(o10 - __bfloat162float(h10));
        oh[p1 + 1] = h11; ol[p1 + 1] = __float2bfloat16(o11 - __bfloat162float(h11));
    }
}

/* ================= NLL + loss ============================================ */
__global__ __launch_bounds__(256)
void nll_kernel(const float* __restrict__ logits, const int* __restrict__ tgt,
                float* __restrict__ nll) {
    int m = blockIdx.x, tid = threadIdx.x;
    const float* lr = logits + (size_t)m * VOCAB;
    __shared__ float red[256];
    float mx = -1e30f;
    for (int n = tid; n < VOCAB; n += 256) mx = fmaxf(mx, lr[n]);
    red[tid] = mx;
    __syncthreads();
    for (int s = 128; s > 0; s >>= 1) {
        if (tid < s) red[tid] = fmaxf(red[tid], red[tid + s]);
        __syncthreads();
    }
    mx = red[0];
    __syncthreads();
    float sum = 0.f;
    for (int n = tid; n < VOCAB; n += 256) sum += __expf(lr[n] - mx);
    red[tid] = sum;
    __syncthreads();
    for (int s = 128; s > 0; s >>= 1) {
        if (tid < s) red[tid] += red[tid + s];
        __syncthreads();
    }
    if (tid == 0)
        nll[m] = (logf(red[0]) + mx) - lr[tgt[m]];
}

__global__ __launch_bounds__(256)
void loss_reduce_kernel(const float* __restrict__ nll, float* __restrict__ out) {
    __shared__ float red[256];
    int tid = threadIdx.x;
    float s = 0.f;
    for (int i = tid; i < MTOK; i += 256) s += nll[i];
    red[tid] = s;
    __syncthreads();
    for (int k = 128; k > 0; k >>= 1) {
        if (tid < k) red[tid] += red[tid + k];
        __syncthreads();
    }
    if (tid == 0) out[0] = red[0] * (1.0f / MTOK);
}

/* ================= host orchestration ==================================== */
extern "C" void kernel_launch(void* const* d_in, const int* in_sizes, int n_in,
                              void* d_out, int out_size) {
    const int*   idx   = (const int*)  d_in[0];
    const int*   tgt   = (const int*)  d_in[1];
    const float* emb   = (const float*)d_in[2];
    const float* wq    = (const float*)d_in[3];
    const float* wk    = (const float*)d_in[4];
    const float* wv    = (const float*)d_in[5];
    const float* wproj = (const float*)d_in[6];
    const float* bproj = (const float*)d_in[7];
    const float* w1    = (const float*)d_in[8];
    const float* b1    = (const float*)d_in[9];
    const float* w2    = (const float*)d_in[10];
    const float* b2    = (const float*)d_in[11];
    const float* ln1g  = (const float*)d_in[12];
    const float* ln1b  = (const float*)d_in[13];
    const float* ln2g  = (const float*)d_in[14];
    const float* ln2b  = (const float*)d_in[15];
    const float* lm_w  = (const float*)d_in[16];
    const float* lm_b  = (const float*)d_in[17];

    float *x, *nll, *lscr;
    float2* cs;
    __nv_bfloat16 *yh, *yl, *qh, *ql, *oh, *ol, *hh, *hl;
    __nv_bfloat16 *qkvTh, *qkvTl, *projTh, *projTl, *w1Th, *w1Tl, *w2Th, *w2Tl;
    __half *lmTh, *lmTl, *yf;
    cudaGetSymbolAddress((void**)&x,     g_x);
    cudaGetSymbolAddress((void**)&yh,    g_yh);
    cudaGetSymbolAddress((void**)&yl,    g_yl);
    cudaGetSymbolAddress((void**)&qh,    g_qh);
    cudaGetSymbolAddress((void**)&ql,    g_ql);
    cudaGetSymbolAddress((void**)&oh,    g_oh);
    cudaGetSymbolAddress((void**)&ol,    g_ol);
    cudaGetSymbolAddress((void**)&hh,    g_hh);
    cudaGetSymbolAddress((void**)&hl,    g_hl);
    cudaGetSymbolAddress((void**)&nll,   g_nllv);
    cudaGetSymbolAddress((void**)&lscr,  g_logits_scratch);
    cudaGetSymbolAddress((void**)&cs,    g_cs);
    cudaGetSymbolAddress((void**)&qkvTh, g_qkvT_h);
    cudaGetSymbolAddress((void**)&qkvTl, g_qkvT_l);
    cudaGetSymbolAddress((void**)&projTh, g_projT_h);
    cudaGetSymbolAddress((void**)&projTl, g_projT_l);
    cudaGetSymbolAddress((void**)&w1Th,  g_w1T_h);
    cudaGetSymbolAddress((void**)&w1Tl,  g_w1T_l);
    cudaGetSymbolAddress((void**)&w2Th,  g_w2T_h);
    cudaGetSymbolAddress((void**)&w2Tl,  g_w2T_l);
    cudaGetSymbolAddress((void**)&lmTh,  g_lmT_h);
    cudaGetSymbolAddress((void**)&lmTl,  g_lmT_l);
    cudaGetSymbolAddress((void**)&yf,    g_yf);

    cudaFuncSetAttribute(mma_gemm<false, false, false>, cudaFuncAttributeMaxDynamicSharedMemorySize, SMTOT);
    cudaFuncSetAttribute(mma_gemm<false, true,  true >, cudaFuncAttributeMaxDynamicSharedMemorySize, SMTOT);
    cudaFuncSetAttribute(mma_gemm<true,  true,  false>, cudaFuncAttributeMaxDynamicSharedMemorySize, SMTOT);
    cudaFuncSetAttribute(mma_gemm_lm, cudaFuncAttributeMaxDynamicSharedMemorySize, LSMTOT);

    const long BTV = (long)MTOK * VOCAB;
    float* logits = ((long)out_size >= BTV) ? (float*)d_out : lscr;

    dim3 tb(32, 8);
    embed_ln_kernel<<<MTOK, 256>>>(idx, emb, ln1g, ln1b, x, yh, yl);
    wt_qkv_all<<<dim3(2, 32, 288), tb>>>(wq, wk, wv, qkvTh, qkvTl);
    mma_gemm<false, true, true><<<dim3(3 * E_DIM / 128, MTOK / 128), 256, SMTOT>>>(
        yh, yl, qkvTh, qkvTl, E_DIM, 3 * E_DIM,
        nullptr, qh, ql, nullptr, nullptr, (const float2*)cs);
    attn_kernel<<<dim3(T_LEN / 64, BATCH * N_HEAD), 128, ASM>>>(qh, ql, oh, ol);

    wt_gen<<<dim3(32, 32, N_LAYER), tb>>>(wproj, (long)E_DIM * E_DIM, projTh, projTl,
                                          (long)E_DIM * E_DIM, E_DIM, E_DIM);
    wt_gen<<<dim3(128, 32, N_LAYER), tb>>>(w1, (long)E_DIM * FF, w1Th, w1Tl,
                                           (long)E_DIM * FF, E_DIM, FF);
    wt_gen<<<dim3(32, 128, N_LAYER), tb>>>(w2, (long)FF * E_DIM, w2Th, w2Tl,
                                           (long)FF * E_DIM, FF, E_DIM);
    wt_lm16<<<dim3(1000, 32, 1), tb>>>(lm_w, lmTh, lmTl);

    for (int l = 0; l < N_LAYER; l++) {
        size_t qkvW = (size_t)l * 3 * E_DIM * E_DIM;
        size_t prW  = (size_t)l * E_DIM * E_DIM;
        size_t w1W  = (size_t)l * FF * E_DIM;

        if (l > 0) {
            ln_split_kernel<<<MTOK, 256>>>(x, ln1g + (size_t)l * E_DIM, ln1b + (size_t)l * E_DIM, yh, yl);
            mma_gemm<false, true, true><<<dim3(3 * E_DIM / 128, MTOK / 128), 256, SMTOT>>>(
                yh, yl, qkvTh + qkvW, qkvTl + qkvW, E_DIM, 3 * E_DIM,
                nullptr, qh, ql, nullptr, nullptr, (const float2*)cs);
            attn_kernel<<<dim3(T_LEN / 64, BATCH * N_HEAD), 128, ASM>>>(qh, ql, oh, ol);
        }

        mma_gemm<false, false, false><<<dim3(E_DIM / 128, MTOK / 128), 256, SMTOT>>>(
            oh, ol, projTh + prW, projTl + prW, E_DIM, E_DIM,
            x, nullptr, nullptr, bproj + (size_t)l * E_DIM, x, nullptr);

        ln_split_kernel<<<MTOK, 256>>>(x, ln2g + (size_t)l * E_DIM, ln2b + (size_t)l * E_DIM, yh, yl);

        mma_gemm<true, true, false><<<dim3(FF / 128, MTOK / 128), 256, SMTOT>>>(
            yh, yl, w1Th + w1W, w1Tl + w1W, E_DIM, FF,
            nullptr, hh, hl, b1 + (size_t)l * FF, nullptr, nullptr);

        mma_gemm<false, false, false><<<dim3(E_DIM / 128, MTOK / 128), 256, SMTOT>>>(
            hh, hl, w2Th + w1W, w2Tl + w1W, FF, E_DIM,
            x, nullptr, nullptr, b2 + (size_t)l * E_DIM, x, nullptr);
    }

    split_f16_kernel<<<(MTOK * E_DIM + 255) / 256, 256>>>(x, yf, MTOK * E_DIM);

    /* LM head: fp16 2-MMA (A single, B hi/lo) */
    mma_gemm_lm<<<dim3(VOCAB / 128, MTOK / 128), 256, LSMTOT>>>(
        yf, lmTh, lmTl, E_DIM, VOCAB, logits, lm_b);

    nll_kernel<<<MTOK, 256>>>(logits, tgt, nll);

    if ((long)out_size == BTV + 1) {
        loss_reduce_kernel<<<1, 256>>>(nll, (float*)d_out + BTV);
    } else if ((long)out_size < BTV) {
        loss_reduce_kernel<<<1, 256>>>(nll, (float*)d_out);
    }
}

// round 16
// speedup vs baseline: 1.3901x; 1.1872x over previous
#include <cuda_runtime.h>
#include <cuda_bf16.h>
#include <cuda_fp16.h>
#include <math.h>
#include <cstdint>

#define E_DIM   1024
#define N_HEAD  16
#define HD      64
#define T_LEN   1024
#define N_LAYER 6
#define VOCAB   32000
#define BATCH   2
#define MTOK    (BATCH * T_LEN)     /* 2048 */
#define FF      (4 * E_DIM)         /* 4096 */

/* ================= scratch =============================================== */
__device__ float g_x   [MTOK * E_DIM];
__device__ __nv_bfloat16 g_yh[MTOK * E_DIM];
__device__ __nv_bfloat16 g_yl[MTOK * E_DIM];
__device__ __nv_bfloat16 g_qh[(size_t)MTOK * 3 * E_DIM];
__device__ __nv_bfloat16 g_ql[(size_t)MTOK * 3 * E_DIM];
__device__ __nv_bfloat16 g_oh[MTOK * E_DIM];
__device__ __nv_bfloat16 g_ol[MTOK * E_DIM];
__device__ __half g_y16[MTOK * E_DIM];              /* fp16 LN2 out */
__device__ __half g_h16[(size_t)MTOK * FF];         /* fp16 W1 out */
__device__ float g_nllv[MTOK];
__device__ float g_logits_scratch[(size_t)MTOK * VOCAB];
__device__ float2 g_cs[T_LEN * 32];
__device__ __nv_bfloat16 g_qkvT_h[(size_t)N_LAYER * 3 * E_DIM * E_DIM];
__device__ __nv_bfloat16 g_qkvT_l[(size_t)N_LAYER * 3 * E_DIM * E_DIM];
__device__ __nv_bfloat16 g_projT_h[(size_t)N_LAYER * E_DIM * E_DIM];
__device__ __nv_bfloat16 g_projT_l[(size_t)N_LAYER * E_DIM * E_DIM];
__device__ __half g_w1T16_h[(size_t)N_LAYER * FF * E_DIM];
__device__ __half g_w1T16_l[(size_t)N_LAYER * FF * E_DIM];
__device__ __half g_w2T16_h[(size_t)N_LAYER * E_DIM * FF];
__device__ __half g_w2T16_l[(size_t)N_LAYER * E_DIM * FF];
__device__ __half g_lmT_h[(size_t)VOCAB * E_DIM];
__device__ __half g_lmT_l[(size_t)VOCAB * E_DIM];
__device__ __half g_yf  [MTOK * E_DIM];             /* fp16 LM input */

/* ================= small PTX wrappers ==================================== */
__device__ __forceinline__ uint32_t smem_u32(const void* p) {
    uint32_t a;
    asm("{ .reg .u64 t; cvta.to.shared.u64 t, %1; cvt.u32.u64 %0, t; }" : "=r"(a) : "l"(p));
    return a;
}
__device__ __forceinline__ void cp16(uint32_t s, const void* g) {
    asm volatile("cp.async.cg.shared.global [%0], [%1], 16;" :: "r"(s), "l"(g));
}
__device__ __forceinline__ void cp_commit() { asm volatile("cp.async.commit_group;"); }
template<int N> __device__ __forceinline__ void cp_wait() {
    asm volatile("cp.async.wait_group %0;" :: "n"(N));
}
__device__ __forceinline__ void ldmA(uint32_t* r, uint32_t a) {
    asm volatile("ldmatrix.sync.aligned.m8n8.x4.shared.b16 {%0,%1,%2,%3}, [%4];"
                 : "=r"(r[0]), "=r"(r[1]), "=r"(r[2]), "=r"(r[3]) : "r"(a));
}
__device__ __forceinline__ void ldmB(uint32_t* r, uint32_t a) {
    asm volatile("ldmatrix.sync.aligned.m8n8.x2.shared.b16 {%0,%1}, [%2];"
                 : "=r"(r[0]), "=r"(r[1]) : "r"(a));
}
__device__ __forceinline__ void ldmB4(uint32_t& r0, uint32_t& r1, uint32_t& r2, uint32_t& r3,
                                      uint32_t a) {
    asm volatile("ldmatrix.sync.aligned.m8n8.x4.shared.b16 {%0,%1,%2,%3}, [%4];"
                 : "=r"(r0), "=r"(r1), "=r"(r2), "=r"(r3) : "r"(a));
}
__device__ __forceinline__ void ldmT(uint32_t* r, uint32_t a) {
    asm volatile("ldmatrix.sync.aligned.m8n8.x2.trans.shared.b16 {%0,%1}, [%2];"
                 : "=r"(r[0]), "=r"(r[1]) : "r"(a));
}
__device__ __forceinline__ void mma16816(float* c, const uint32_t* a, const uint32_t* b) {
    asm volatile("mma.sync.aligned.m16n8k16.row.col.f32.bf16.bf16.f32 "
                 "{%0,%1,%2,%3}, {%4,%5,%6,%7}, {%8,%9}, {%0,%1,%2,%3};"
                 : "+f"(c[0]), "+f"(c[1]), "+f"(c[2]), "+f"(c[3])
                 : "r"(a[0]), "r"(a[1]), "r"(a[2]), "r"(a[3]), "r"(b[0]), "r"(b[1]));
}
__device__ __forceinline__ void mma16816h(float* c, const uint32_t* a, const uint32_t* b) {
    asm volatile("mma.sync.aligned.m16n8k16.row.col.f32.f16.f16.f32 "
                 "{%0,%1,%2,%3}, {%4,%5,%6,%7}, {%8,%9}, {%0,%1,%2,%3};"
                 : "+f"(c[0]), "+f"(c[1]), "+f"(c[2]), "+f"(c[3])
                 : "r"(a[0]), "r"(a[1]), "r"(a[2]), "r"(a[3]), "r"(b[0]), "r"(b[1]));
}
__device__ __forceinline__ uint32_t packbf(float a, float b) {
    __nv_bfloat162 t = __floats2bfloat162_rn(a, b);
    return *(uint32_t*)&t;
}

/* ============ HMMA GEMM 128x128 bf16 3-MMA (QKV / proj) ================== */
#define ROWB   80
#define TILEB  (128 * ROWB)
#define STAGEB (4 * TILEB)
#define SMTOT  (2 * STAGEB)

template<bool SPLIT, bool ROPE>
__global__ __launch_bounds__(256, 2)
void mma_gemm(const __nv_bfloat16* __restrict__ Ah, const __nv_bfloat16* __restrict__ Al,
              const __nv_bfloat16* __restrict__ Bh, const __nv_bfloat16* __restrict__ Bl,
              int K, int N,
              float* __restrict__ C,
              __nv_bfloat16* __restrict__ Oh, __nv_bfloat16* __restrict__ Ol,
              const float* __restrict__ bias, const float* __restrict__ res,
              const float2* __restrict__ cs) {
    extern __shared__ char smem[];
    const uint32_t sb = smem_u32(smem);
    const int tid = threadIdx.x;
    const int lane = tid & 31;
    const int wid = tid >> 5;
    const int warp_m = wid & 1;
    const int warp_n = wid >> 1;
    const size_t bm = (size_t)blockIdx.y * 128;
    const size_t bn = (size_t)blockIdx.x * 128;

    float acc[4][4][4];
    #pragma unroll
    for (int i = 0; i < 4; i++)
        #pragma unroll
        for (int j = 0; j < 4; j++)
            #pragma unroll
            for (int q = 0; q < 4; q++) acc[i][j][q] = 0.f;

    const int nc = K >> 5;

    auto load_stage = [&](int c) {
        const int k0 = c << 5;
        const uint32_t sbase = sb + (c & 1) * STAGEB;
        #pragma unroll
        for (int t = 0; t < 8; t++) {
            int idx = tid + (t << 8);
            int tile = idx >> 9;
            int r    = (idx >> 2) & 127;
            int cch  = idx & 3;
            const __nv_bfloat16* base = (tile == 0) ? Ah : (tile == 1) ? Al
                                      : (tile == 2) ? Bh : Bl;
            size_t grow = ((tile < 2) ? bm : bn) + r;
            cp16(sbase + tile * TILEB + r * ROWB + cch * 16,
                 base + grow * (size_t)K + k0 + cch * 8);
        }
        cp_commit();
    };

    load_stage(0);

    const uint32_t aRowOff = (uint32_t)((warp_m * 64 + (lane & 15)) * ROWB + ((lane >> 4) << 4));
    const uint32_t bRow4Off = (uint32_t)((warp_n * 32 + ((lane & 16) >> 1) + (lane & 7)) * ROWB
                                         + ((lane & 8) << 1));

    for (int c = 0; c < nc; c++) {
        cp_wait<0>();
        __syncthreads();
        if (c + 1 < nc) load_stage(c + 1);

        const uint32_t st = sb + (c & 1) * STAGEB;
        const uint32_t aH = st + aRowOff;
        const uint32_t aL = st + TILEB + aRowOff;
        const uint32_t bH = st + 2 * TILEB + bRow4Off;
        const uint32_t bL = st + 3 * TILEB + bRow4Off;

        #pragma unroll
        for (int kk = 0; kk < 2; kk++) {
            const uint32_t kb = kk * 32;
            uint32_t a[4][4], bh[4][2], bl[4][2];
            #pragma unroll
            for (int p = 0; p < 2; p++) {
                ldmB4(bh[2*p][0], bh[2*p][1], bh[2*p+1][0], bh[2*p+1][1],
                      bH + p * (16 * ROWB) + kb);
                ldmB4(bl[2*p][0], bl[2*p][1], bl[2*p+1][0], bl[2*p+1][1],
                      bL + p * (16 * ROWB) + kb);
            }
            #pragma unroll
            for (int mt = 0; mt < 4; mt++)
                ldmA(a[mt], aH + mt * (16 * ROWB) + kb);
            #pragma unroll
            for (int mt = 0; mt < 4; mt++)
                #pragma unroll
                for (int nt = 0; nt < 4; nt++)
                    mma16816(acc[mt][nt], a[mt], bh[nt]);
            #pragma unroll
            for (int mt = 0; mt < 4; mt++)
                #pragma unroll
                for (int nt = 0; nt < 4; nt++)
                    mma16816(acc[mt][nt], a[mt], bl[nt]);
            #pragma unroll
            for (int mt = 0; mt < 4; mt++)
                ldmA(a[mt], aL + mt * (16 * ROWB) + kb);
            #pragma unroll
            for (int mt = 0; mt < 4; mt++)
                #pragma unroll
                for (int nt = 0; nt < 4; nt++)
                    mma16816(acc[mt][nt], a[mt], bh[nt]);
        }
    }

    #pragma unroll
    for (int mt = 0; mt < 4; mt++) {
        #pragma unroll
        for (int nt = 0; nt < 4; nt++) {
            size_t col = bn + warp_n * 32 + nt * 8 + (lane & 3) * 2;
            #pragma unroll
            for (int half = 0; half < 2; half++) {
                size_t row = bm + warp_m * 64 + mt * 16 + (lane >> 2) + half * 8;
                float v0 = acc[mt][nt][half * 2 + 0];
                float v1 = acc[mt][nt][half * 2 + 1];
                if (bias) { v0 += bias[col]; v1 += bias[col + 1]; }
                if (res) {
                    const float2 r2 = *(const float2*)(res + row * (size_t)N + col);
                    v0 += r2.x; v1 += r2.y;
                }
                if (ROPE && col < 2048) {
                    int t = (int)(row & (T_LEN - 1));
                    int p = ((int)col & 63) >> 1;
                    float2 c2 = cs[t * 32 + p];
                    float r0 = v0 * c2.x - v1 * c2.y;
                    float r1 = v0 * c2.y + v1 * c2.x;
                    v0 = r0; v1 = r1;
                }
                size_t o = row * (size_t)N + col;
                if (SPLIT) {
                    __nv_bfloat16 h0 = __float2bfloat16(v0);
                    __nv_bfloat16 h1 = __float2bfloat16(v1);
                    Oh[o] = h0;     Ol[o] = __float2bfloat16(v0 - __bfloat162float(h0));
                    Oh[o + 1] = h1; Ol[o + 1] = __float2bfloat16(v1 - __bfloat162float(h1));
                } else {
                    *(float2*)(C + o) = make_float2(v0, v1);
                }
            }
        }
    }
}

/* ====== fp16 2-MMA GEMM (A single, B hi/lo): W1 / W2 / LM head =========== */
#define LTILEB (128 * ROWB)
#define LSTAGE (3 * LTILEB)          /* 30720: A, Bh, Bl */
#define LSMTOT (2 * LSTAGE)          /* 61440 */

template<bool RELU, bool OUT16>
__global__ __launch_bounds__(256, 2)
void mma_gemm_f16(const __half* __restrict__ A,
                  const __half* __restrict__ Bh, const __half* __restrict__ Bl,
                  int K, int N,
                  float* __restrict__ C, __half* __restrict__ O16,
                  const float* __restrict__ bias, const float* __restrict__ res) {
    extern __shared__ char smem[];
    const uint32_t sb = smem_u32(smem);
    const int tid = threadIdx.x;
    const int lane = tid & 31;
    const int wid = tid >> 5;
    const int warp_m = wid & 1;
    const int warp_n = wid >> 1;
    const size_t bm = (size_t)blockIdx.y * 128;
    const size_t bn = (size_t)blockIdx.x * 128;

    float acc[4][4][4];
    #pragma unroll
    for (int i = 0; i < 4; i++)
        #pragma unroll
        for (int j = 0; j < 4; j++)
            #pragma unroll
            for (int q = 0; q < 4; q++) acc[i][j][q] = 0.f;

    const int nc = K >> 5;

    auto load_stage = [&](int c) {
        const int k0 = c << 5;
        const uint32_t sbase = sb + (c & 1) * LSTAGE;
        #pragma unroll
        for (int t = 0; t < 6; t++) {
            int idx = tid + (t << 8);
            int tile = idx >> 9;
            int r    = (idx >> 2) & 127;
            int cch  = idx & 3;
            const __half* base = (tile == 0) ? A : (tile == 1) ? Bh : Bl;
            size_t grow = ((tile == 0) ? bm : bn) + r;
            cp16(sbase + tile * LTILEB + r * ROWB + cch * 16,
                 base + grow * (size_t)K + k0 + cch * 8);
        }
        cp_commit();
    };

    load_stage(0);

    const uint32_t aRowOff = (uint32_t)((warp_m * 64 + (lane & 15)) * ROWB + ((lane >> 4) << 4));
    const uint32_t bRow4Off = (uint32_t)((warp_n * 32 + ((lane & 16) >> 1) + (lane & 7)) * ROWB
                                         + ((lane & 8) << 1));

    for (int c = 0; c < nc; c++) {
        cp_wait<0>();
        __syncthreads();
        if (c + 1 < nc) load_stage(c + 1);

        const uint32_t st = sb + (c & 1) * LSTAGE;
        const uint32_t aT = st + aRowOff;
        const uint32_t bH = st + LTILEB + bRow4Off;
        const uint32_t bL = st + 2 * LTILEB + bRow4Off;

        #pragma unroll
        for (int kk = 0; kk < 2; kk++) {
            const uint32_t kb = kk * 32;
            uint32_t a[4][4], bh[4][2], bl[4][2];
            #pragma unroll
            for (int p = 0; p < 2; p++) {
                ldmB4(bh[2*p][0], bh[2*p][1], bh[2*p+1][0], bh[2*p+1][1],
                      bH + p * (16 * ROWB) + kb);
                ldmB4(bl[2*p][0], bl[2*p][1], bl[2*p+1][0], bl[2*p+1][1],
                      bL + p * (16 * ROWB) + kb);
            }
            #pragma unroll
            for (int mt = 0; mt < 4; mt++)
                ldmA(a[mt], aT + mt * (16 * ROWB) + kb);
            #pragma unroll
            for (int mt = 0; mt < 4; mt++)
                #pragma unroll
                for (int nt = 0; nt < 4; nt++)
                    mma16816h(acc[mt][nt], a[mt], bh[nt]);
            #pragma unroll
            for (int mt = 0; mt < 4; mt++)
                #pragma unroll
                for (int nt = 0; nt < 4; nt++)
                    mma16816h(acc[mt][nt], a[mt], bl[nt]);
        }
    }

    #pragma unroll
    for (int mt = 0; mt < 4; mt++) {
        #pragma unroll
        for (int nt = 0; nt < 4; nt++) {
            size_t col = bn + warp_n * 32 + nt * 8 + (lane & 3) * 2;
            #pragma unroll
            for (int half = 0; half < 2; half++) {
                size_t row = bm + warp_m * 64 + mt * 16 + (lane >> 2) + half * 8;
                float v0 = acc[mt][nt][half * 2 + 0];
                float v1 = acc[mt][nt][half * 2 + 1];
                if (bias) { v0 += bias[col]; v1 += bias[col + 1]; }
                if (res) {
                    const float2 r2 = *(const float2*)(res + row * (size_t)N + col);
                    v0 += r2.x; v1 += r2.y;
                }
                if (RELU) { v0 = fmaxf(v0, 0.f); v1 = fmaxf(v1, 0.f); }
                size_t o = row * (size_t)N + col;
                if (OUT16) {
                    __half2 h2 = __floats2half2_rn(v0, v1);
                    *(__half2*)(O16 + o) = h2;
                } else {
                    *(float2*)(C + o) = make_float2(v0, v1);
                }
            }
        }
    }
}

/* ================= weight transpose+split ================================ */
__global__ void wt_gen(const float* __restrict__ in, long in_zs,
                       __nv_bfloat16* __restrict__ oh, __nv_bfloat16* __restrict__ ol,
                       long out_zs, int Kd, int Nd) {
    __shared__ float t[32][33];
    int z = blockIdx.z;
    in += (size_t)z * in_zs; oh += (size_t)z * out_zs; ol += (size_t)z * out_zs;
    int n0 = blockIdx.x * 32, k0 = blockIdx.y * 32;
    int tx = threadIdx.x, ty = threadIdx.y;
    #pragma unroll
    for (int j = ty; j < 32; j += 8)
        t[j][tx] = in[(size_t)(k0 + j) * Nd + n0 + tx];
    __syncthreads();
    #pragma unroll
    for (int j = ty; j < 32; j += 8) {
        float v = t[tx][j];
        size_t o = (size_t)(n0 + j) * Kd + k0 + tx;
        __nv_bfloat16 h = __float2bfloat16(v);
        oh[o] = h;
        ol[o] = __float2bfloat16(v - __bfloat162float(h));
    }
}
/* fp16 hi/lo z-batched transpose [Kd][Nd] -> [Nd][Kd] */
__global__ void wt_gen16(const float* __restrict__ in, long in_zs,
                         __half* __restrict__ oh, __half* __restrict__ ol,
                         long out_zs, int Kd, int Nd) {
    __shared__ float t[32][33];
    int z = blockIdx.z;
    in += (size_t)z * in_zs; oh += (size_t)z * out_zs; ol += (size_t)z * out_zs;
    int n0 = blockIdx.x * 32, k0 = blockIdx.y * 32;
    int tx = threadIdx.x, ty = threadIdx.y;
    #pragma unroll
    for (int j = ty; j < 32; j += 8)
        t[j][tx] = in[(size_t)(k0 + j) * Nd + n0 + tx];
    __syncthreads();
    #pragma unroll
    for (int j = ty; j < 32; j += 8) {
        float v = t[tx][j];
        size_t o = (size_t)(n0 + j) * Kd + k0 + tx;
        __half h = __float2half_rn(v);
        oh[o] = h;
        ol[o] = __float2half_rn(v - __half2float(h));
    }
}
__global__ void wt_qkv_all(const float* __restrict__ wq, const float* __restrict__ wk,
                           const float* __restrict__ wv,
                           __nv_bfloat16* __restrict__ oh, __nv_bfloat16* __restrict__ ol) {
    __shared__ float t[32][33];
    int z = blockIdx.z;
    int sel = z / 96;
    int zz  = z - sel * 96;
    int l = zz >> 4, h = zz & 15;
    const float* w = (sel == 0) ? wq : (sel == 1) ? wk : wv;
    const float scale = (sel == 0) ? 0.03125f : 1.0f;
    const float* in = w + (size_t)zz * E_DIM * HD;
    size_t orow0 = (size_t)l * 3 * E_DIM + (size_t)sel * E_DIM + h * HD;
    __nv_bfloat16* ohp = oh + orow0 * E_DIM;
    __nv_bfloat16* olp = ol + orow0 * E_DIM;
    int d0 = blockIdx.x * 32, e0 = blockIdx.y * 32;
    int tx = threadIdx.x, ty = threadIdx.y;
    #pragma unroll
    for (int j = ty; j < 32; j += 8)
        t[j][tx] = in[(size_t)(e0 + j) * HD + d0 + tx];
    __syncthreads();
    #pragma unroll
    for (int j = ty; j < 32; j += 8) {
        float v = t[tx][j] * scale;
        size_t o = (size_t)(d0 + j) * E_DIM + e0 + tx;
        __nv_bfloat16 hh = __float2bfloat16(v);
        ohp[o] = hh;
        olp[o] = __float2bfloat16(v - __bfloat162float(hh));
    }
}

/* ================= fused embed + LN1(layer0) + cs table ================== */
__global__ __launch_bounds__(256)
void embed_ln_kernel(const int* __restrict__ idx, const float* __restrict__ emb,
                     const float* __restrict__ g, const float* __restrict__ b,
                     float* __restrict__ x,
                     __nv_bfloat16* __restrict__ yh, __nv_bfloat16* __restrict__ yl) {
    int m = blockIdx.x, tid = threadIdx.x;
    __shared__ float r1[256], r2[256];
    const float4* src = (const float4*)(emb + (size_t)idx[m] * E_DIM);
    float4 v = src[tid];
    ((float4*)(x + (size_t)m * E_DIM))[tid] = v;
    r1[tid] = v.x + v.y + v.z + v.w;
    r2[tid] = v.x * v.x + v.y * v.y + v.z * v.z + v.w * v.w;
    if (m < 128) {
        int i = m * 256 + tid;
        if (i < T_LEN * 32) {
            int t = i >> 5, p = i & 31;
            float invf = powf(10000.f, -(float)(2 * p) / (float)HD);
            float sn, c;
            sincosf((float)t * invf, &sn, &c);
            g_cs[i] = make_float2(c, sn);
        }
    }
    __syncthreads();
    for (int s = 128; s > 0; s >>= 1) {
        if (tid < s) { r1[tid] += r1[tid + s]; r2[tid] += r2[tid + s]; }
        __syncthreads();
    }
    float mean = r1[0] * (1.0f / E_DIM);
    float var  = r2[0] * (1.0f / E_DIM) - mean * mean;
    float rstd = rsqrtf(var + 1e-5f);
    float4 gg = ((const float4*)g)[tid];
    float4 bb = ((const float4*)b)[tid];
    float o[4] = { (v.x - mean) * rstd * gg.x + bb.x, (v.y - mean) * rstd * gg.y + bb.y,
                   (v.z - mean) * rstd * gg.z + bb.z, (v.w - mean) * rstd * gg.w + bb.w };
    size_t base = (size_t)m * E_DIM + tid * 4;
    #pragma unroll
    for (int j = 0; j < 4; j++) {
        __nv_bfloat16 h = __float2bfloat16(o[j]);
        yh[base + j] = h;
        yl[base + j] = __float2bfloat16(o[j] - __bfloat162float(h));
    }
}

/* LN -> split bf16 (QKV path) */
__global__ __launch_bounds__(256)
void ln_split_kernel(const float* __restrict__ x, const float* __restrict__ g,
                     const float* __restrict__ b,
                     __nv_bfloat16* __restrict__ yh, __nv_bfloat16* __restrict__ yl) {
    int m = blockIdx.x, tid = threadIdx.x;
    __shared__ float r1[256], r2[256];
    const float4* xr = (const float4*)(x + (size_t)m * E_DIM);
    float4 v = xr[tid];
    r1[tid] = v.x + v.y + v.z + v.w;
    r2[tid] = v.x * v.x + v.y * v.y + v.z * v.z + v.w * v.w;
    __syncthreads();
    for (int s = 128; s > 0; s >>= 1) {
        if (tid < s) { r1[tid] += r1[tid + s]; r2[tid] += r2[tid + s]; }
        __syncthreads();
    }
    float mean = r1[0] * (1.0f / E_DIM);
    float var  = r2[0] * (1.0f / E_DIM) - mean * mean;
    float rstd = rsqrtf(var + 1e-5f);
    float4 gg = ((const float4*)g)[tid];
    float4 bb = ((const float4*)b)[tid];
    float o[4] = { (v.x - mean) * rstd * gg.x + bb.x, (v.y - mean) * rstd * gg.y + bb.y,
                   (v.z - mean) * rstd * gg.z + bb.z, (v.w - mean) * rstd * gg.w + bb.w };
    size_t base = (size_t)m * E_DIM + tid * 4;
    #pragma unroll
    for (int j = 0; j < 4; j++) {
        __nv_bfloat16 h = __float2bfloat16(o[j]);
        yh[base + j] = h;
        yl[base + j] = __float2bfloat16(o[j] - __bfloat162float(h));
    }
}

/* LN -> single fp16 (MLP path) */
__global__ __launch_bounds__(256)
void ln_f16_kernel(const float* __restrict__ x, const float* __restrict__ g,
                   const float* __restrict__ b, __half* __restrict__ y16) {
    int m = blockIdx.x, tid = threadIdx.x;
    __shared__ float r1[256], r2[256];
    const float4* xr = (const float4*)(x + (size_t)m * E_DIM);
    float4 v = xr[tid];
    r1[tid] = v.x + v.y + v.z + v.w;
    r2[tid] = v.x * v.x + v.y * v.y + v.z * v.z + v.w * v.w;
    __syncthreads();
    for (int s = 128; s > 0; s >>= 1) {
        if (tid < s) { r1[tid] += r1[tid + s]; r2[tid] += r2[tid + s]; }
        __syncthreads();
    }
    float mean = r1[0] * (1.0f / E_DIM);
    float var  = r2[0] * (1.0f / E_DIM) - mean * mean;
    float rstd = rsqrtf(var + 1e-5f);
    float4 gg = ((const float4*)g)[tid];
    float4 bb = ((const float4*)b)[tid];
    __half2 h0 = __floats2half2_rn((v.x - mean) * rstd * gg.x + bb.x,
                                   (v.y - mean) * rstd * gg.y + bb.y);
    __half2 h1 = __floats2half2_rn((v.z - mean) * rstd * gg.z + bb.z,
                                   (v.w - mean) * rstd * gg.w + bb.w);
    size_t base = (size_t)m * E_DIM + tid * 4;
    *(__half2*)(g_y16 + base)     = h0;
    *(__half2*)(g_y16 + base + 2) = h1;
    (void)y16;
}

__global__ void split_f16_kernel(const float* __restrict__ x,
                                 __half* __restrict__ yf, int n) {
    int i = blockIdx.x * blockDim.x + threadIdx.x;
    if (i < n) yf[i] = __float2half_rn(x[i]);
}

/* ======== flash attention (HMMA, split-bf16): 64q tiles, 64k chunks ====== */
#define ARS  144
#define ATILE (64 * ARS)
#define ASM  (4 * ATILE)

__global__ __launch_bounds__(128)
void attn_kernel(const __nv_bfloat16* __restrict__ qg_h, const __nv_bfloat16* __restrict__ qg_l,
                 __nv_bfloat16* __restrict__ oh, __nv_bfloat16* __restrict__ ol) {
    extern __shared__ char sm[];
    const uint32_t sb = smem_u32(sm);
    const int tid = threadIdx.x, lane = tid & 31, w = tid >> 5;
    const int qt = blockIdx.x;
    const int b  = blockIdx.y >> 4;
    const int h  = blockIdx.y & 15;
    const int t0 = qt * 64;
    const size_t mbase = (size_t)b * T_LEN;

    for (int i = tid; i < 512; i += 128) {
        int r = i >> 3, c = i & 7;
        size_t src = (mbase + t0 + r) * 3072 + h * 64 + c * 8;
        cp16(sb + r * ARS + c * 16, qg_h + src);
        cp16(sb + ATILE + r * ARS + c * 16, qg_l + src);
    }
    cp_commit(); cp_wait<0>(); __syncthreads();

    uint32_t Qh[4][4], Ql[4][4];
    {
        uint32_t qo = sb + (w * 16 + (lane & 15)) * ARS + ((lane >> 4) << 4);
        #pragma unroll
        for (int ks = 0; ks < 4; ks++) {
            ldmA(Qh[ks], qo + ks * 32);
            ldmA(Ql[ks], qo + ATILE + ks * 32);
        }
    }
    __syncthreads();

    float O[8][4];
    #pragma unroll
    for (int i = 0; i < 8; i++)
        #pragma unroll
        for (int j = 0; j < 4; j++) O[i][j] = 0.f;
    float m0 = -1e30f, m1 = -1e30f, l0 = 0.f, l1 = 0.f;
    const int g = lane >> 2, t4 = lane & 3;
    const int row0 = t0 + w * 16 + g;
    const int row1 = row0 + 8;

    const int nch = qt + 1;
    for (int ch = 0; ch < nch; ch++) {
        const int c0 = ch * 64;
        for (int i = tid; i < 512; i += 128) {
            int r = i >> 3, c = i & 7;
            size_t srck = (mbase + c0 + r) * 3072 + 1024 + h * 64 + c * 8;
            cp16(sb + 0 * ATILE + r * ARS + c * 16, qg_h + srck);
            cp16(sb + 1 * ATILE + r * ARS + c * 16, qg_l + srck);
            cp16(sb + 2 * ATILE + r * ARS + c * 16, qg_h + srck + 1024);
            cp16(sb + 3 * ATILE + r * ARS + c * 16, qg_l + srck + 1024);
        }
        cp_commit(); cp_wait<0>(); __syncthreads();

        float S[8][4];
        const uint32_t kbo = sb + (lane & 7) * ARS + (((lane >> 3) & 1) << 4);
        #pragma unroll
        for (int nt = 0; nt < 8; nt++) {
            #pragma unroll
            for (int j = 0; j < 4; j++) S[nt][j] = 0.f;
            uint32_t kh[4][2], kl[4][2];
            #pragma unroll
            for (int ks = 0; ks < 4; ks++) {
                ldmB(kh[ks], kbo + nt * (8 * ARS) + ks * 32);
                ldmB(kl[ks], kbo + ATILE + nt * (8 * ARS) + ks * 32);
            }
            #pragma unroll
            for (int ks = 0; ks < 4; ks++) {
                mma16816(S[nt], Qh[ks], kh[ks]);
                mma16816(S[nt], Qh[ks], kl[ks]);
                mma16816(S[nt], Ql[ks], kh[ks]);
            }
        }

        if (ch == nch - 1) {
            #pragma unroll
            for (int nt = 0; nt < 8; nt++) {
                int kc = c0 + nt * 8 + 2 * t4;
                if (kc > row0)     S[nt][0] = -1e30f;
                if (kc + 1 > row0) S[nt][1] = -1e30f;
                if (kc > row1)     S[nt][2] = -1e30f;
                if (kc + 1 > row1) S[nt][3] = -1e30f;
            }
        }

        float mc0 = -1e30f, mc1 = -1e30f;
        #pragma unroll
        for (int nt = 0; nt < 8; nt++) {
            mc0 = fmaxf(mc0, fmaxf(S[nt][0], S[nt][1]));
            mc1 = fmaxf(mc1, fmaxf(S[nt][2], S[nt][3]));
        }
        mc0 = fmaxf(mc0, __shfl_xor_sync(~0u, mc0, 1));
        mc0 = fmaxf(mc0, __shfl_xor_sync(~0u, mc0, 2));
        mc1 = fmaxf(mc1, __shfl_xor_sync(~0u, mc1, 1));
        mc1 = fmaxf(mc1, __shfl_xor_sync(~0u, mc1, 2));
        float mn0 = fmaxf(m0, mc0), mn1 = fmaxf(m1, mc1);
        float a0 = __expf(m0 - mn0), a1 = __expf(m1 - mn1);
        m0 = mn0; m1 = mn1;
        float s0 = 0.f, s1 = 0.f;
        #pragma unroll
        for (int nt = 0; nt < 8; nt++) {
            S[nt][0] = __expf(S[nt][0] - mn0); s0 += S[nt][0];
            S[nt][1] = __expf(S[nt][1] - mn0); s0 += S[nt][1];
            S[nt][2] = __expf(S[nt][2] - mn1); s1 += S[nt][2];
            S[nt][3] = __expf(S[nt][3] - mn1); s1 += S[nt][3];
        }
        s0 += __shfl_xor_sync(~0u, s0, 1); s0 += __shfl_xor_sync(~0u, s0, 2);
        s1 += __shfl_xor_sync(~0u, s1, 1); s1 += __shfl_xor_sync(~0u, s1, 2);
        l0 = l0 * a0 + s0;
        l1 = l1 * a1 + s1;
        #pragma unroll
        for (int nt = 0; nt < 8; nt++) {
            O[nt][0] *= a0; O[nt][1] *= a0; O[nt][2] *= a1; O[nt][3] *= a1;
        }

        #pragma unroll
        for (int ks = 0; ks < 4; ks++) {
            uint32_t Ph[4], Pl[4];
            #pragma unroll
            for (int half = 0; half < 2; half++) {
                float p0 = S[2 * ks + half][0], p1 = S[2 * ks + half][1];
                float p2 = S[2 * ks + half][2], p3 = S[2 * ks + half][3];
                __nv_bfloat16 h0 = __float2bfloat16(p0), h1 = __float2bfloat16(p1);
                __nv_bfloat16 h2 = __float2bfloat16(p2), h3 = __float2bfloat16(p3);
                Ph[half * 2 + 0] = packbf(__bfloat162float(h0), __bfloat162float(h1));
                Ph[half * 2 + 1] = packbf(__bfloat162float(h2), __bfloat162float(h3));
                Pl[half * 2 + 0] = packbf(p0 - __bfloat162float(h0), p1 - __bfloat162float(h1));
                Pl[half * 2 + 1] = packbf(p2 - __bfloat162float(h2), p3 - __bfloat162float(h3));
            }
            uint32_t A_h[4] = { Ph[0], Ph[1], Ph[2], Ph[3] };
            uint32_t A_l[4] = { Pl[0], Pl[1], Pl[2], Pl[3] };
            const uint32_t vbase = sb + 2 * ATILE + (ks * 16 + (lane & 15)) * ARS;
            #pragma unroll
            for (int nt = 0; nt < 8; nt++) {
                uint32_t vh[2], vl[2];
                ldmT(vh, vbase + nt * 16);
                ldmT(vl, vbase + ATILE + nt * 16);
                mma16816(O[nt], A_h, vh);
                mma16816(O[nt], A_h, vl);
                mma16816(O[nt], A_l, vh);
            }
        }
        __syncthreads();
    }

    const float il0 = 1.f / l0, il1 = 1.f / l1;
    #pragma unroll
    for (int nt = 0; nt < 8; nt++) {
        size_t p0 = (mbase + row0) * E_DIM + h * 64 + nt * 8 + 2 * t4;
        size_t p1 = (mbase + row1) * E_DIM + h * 64 + nt * 8 + 2 * t4;
        float o00 = O[nt][0] * il0, o01 = O[nt][1] * il0;
        float o10 = O[nt][2] * il1, o11 = O[nt][3] * il1;
        __nv_bfloat16 h00 = __float2bfloat16(o00), h01 = __float2bfloat16(o01);
        __nv_bfloat16 h10 = __float2bfloat16(o10), h11 = __float2bfloat16(o11);
        oh[p0] = h00;     ol[p0] = __float2bfloat16(o00 - __bfloat162float(h00));
        oh[p0 + 1] = h01; ol[p0 + 1] = __float2bfloat16(o01 - __bfloat162float(h01));
        oh[p1] = h10;     ol[p1] = __float2bfloat16(o10 - __bfloat162float(h10));
        oh[p1 + 1] = h11; ol[p1 + 1] = __float2bfloat16(o11 - __bfloat162float(h11));
    }
}

/* ================= NLL + loss ============================================ */
__global__ __launch_bounds__(256)
void nll_kernel(const float* __restrict__ logits, const int* __restrict__ tgt,
                float* __restrict__ nll) {
    int m = blockIdx.x, tid = threadIdx.x;
    const float* lr = logits + (size_t)m * VOCAB;
    __shared__ float red[256];
    float mx = -1e30f;
    for (int n = tid; n < VOCAB; n += 256) mx = fmaxf(mx, lr[n]);
    red[tid] = mx;
    __syncthreads();
    for (int s = 128; s > 0; s >>= 1) {
        if (tid < s) red[tid] = fmaxf(red[tid], red[tid + s]);
        __syncthreads();
    }
    mx = red[0];
    __syncthreads();
    float sum = 0.f;
    for (int n = tid; n < VOCAB; n += 256) sum += __expf(lr[n] - mx);
    red[tid] = sum;
    __syncthreads();
    for (int s = 128; s > 0; s >>= 1) {
        if (tid < s) red[tid] += red[tid + s];
        __syncthreads();
    }
    if (tid == 0)
        nll[m] = (logf(red[0]) + mx) - lr[tgt[m]];
}

__global__ __launch_bounds__(256)
void loss_reduce_kernel(const float* __restrict__ nll, float* __restrict__ out) {
    __shared__ float red[256];
    int tid = threadIdx.x;
    float s = 0.f;
    for (int i = tid; i < MTOK; i += 256) s += nll[i];
    red[tid] = s;
    __syncthreads();
    for (int k = 128; k > 0; k >>= 1) {
        if (tid < k) red[tid] += red[tid + k];
        __syncthreads();
    }
    if (tid == 0) out[0] = red[0] * (1.0f / MTOK);
}

/* ================= host orchestration ==================================== */
extern "C" void kernel_launch(void* const* d_in, const int* in_sizes, int n_in,
                              void* d_out, int out_size) {
    const int*   idx   = (const int*)  d_in[0];
    const int*   tgt   = (const int*)  d_in[1];
    const float* emb   = (const float*)d_in[2];
    const float* wq    = (const float*)d_in[3];
    const float* wk    = (const float*)d_in[4];
    const float* wv    = (const float*)d_in[5];
    const float* wproj = (const float*)d_in[6];
    const float* bproj = (const float*)d_in[7];
    const float* w1    = (const float*)d_in[8];
    const float* b1    = (const float*)d_in[9];
    const float* w2    = (const float*)d_in[10];
    const float* b2    = (const float*)d_in[11];
    const float* ln1g  = (const float*)d_in[12];
    const float* ln1b  = (const float*)d_in[13];
    const float* ln2g  = (const float*)d_in[14];
    const float* ln2b  = (const float*)d_in[15];
    const float* lm_w  = (const float*)d_in[16];
    const float* lm_b  = (const float*)d_in[17];

    float *x, *nll, *lscr;
    float2* cs;
    __nv_bfloat16 *yh, *yl, *qh, *ql, *oh, *ol;
    __nv_bfloat16 *qkvTh, *qkvTl, *projTh, *projTl;
    __half *w1Th, *w1Tl, *w2Th, *w2Tl, *lmTh, *lmTl, *yf, *y16, *h16;
    cudaGetSymbolAddress((void**)&x,     g_x);
    cudaGetSymbolAddress((void**)&yh,    g_yh);
    cudaGetSymbolAddress((void**)&yl,    g_yl);
    cudaGetSymbolAddress((void**)&qh,    g_qh);
    cudaGetSymbolAddress((void**)&ql,    g_ql);
    cudaGetSymbolAddress((void**)&oh,    g_oh);
    cudaGetSymbolAddress((void**)&ol,    g_ol);
    cudaGetSymbolAddress((void**)&y16,   g_y16);
    cudaGetSymbolAddress((void**)&h16,   g_h16);
    cudaGetSymbolAddress((void**)&nll,   g_nllv);
    cudaGetSymbolAddress((void**)&lscr,  g_logits_scratch);
    cudaGetSymbolAddress((void**)&cs,    g_cs);
    cudaGetSymbolAddress((void**)&qkvTh, g_qkvT_h);
    cudaGetSymbolAddress((void**)&qkvTl, g_qkvT_l);
    cudaGetSymbolAddress((void**)&projTh, g_projT_h);
    cudaGetSymbolAddress((void**)&projTl, g_projT_l);
    cudaGetSymbolAddress((void**)&w1Th,  g_w1T16_h);
    cudaGetSymbolAddress((void**)&w1Tl,  g_w1T16_l);
    cudaGetSymbolAddress((void**)&w2Th,  g_w2T16_h);
    cudaGetSymbolAddress((void**)&w2Tl,  g_w2T16_l);
    cudaGetSymbolAddress((void**)&lmTh,  g_lmT_h);
    cudaGetSymbolAddress((void**)&lmTl,  g_lmT_l);
    cudaGetSymbolAddress((void**)&yf,    g_yf);

    cudaFuncSetAttribute(mma_gemm<false, false>, cudaFuncAttributeMaxDynamicSharedMemorySize, SMTOT);
    cudaFuncSetAttribute(mma_gemm<true,  true >, cudaFuncAttributeMaxDynamicSharedMemorySize, SMTOT);
    cudaFuncSetAttribute(mma_gemm_f16<false, false>, cudaFuncAttributeMaxDynamicSharedMemorySize, LSMTOT);
    cudaFuncSetAttribute(mma_gemm_f16<true,  true >, cudaFuncAttributeMaxDynamicSharedMemorySize, LSMTOT);

    const long BTV = (long)MTOK * VOCAB;
    float* logits = ((long)out_size >= BTV) ? (float*)d_out : lscr;

    dim3 tb(32, 8);
    embed_ln_kernel<<<MTOK, 256>>>(idx, emb, ln1g, ln1b, x, yh, yl);
    wt_qkv_all<<<dim3(2, 32, 288), tb>>>(wq, wk, wv, qkvTh, qkvTl);
    mma_gemm<true, true><<<dim3(3 * E_DIM / 128, MTOK / 128), 256, SMTOT>>>(
        yh, yl, qkvTh, qkvTl, E_DIM, 3 * E_DIM,
        nullptr, qh, ql, nullptr, nullptr, (const float2*)cs);
    attn_kernel<<<dim3(T_LEN / 64, BATCH * N_HEAD), 128, ASM>>>(qh, ql, oh, ol);

    wt_gen<<<dim3(32, 32, N_LAYER), tb>>>(wproj, (long)E_DIM * E_DIM, projTh, projTl,
                                          (long)E_DIM * E_DIM, E_DIM, E_DIM);
    wt_gen16<<<dim3(128, 32, N_LAYER), tb>>>(w1, (long)E_DIM * FF, w1Th, w1Tl,
                                             (long)E_DIM * FF, E_DIM, FF);
    wt_gen16<<<dim3(32, 128, N_LAYER), tb>>>(w2, (long)FF * E_DIM, w2Th, w2Tl,
                                             (long)FF * E_DIM, FF, E_DIM);
    wt_gen16<<<dim3(1000, 32, 1), tb>>>(lm_w, 0, lmTh, lmTl, 0, E_DIM, VOCAB);

    for (int l = 0; l < N_LAYER; l++) {
        size_t qkvW = (size_t)l * 3 * E_DIM * E_DIM;
        size_t prW  = (size_t)l * E_DIM * E_DIM;
        size_t w1W  = (size_t)l * FF * E_DIM;

        if (l > 0) {
            ln_split_kernel<<<MTOK, 256>>>(x, ln1g + (size_t)l * E_DIM, ln1b + (size_t)l * E_DIM, yh, yl);
            mma_gemm<true, true><<<dim3(3 * E_DIM / 128, MTOK / 128), 256, SMTOT>>>(
                yh, yl, qkvTh + qkvW, qkvTl + qkvW, E_DIM, 3 * E_DIM,
                nullptr, qh, ql, nullptr, nullptr, (const float2*)cs);
            attn_kernel<<<dim3(T_LEN / 64, BATCH * N_HEAD), 128, ASM>>>(qh, ql, oh, ol);
        }

        mma_gemm<false, false><<<dim3(E_DIM / 128, MTOK / 128), 256, SMTOT>>>(
            oh, ol, projTh + prW, projTl + prW, E_DIM, E_DIM,
            x, nullptr, nullptr, bproj + (size_t)l * E_DIM, x, nullptr);

        ln_f16_kernel<<<MTOK, 256>>>(x, ln2g + (size_t)l * E_DIM, ln2b + (size_t)l * E_DIM, y16);

        mma_gemm_f16<true, true><<<dim3(FF / 128, MTOK / 128), 256, LSMTOT>>>(
            y16, w1Th + w1W, w1Tl + w1W, E_DIM, FF,
            nullptr, h16, b1 + (size_t)l * FF, nullptr);

        mma_gemm_f16<false, false><<<dim3(E_DIM / 128, MTOK / 128), 256, LSMTOT>>>(
            h16, w2Th + w1W, w2Tl + w1W, FF, E_DIM,
            x, nullptr, b2 + (size_t)l * E_DIM, x);
    }

    split_f16_kernel<<<(MTOK * E_DIM + 255) / 256, 256>>>(x, yf, MTOK * E_DIM);

    mma_gemm_f16<false, false><<<dim3(VOCAB / 128, MTOK / 128), 256, LSMTOT>>>(
        yf, lmTh, lmTl, E_DIM, VOCAB, logits, nullptr, lm_b, nullptr);

    nll_kernel<<<MTOK, 256>>>(logits, tgt, nll);

    if ((long)out_size == BTV + 1) {
        loss_reduce_kernel<<<1, 256>>>(nll, (float*)d_out + BTV);
    } else if ((long)out_size < BTV) {
        loss_reduce_kernel<<<1, 256>>>(nll, (float*)d_out);
    }
}